// round 9
// baseline (speedup 1.0000x reference)
#include <cuda_runtime.h>
#include <cuda_fp16.h>
#include <math.h>
#include <stdint.h>

#define BB 4
#define CC 64
#define HW 4096
#define CHW (CC*HW)
#define EPSV 1e-5f
#define OFRV 4.0f
#define SCALEV 0.125f

// -------- scratch (device globals) --------
__device__ __half g_qh[BB*CHW];   // [b][p][c]  fp16
__device__ __half g_kh[BB*CHW];   // [b][n][c]  fp16
__device__ __half g_vh[BB*CHW];   // [b][c][n]  fp16 (TRANSPOSED)
__device__ float  g_ao[BB*CHW];   // [b][p][c]  fp32
__device__ float  g_vsum[BB*CC];  // colsum of V

// ================= helpers =================
__device__ __forceinline__ uint32_t smem_u32(const void* p){
    uint32_t a;
    asm("{ .reg .u64 t; cvta.to.shared.u64 t, %1; cvt.u32.u64 %0, t; }" : "=r"(a) : "l"(p));
    return a;
}
__device__ __forceinline__ void cp16(uint32_t dst, const void* src){
    asm volatile("cp.async.cg.shared.global [%0], [%1], 16;" :: "r"(dst), "l"(src));
}
#define CP_COMMIT() asm volatile("cp.async.commit_group;" ::: "memory")
#define CP_WAIT0()  asm volatile("cp.async.wait_group 0;" ::: "memory")
#define CP_WAIT1()  asm volatile("cp.async.wait_group 1;" ::: "memory")

#define LDSM4(R0,R1,R2,R3,ADDR) \
    asm volatile("ldmatrix.sync.aligned.m8n8.x4.shared.b16 {%0,%1,%2,%3}, [%4];" \
        : "=r"(R0),"=r"(R1),"=r"(R2),"=r"(R3) : "r"(ADDR))

__device__ __forceinline__ void mma_f16(float* d, const uint32_t* a,
                                        uint32_t b0, uint32_t b1, const float* c){
    asm volatile(
        "mma.sync.aligned.m16n8k16.row.col.f32.f16.f16.f32 "
        "{%0,%1,%2,%3}, {%4,%5,%6,%7}, {%8,%9}, {%10,%11,%12,%13};"
        : "=f"(d[0]), "=f"(d[1]), "=f"(d[2]), "=f"(d[3])
        : "r"(a[0]), "r"(a[1]), "r"(a[2]), "r"(a[3]),
          "r"(b0), "r"(b1),
          "f"(c[0]), "f"(c[1]), "f"(c[2]), "f"(c[3]));
}

// ================= conv1x1 q: prompt [c][p] -> g_qh [p][c] fp16
__global__ void k_convq(const float* __restrict__ prompt,
                        const float* __restrict__ wq,
                        const float* __restrict__ bq) {
    __shared__ float ws[4096];
    __shared__ float bs[64];
    int tid = threadIdx.x;
    for (int i = tid; i < 4096; i += 256) ws[i] = wq[i];
    if (tid < 64) bs[tid] = bq[tid];
    __syncthreads();
    int qtr = tid >> 6;
    int p   = blockIdx.x * 64 + (tid & 63);
    int bb  = blockIdx.y;
    const float* xb = prompt + bb * CHW + p;
    float xr[64];
#pragma unroll
    for (int c = 0; c < 64; c++) xr[c] = xb[c * HW];
    __half2* yb = (__half2*)(g_qh + bb * CHW + p * 64 + qtr * 16);
    const float* wbase = ws + qtr * 16 * 64;
#pragma unroll
    for (int o4 = 0; o4 < 4; o4++) {
        float a0 = bs[qtr*16 + o4*4 + 0], a1 = bs[qtr*16 + o4*4 + 1];
        float a2 = bs[qtr*16 + o4*4 + 2], a3 = bs[qtr*16 + o4*4 + 3];
#pragma unroll
        for (int c = 0; c < 64; c++) {
            float x = xr[c];
            a0 += wbase[(o4*4+0)*64 + c] * x;
            a1 += wbase[(o4*4+1)*64 + c] * x;
            a2 += wbase[(o4*4+2)*64 + c] * x;
            a3 += wbase[(o4*4+3)*64 + c] * x;
        }
        yb[o4*2]     = __floats2half2_rn(a0, a1);
        yb[o4*2 + 1] = __floats2half2_rn(a2, a3);
    }
}

// ================= conv1x1 out: g_ao [p][c] -> out [c][p]
__global__ void k_convo(const float* __restrict__ wo,
                        const float* __restrict__ bo,
                        float* __restrict__ out) {
    __shared__ float ws[4096];
    __shared__ float bs[64];
    int tid = threadIdx.x;
    for (int i = tid; i < 4096; i += 256) ws[i] = wo[i];
    if (tid < 64) bs[tid] = bo[tid];
    __syncthreads();
    int qtr = tid >> 6;
    int p   = blockIdx.x * 64 + (tid & 63);
    int bb  = blockIdx.y;
    const float4* xb4 = (const float4*)(g_ao + bb * CHW + p * 64);
    float xr[64];
#pragma unroll
    for (int c4 = 0; c4 < 16; c4++) {
        float4 v = xb4[c4];
        xr[c4*4+0] = v.x; xr[c4*4+1] = v.y; xr[c4*4+2] = v.z; xr[c4*4+3] = v.w;
    }
    float* yb = out + bb * CHW + (qtr * 16) * HW + p;
    const float* wbase = ws + qtr * 16 * 64;
#pragma unroll
    for (int o4 = 0; o4 < 4; o4++) {
        float a0 = bs[qtr*16 + o4*4 + 0], a1 = bs[qtr*16 + o4*4 + 1];
        float a2 = bs[qtr*16 + o4*4 + 2], a3 = bs[qtr*16 + o4*4 + 3];
#pragma unroll
        for (int c = 0; c < 64; c++) {
            float x = xr[c];
            a0 += wbase[(o4*4+0)*64 + c] * x;
            a1 += wbase[(o4*4+1)*64 + c] * x;
            a2 += wbase[(o4*4+2)*64 + c] * x;
            a3 += wbase[(o4*4+3)*64 + c] * x;
        }
        yb[(o4*4+0) * HW] = a0;
        yb[(o4*4+1) * HW] = a1;
        yb[(o4*4+2) * HW] = a2;
        yb[(o4*4+3) * HW] = a3;
    }
}

// ================= fused: dw3x3 + LN + GELU + offset + tanh + bilinear + K/V proj
__global__ void k_fuse(const float* __restrict__ kv,
                       const float* __restrict__ dw_w,
                       const float* __restrict__ dw_b,
                       const float* __restrict__ ln_w,
                       const float* __restrict__ ln_b,
                       const float* __restrict__ off_w,
                       const float* __restrict__ wk,
                       const float* __restrict__ bk,
                       const float* __restrict__ wv,
                       const float* __restrict__ bv) {
    __shared__ float s_wk[4096], s_wv[4096];
    __shared__ float s_dw[576], s_dwb[64], s_lnw[64], s_lnb[64];
    __shared__ float s_offw[128], s_bk[64], s_bv[64];

    for (int i = threadIdx.x; i < 4096; i += 128) { s_wk[i] = wk[i]; s_wv[i] = wv[i]; }
    for (int i = threadIdx.x; i < 576; i += 128) s_dw[i] = dw_w[i];
    if (threadIdx.x < 64) {
        s_dwb[threadIdx.x] = dw_b[threadIdx.x];
        s_lnw[threadIdx.x] = ln_w[threadIdx.x];
        s_lnb[threadIdx.x] = ln_b[threadIdx.x];
        s_bk[threadIdx.x]  = bk[threadIdx.x];
        s_bv[threadIdx.x]  = bv[threadIdx.x];
    }
    if (threadIdx.x < 128) s_offw[threadIdx.x] = off_w[threadIdx.x];
    __syncthreads();

    int p  = blockIdx.x * 128 + threadIdx.x;
    int bb = blockIdx.y;
    int py = p >> 6;
    int px = p & 63;

    const __half* qb = g_qh + bb * CHW;   // [p][c]

    float t[64];
#pragma unroll
    for (int c = 0; c < 64; c++) t[c] = s_dwb[c];

    for (int k9 = 0; k9 < 9; k9++) {
        int dy = k9 / 3 - 1, dx = k9 % 3 - 1;
        int yy = py + dy, xx = px + dx;
        if (yy < 0 || yy > 63 || xx < 0 || xx > 63) continue;
        const __half2* qp = (const __half2*)(qb + (yy * 64 + xx) * 64);
#pragma unroll
        for (int c2 = 0; c2 < 32; c2++) {
            float2 qv = __half22float2(qp[c2]);
            t[c2*2+0] += qv.x * s_dw[(c2*2+0)*9 + k9];
            t[c2*2+1] += qv.y * s_dw[(c2*2+1)*9 + k9];
        }
    }

    float mu = 0.f;
#pragma unroll
    for (int c = 0; c < 64; c++) mu += t[c];
    mu *= (1.0f / 64.0f);
    float var = 0.f;
#pragma unroll
    for (int c = 0; c < 64; c++) { float d = t[c] - mu; var += d * d; }
    var *= (1.0f / 64.0f);
    float rstd = rsqrtf(var + EPSV);
#pragma unroll
    for (int c = 0; c < 64; c++) {
        float z = (t[c] - mu) * rstd * s_lnw[c] + s_lnb[c];
        t[c] = 0.5f * z * (1.0f + erff(z * 0.70710678118654752f));
    }

    float o0 = 0.f, o1 = 0.f;
#pragma unroll
    for (int c = 0; c < 64; c++) { o0 += s_offw[c] * t[c]; o1 += s_offw[64 + c] * t[c]; }
    float off0 = tanhf(o0) * (1.0f / 63.0f) * OFRV;
    float off1 = tanhf(o1) * (1.0f / 63.0f) * OFRV;

    float refy = (0.5f + (float)py) * (2.0f / 63.0f) - 1.0f;
    float refx = (0.5f + (float)px) * (2.0f / 63.0f) - 1.0f;
    float gx = (off1 + refx + 1.0f) * 0.5f * 63.0f;
    float gy = (off0 + refy + 1.0f) * 0.5f * 63.0f;

    float x0f = floorf(gx), y0f = floorf(gy);
    float wx = gx - x0f, wy = gy - y0f;
    int x0 = (int)x0f, y0 = (int)y0f;
    int x1 = x0 + 1,   y1 = y0 + 1;

    float m00 = (x0 >= 0 && x0 <= 63 && y0 >= 0 && y0 <= 63) ? 1.f : 0.f;
    float m01 = (x1 >= 0 && x1 <= 63 && y0 >= 0 && y0 <= 63) ? 1.f : 0.f;
    float m10 = (x0 >= 0 && x0 <= 63 && y1 >= 0 && y1 <= 63) ? 1.f : 0.f;
    float m11 = (x1 >= 0 && x1 <= 63 && y1 >= 0 && y1 <= 63) ? 1.f : 0.f;

    int xc0 = min(max(x0, 0), 63), xc1 = min(max(x1, 0), 63);
    int yc0 = min(max(y0, 0), 63), yc1 = min(max(y1, 0), 63);

    float w00 = m00 * (1.0f - wx) * (1.0f - wy);
    float w01 = m01 * wx * (1.0f - wy);
    float w10 = m10 * (1.0f - wx) * wy;
    float w11 = m11 * wx * wy;

    int i00 = yc0 * 64 + xc0, i01 = yc0 * 64 + xc1;
    int i10 = yc1 * 64 + xc0, i11 = yc1 * 64 + xc1;

    const float* kvb = kv + bb * CHW;
#pragma unroll
    for (int c = 0; c < 64; c++) {
        const float* kc = kvb + c * HW;
        t[c] = w00 * kc[i00] + w01 * kc[i01] + w10 * kc[i10] + w11 * kc[i11];
    }

    __half* kout = g_kh + bb * CHW + p * 64;   // [n][c]
    __half* vout = g_vh + bb * CHW + p;        // [c][n] transposed
    for (int o4 = 0; o4 < 16; o4++) {
        float ka[4], va[4];
#pragma unroll
        for (int i = 0; i < 4; i++) { ka[i] = s_bk[o4*4+i]; va[i] = s_bv[o4*4+i]; }
#pragma unroll
        for (int c = 0; c < 64; c++) {
            float x = t[c];
#pragma unroll
            for (int i = 0; i < 4; i++) {
                ka[i] += s_wk[(o4*4+i)*64 + c] * x;
                va[i] += s_wv[(o4*4+i)*64 + c] * x;
            }
        }
        ((__half2*)kout)[o4*2]   = __floats2half2_rn(ka[0], ka[1]);
        ((__half2*)kout)[o4*2+1] = __floats2half2_rn(ka[2], ka[3]);
#pragma unroll
        for (int i = 0; i < 4; i++) vout[(o4*4+i) * HW] = __float2half_rn(va[i]);
    }
}

// ================= V column sums (fp32 accum, deterministic) =================
// g_vh [c][n]: thread: c = tid>>3, oct = tid&7 -> 512 contiguous keys
__global__ void k_vsum() {
    __shared__ float red[512];
    int tid = threadIdx.x;
    int bb  = blockIdx.x;
    int c   = tid >> 3;
    int oct = tid & 7;
    const __half2* vp = (const __half2*)(g_vh + bb * CHW + c * HW + oct * 512);
    float acc = 0.f;
    for (int i = 0; i < 256; i += 4) {
        float2 a = __half22float2(vp[i]);
        float2 b = __half22float2(vp[i+1]);
        float2 d = __half22float2(vp[i+2]);
        float2 e = __half22float2(vp[i+3]);
        acc += (a.x + a.y) + (b.x + b.y) + (d.x + d.y) + (e.x + e.y);
    }
    red[c * 8 + oct] = acc;
    __syncthreads();
    if (tid < 64) {
        float s = 0.f;
#pragma unroll
        for (int g = 0; g < 8; g++) s += red[tid * 8 + g];
        g_vsum[bb * 64 + tid] = s;
    }
}

// ================= fp16 mma flash attention, ldmatrix fragments =============
// 256 thr = 8 warps. Warp w: query pair-block qw=w&3 (32 q), key half kh=w>>2.
// K smem [key][c] fp16 stride 72 halves; V smem [c][key] stride 136; P [q][key] stride 136.
#define KS0B 0
#define KS1B 18432
#define VS0B 36864
#define VS1B 54272
#define PSB  71680
#define ATTN_SMEM (PSB + 128*272)   // 106496 B

__global__ void __launch_bounds__(256) k_attn() {
    extern __shared__ char smc[];
    float* smf = (float*)smc;
    uint32_t sb = smem_u32(smc);
    int tid  = threadIdx.x;
    int wid  = tid >> 5;
    int lane = tid & 31;
    int qw   = wid & 3;
    int kh   = wid >> 2;
    int qr   = lane >> 2;
    int qc   = lane & 3;
    int lj   = lane & 7;
    int lt   = lane >> 3;
    int bb = blockIdx.y;
    int m0 = blockIdx.x * 128;

    const __half* qbh = g_qh + bb * CHW;
    const __half* kbh = g_kh + bb * CHW;
    const __half* vbh = g_vh + bb * CHW;

    // ---- Q fragments (fp16, persist in registers) ----
    uint32_t aq[2][4][4];
#pragma unroll
    for (int blk = 0; blk < 2; blk++) {
        const __half* qp = qbh + (m0 + qw * 32 + blk * 16) * 64;
#pragma unroll
        for (int kc = 0; kc < 4; kc++) {
            aq[blk][kc][0] = *(const uint32_t*)(qp +  qr      * 64 + kc*16 + qc*2);
            aq[blk][kc][1] = *(const uint32_t*)(qp + (qr + 8) * 64 + kc*16 + qc*2);
            aq[blk][kc][2] = *(const uint32_t*)(qp +  qr      * 64 + kc*16 + qc*2 + 8);
            aq[blk][kc][3] = *(const uint32_t*)(qp + (qr + 8) * 64 + kc*16 + qc*2 + 8);
        }
    }

    float oacc[2][8][4];
#pragma unroll
    for (int blk = 0; blk < 2; blk++)
#pragma unroll
        for (int nc = 0; nc < 8; nc++)
#pragma unroll
            for (int j = 0; j < 4; j++) oacc[blk][nc][j] = 0.f;
    float rs00 = 0.f, rs01 = 0.f, rs10 = 0.f, rs11 = 0.f;

    // ---- prefetch tile 0 ----
    {
#pragma unroll
        for (int it = 0; it < 4; it++) {
            int idx = tid + it * 256;                   // 0..1023
            int key = idx >> 3, c8 = idx & 7;           // K: 128 x 8 chunks
            cp16(sb + KS0B + key * 144 + c8 * 16, kbh + key * 64 + c8 * 8);
            int vc = idx >> 4, k8 = idx & 15;           // V: 64 x 16 chunks
            cp16(sb + VS0B + vc * 272 + k8 * 16, vbh + vc * HW + k8 * 8);
        }
        CP_COMMIT();
    }

    // ldmatrix per-lane address components
    uint32_t kq_off = (uint32_t)(lj * 144 + lt * 16);
    uint32_t pa0    = sb + PSB + (uint32_t)(kh * 128)
                    + (uint32_t)((qw * 32 + (lt & 1) * 8 + lj) * 272 + (lt >> 1) * 16);
    uint32_t pa1    = pa0 + 16 * 272;
    uint32_t vb_off = (uint32_t)(((lt >> 1) * 8 + lj) * 272 + (lt & 1) * 16);

    __half* Pb  = (__half*)(smc + PSB);
    __half* Pw0 = Pb + (qw * 32) * 136 + kh * 64;
    __half* Pw1 = Pw0 + 16 * 136;

    for (int i = 0; i < 32; i++) {
        __syncthreads();
        if (i + 1 < 32) {
            const __half* ks = kbh + (i + 1) * 128 * 64;
            const __half* vs = vbh + (i + 1) * 128;
            uint32_t ko = ((i + 1) & 1) ? KS1B : KS0B;
            uint32_t vo = ((i + 1) & 1) ? VS1B : VS0B;
#pragma unroll
            for (int it = 0; it < 4; it++) {
                int idx = tid + it * 256;
                int key = idx >> 3, c8 = idx & 7;
                cp16(sb + ko + key * 144 + c8 * 16, ks + key * 64 + c8 * 8);
                int vc = idx >> 4, k8 = idx & 15;
                cp16(sb + vo + vc * 272 + k8 * 16, vs + vc * HW + k8 * 8);
            }
            CP_COMMIT();
            CP_WAIT1();
        } else {
            CP_WAIT0();
        }
        __syncthreads();

        uint32_t Kb = sb + ((i & 1) ? KS1B : KS0B) + (uint32_t)(kh * 9216) + kq_off;
        uint32_t Vb = sb + ((i & 1) ? VS1B : VS0B) + (uint32_t)(kh * 128) + vb_off;

        // ---- S = Q K^T ; P' = exp(S*scale)-1 -> smem (fp16) ----
#pragma unroll
        for (int nc = 0; nc < 8; nc++) {
            uint32_t b0, b1, b2, b3, c0, c1, c2, c3;
            LDSM4(b0, b1, b2, b3, Kb + nc * 1152);
            LDSM4(c0, c1, c2, c3, Kb + nc * 1152 + 64);
            float s0[4] = {0.f, 0.f, 0.f, 0.f};
            float s1[4] = {0.f, 0.f, 0.f, 0.f};
            mma_f16(s0, aq[0][0], b0, b1, s0);
            mma_f16(s0, aq[0][1], b2, b3, s0);
            mma_f16(s0, aq[0][2], c0, c1, s0);
            mma_f16(s0, aq[0][3], c2, c3, s0);
            mma_f16(s1, aq[1][0], b0, b1, s1);
            mma_f16(s1, aq[1][1], b2, b3, s1);
            mma_f16(s1, aq[1][2], c0, c1, s1);
            mma_f16(s1, aq[1][3], c2, c3, s1);

            float e00 = __expf(s0[0] * SCALEV) - 1.0f;
            float e01 = __expf(s0[1] * SCALEV) - 1.0f;
            float e02 = __expf(s0[2] * SCALEV) - 1.0f;
            float e03 = __expf(s0[3] * SCALEV) - 1.0f;
            rs00 += e00 + e01;
            rs01 += e02 + e03;
            *(__half2*)(Pw0 +  qr      * 136 + nc * 8 + qc * 2) = __floats2half2_rn(e00, e01);
            *(__half2*)(Pw0 + (qr + 8) * 136 + nc * 8 + qc * 2) = __floats2half2_rn(e02, e03);
            float e10 = __expf(s1[0] * SCALEV) - 1.0f;
            float e11 = __expf(s1[1] * SCALEV) - 1.0f;
            float e12 = __expf(s1[2] * SCALEV) - 1.0f;
            float e13 = __expf(s1[3] * SCALEV) - 1.0f;
            rs10 += e10 + e11;
            rs11 += e12 + e13;
            *(__half2*)(Pw1 +  qr      * 136 + nc * 8 + qc * 2) = __floats2half2_rn(e10, e11);
            *(__half2*)(Pw1 + (qr + 8) * 136 + nc * 8 + qc * 2) = __floats2half2_rn(e12, e13);
        }
        __syncwarp();

        // ---- O += P' @ V ----
#pragma unroll
        for (int kc = 0; kc < 4; kc++) {
            uint32_t ap0[4], ap1[4];
            LDSM4(ap0[0], ap0[1], ap0[2], ap0[3], pa0 + kc * 32);
            LDSM4(ap1[0], ap1[1], ap1[2], ap1[3], pa1 + kc * 32);
#pragma unroll
            for (int np = 0; np < 4; np++) {
                uint32_t b0, b1, b2, b3;
                LDSM4(b0, b1, b2, b3, Vb + np * 16 * 272 + kc * 32);
                mma_f16(oacc[0][np*2    ], ap0, b0, b1, oacc[0][np*2    ]);
                mma_f16(oacc[0][np*2 + 1], ap0, b2, b3, oacc[0][np*2 + 1]);
                mma_f16(oacc[1][np*2    ], ap1, b0, b1, oacc[1][np*2    ]);
                mma_f16(oacc[1][np*2 + 1], ap1, b2, b3, oacc[1][np*2 + 1]);
            }
        }
    }

    // ---- combine key halves (reuse K-buffer region as scratch) ----
    __syncthreads();
    float* scr = smf + qw * 2240;
    if (kh == 1) {
#pragma unroll
        for (int blk = 0; blk < 2; blk++) {
            float* s = scr + blk * 1120 + lane * 35;
#pragma unroll
            for (int nc = 0; nc < 8; nc++)
#pragma unroll
                for (int j = 0; j < 4; j++) s[nc * 4 + j] = oacc[blk][nc][j];
        }
        scr[lane * 35 + 32]        = rs00;
        scr[lane * 35 + 33]        = rs01;
        scr[1120 + lane * 35 + 32] = rs10;
        scr[1120 + lane * 35 + 33] = rs11;
    }
    __syncthreads();
    if (kh == 0) {
#pragma unroll
        for (int blk = 0; blk < 2; blk++) {
            float* s = scr + blk * 1120 + lane * 35;
#pragma unroll
            for (int nc = 0; nc < 8; nc++)
#pragma unroll
                for (int j = 0; j < 4; j++) oacc[blk][nc][j] += s[nc * 4 + j];
        }
        rs00 += scr[lane * 35 + 32];
        rs01 += scr[lane * 35 + 33];
        rs10 += scr[1120 + lane * 35 + 32];
        rs11 += scr[1120 + lane * 35 + 33];

        rs00 += __shfl_xor_sync(0xffffffffu, rs00, 1);
        rs00 += __shfl_xor_sync(0xffffffffu, rs00, 2);
        rs01 += __shfl_xor_sync(0xffffffffu, rs01, 1);
        rs01 += __shfl_xor_sync(0xffffffffu, rs01, 2);
        rs10 += __shfl_xor_sync(0xffffffffu, rs10, 1);
        rs10 += __shfl_xor_sync(0xffffffffu, rs10, 2);
        rs11 += __shfl_xor_sync(0xffffffffu, rs11, 1);
        rs11 += __shfl_xor_sync(0xffffffffu, rs11, 2);
        float inv00 = 1.0f / (4096.0f + rs00);
        float inv01 = 1.0f / (4096.0f + rs01);
        float inv10 = 1.0f / (4096.0f + rs10);
        float inv11 = 1.0f / (4096.0f + rs11);

        const float* vsum = g_vsum + bb * 64;
#pragma unroll
        for (int blk = 0; blk < 2; blk++) {
            float i0 = blk ? inv10 : inv00;
            float i1 = blk ? inv11 : inv01;
            float* ob = g_ao + bb * CHW + (m0 + qw * 32 + blk * 16) * 64;
#pragma unroll
            for (int nc = 0; nc < 8; nc++) {
                float2 vs2 = *(const float2*)(vsum + nc * 8 + 2 * qc);
                *(float2*)(ob +  qr      * 64 + nc * 8 + 2 * qc) =
                    make_float2((oacc[blk][nc][0] + vs2.x) * i0, (oacc[blk][nc][1] + vs2.y) * i0);
                *(float2*)(ob + (qr + 8) * 64 + nc * 8 + 2 * qc) =
                    make_float2((oacc[blk][nc][2] + vs2.x) * i1, (oacc[blk][nc][3] + vs2.y) * i1);
            }
        }
    }
}

// ================= launch =================
extern "C" void kernel_launch(void* const* d_in, const int* in_sizes, int n_in,
                              void* d_out, int out_size) {
    const float* prompt = (const float*)d_in[0];
    const float* kv     = (const float*)d_in[1];
    const float* wq     = (const float*)d_in[2];
    const float* bq     = (const float*)d_in[3];
    const float* wk     = (const float*)d_in[4];
    const float* bk     = (const float*)d_in[5];
    const float* wv     = (const float*)d_in[6];
    const float* bv     = (const float*)d_in[7];
    const float* wo     = (const float*)d_in[8];
    const float* bo     = (const float*)d_in[9];
    const float* dw_w   = (const float*)d_in[10];
    const float* dw_b   = (const float*)d_in[11];
    const float* ln_w   = (const float*)d_in[12];
    const float* ln_b   = (const float*)d_in[13];
    const float* off_w  = (const float*)d_in[14];
    float* out = (float*)d_out;

    cudaFuncSetAttribute(k_attn, cudaFuncAttributeMaxDynamicSharedMemorySize, ATTN_SMEM);

    k_convq<<<dim3(64, BB), 256>>>(prompt, wq, bq);
    k_fuse <<<dim3(32, BB), 128>>>(kv, dw_w, dw_b, ln_w, ln_b, off_w, wk, bk, wv, bv);
    k_vsum <<<BB, 512>>>();
    k_attn <<<dim3(32, BB), 256, ATTN_SMEM>>>();
    k_convo<<<dim3(64, BB), 256>>>(wo, bo, out);
}

// round 11
// speedup vs baseline: 1.4583x; 1.4583x over previous
#include <cuda_runtime.h>
#include <cuda_fp16.h>
#include <math.h>
#include <stdint.h>

#define BB 4
#define CC 64
#define HW 4096
#define CHW (CC*HW)
#define EPSV 1e-5f
#define OFRV 4.0f
#define SCALEV 0.125f

// -------- scratch (device globals) --------
__device__ __half g_qh[BB*CHW];   // [b][p][c]  fp16
__device__ __half g_kh[BB*CHW];   // [b][n][c]  fp16
__device__ __half g_vh[BB*CHW];   // [b][n][c]  fp16 (same layout as K)
__device__ float  g_ao[BB*CHW];   // [b][p][c]  fp32
__device__ float  g_vsum[BB*CC];  // colsum of V

// ================= helpers =================
__device__ __forceinline__ uint32_t smem_u32(const void* p){
    uint32_t a;
    asm("{ .reg .u64 t; cvta.to.shared.u64 t, %1; cvt.u32.u64 %0, t; }" : "=r"(a) : "l"(p));
    return a;
}
__device__ __forceinline__ void cp16(uint32_t dst, const void* src){
    asm volatile("cp.async.cg.shared.global [%0], [%1], 16;" :: "r"(dst), "l"(src));
}
#define CP_COMMIT() asm volatile("cp.async.commit_group;" ::: "memory")
#define CP_WAIT0()  asm volatile("cp.async.wait_group 0;" ::: "memory")
#define CP_WAIT1()  asm volatile("cp.async.wait_group 1;" ::: "memory")

#define LDSM4(R0,R1,R2,R3,ADDR) \
    asm volatile("ldmatrix.sync.aligned.m8n8.x4.shared.b16 {%0,%1,%2,%3}, [%4];" \
        : "=r"(R0),"=r"(R1),"=r"(R2),"=r"(R3) : "r"(ADDR))

#define LDSM4T(R0,R1,R2,R3,ADDR) \
    asm volatile("ldmatrix.sync.aligned.m8n8.x4.trans.shared.b16 {%0,%1,%2,%3}, [%4];" \
        : "=r"(R0),"=r"(R1),"=r"(R2),"=r"(R3) : "r"(ADDR))

__device__ __forceinline__ void mma_f16(float* d, const uint32_t* a,
                                        uint32_t b0, uint32_t b1, const float* c){
    asm volatile(
        "mma.sync.aligned.m16n8k16.row.col.f32.f16.f16.f32 "
        "{%0,%1,%2,%3}, {%4,%5,%6,%7}, {%8,%9}, {%10,%11,%12,%13};"
        : "=f"(d[0]), "=f"(d[1]), "=f"(d[2]), "=f"(d[3])
        : "r"(a[0]), "r"(a[1]), "r"(a[2]), "r"(a[3]),
          "r"(b0), "r"(b1),
          "f"(c[0]), "f"(c[1]), "f"(c[2]), "f"(c[3]));
}

// ================= conv1x1 q: prompt [c][p] -> g_qh [p][c] fp16
__global__ void k_convq(const float* __restrict__ prompt,
                        const float* __restrict__ wq,
                        const float* __restrict__ bq) {
    __shared__ float ws[4096];
    __shared__ float bs[64];
    int tid = threadIdx.x;
    for (int i = tid; i < 4096; i += 256) ws[i] = wq[i];
    if (tid < 64) bs[tid] = bq[tid];
    __syncthreads();
    int qtr = tid >> 6;
    int p   = blockIdx.x * 64 + (tid & 63);
    int bb  = blockIdx.y;
    const float* xb = prompt + bb * CHW + p;
    float xr[64];
#pragma unroll
    for (int c = 0; c < 64; c++) xr[c] = xb[c * HW];
    uint2* yb = (uint2*)(g_qh + bb * CHW + p * 64 + qtr * 16);
    const float* wbase = ws + qtr * 16 * 64;
#pragma unroll
    for (int o4 = 0; o4 < 4; o4++) {
        float a0 = bs[qtr*16 + o4*4 + 0], a1 = bs[qtr*16 + o4*4 + 1];
        float a2 = bs[qtr*16 + o4*4 + 2], a3 = bs[qtr*16 + o4*4 + 3];
#pragma unroll
        for (int c = 0; c < 64; c++) {
            float x = xr[c];
            a0 += wbase[(o4*4+0)*64 + c] * x;
            a1 += wbase[(o4*4+1)*64 + c] * x;
            a2 += wbase[(o4*4+2)*64 + c] * x;
            a3 += wbase[(o4*4+3)*64 + c] * x;
        }
        __half2 h0 = __floats2half2_rn(a0, a1);
        __half2 h1 = __floats2half2_rn(a2, a3);
        yb[o4] = make_uint2(*(uint32_t*)&h0, *(uint32_t*)&h1);
    }
}

// ================= conv1x1 out: g_ao [p][c] -> out [c][p]
__global__ void k_convo(const float* __restrict__ wo,
                        const float* __restrict__ bo,
                        float* __restrict__ out) {
    __shared__ float ws[4096];
    __shared__ float bs[64];
    int tid = threadIdx.x;
    for (int i = tid; i < 4096; i += 256) ws[i] = wo[i];
    if (tid < 64) bs[tid] = bo[tid];
    __syncthreads();
    int qtr = tid >> 6;
    int p   = blockIdx.x * 64 + (tid & 63);
    int bb  = blockIdx.y;
    const float4* xb4 = (const float4*)(g_ao + bb * CHW + p * 64);
    float xr[64];
#pragma unroll
    for (int c4 = 0; c4 < 16; c4++) {
        float4 v = xb4[c4];
        xr[c4*4+0] = v.x; xr[c4*4+1] = v.y; xr[c4*4+2] = v.z; xr[c4*4+3] = v.w;
    }
    float* yb = out + bb * CHW + (qtr * 16) * HW + p;
    const float* wbase = ws + qtr * 16 * 64;
#pragma unroll
    for (int o4 = 0; o4 < 4; o4++) {
        float a0 = bs[qtr*16 + o4*4 + 0], a1 = bs[qtr*16 + o4*4 + 1];
        float a2 = bs[qtr*16 + o4*4 + 2], a3 = bs[qtr*16 + o4*4 + 3];
#pragma unroll
        for (int c = 0; c < 64; c++) {
            float x = xr[c];
            a0 += wbase[(o4*4+0)*64 + c] * x;
            a1 += wbase[(o4*4+1)*64 + c] * x;
            a2 += wbase[(o4*4+2)*64 + c] * x;
            a3 += wbase[(o4*4+3)*64 + c] * x;
        }
        yb[(o4*4+0) * HW] = a0;
        yb[(o4*4+1) * HW] = a1;
        yb[(o4*4+2) * HW] = a2;
        yb[(o4*4+3) * HW] = a3;
    }
}

// ================= fused: dw3x3 + LN + GELU + offset + tanh + bilinear + K/V proj
__global__ void k_fuse(const float* __restrict__ kv,
                       const float* __restrict__ dw_w,
                       const float* __restrict__ dw_b,
                       const float* __restrict__ ln_w,
                       const float* __restrict__ ln_b,
                       const float* __restrict__ off_w,
                       const float* __restrict__ wk,
                       const float* __restrict__ bk,
                       const float* __restrict__ wv,
                       const float* __restrict__ bv) {
    __shared__ float s_wk[4096], s_wv[4096];
    __shared__ float s_dw[576], s_dwb[64], s_lnw[64], s_lnb[64];
    __shared__ float s_offw[128], s_bk[64], s_bv[64];

    for (int i = threadIdx.x; i < 4096; i += 128) { s_wk[i] = wk[i]; s_wv[i] = wv[i]; }
    for (int i = threadIdx.x; i < 576; i += 128) s_dw[i] = dw_w[i];
    if (threadIdx.x < 64) {
        s_dwb[threadIdx.x] = dw_b[threadIdx.x];
        s_lnw[threadIdx.x] = ln_w[threadIdx.x];
        s_lnb[threadIdx.x] = ln_b[threadIdx.x];
        s_bk[threadIdx.x]  = bk[threadIdx.x];
        s_bv[threadIdx.x]  = bv[threadIdx.x];
    }
    if (threadIdx.x < 128) s_offw[threadIdx.x] = off_w[threadIdx.x];
    __syncthreads();

    int p  = blockIdx.x * 128 + threadIdx.x;
    int bb = blockIdx.y;
    int py = p >> 6;
    int px = p & 63;

    const __half* qb = g_qh + bb * CHW;   // [p][c]

    float t[64];
#pragma unroll
    for (int c = 0; c < 64; c++) t[c] = s_dwb[c];

    for (int k9 = 0; k9 < 9; k9++) {
        int dy = k9 / 3 - 1, dx = k9 % 3 - 1;
        int yy = py + dy, xx = px + dx;
        if (yy < 0 || yy > 63 || xx < 0 || xx > 63) continue;
        const uint4* qp = (const uint4*)(qb + (yy * 64 + xx) * 64);
#pragma unroll
        for (int c8 = 0; c8 < 8; c8++) {
            uint4 u = qp[c8];
            uint32_t uu[4] = {u.x, u.y, u.z, u.w};
#pragma unroll
            for (int j = 0; j < 4; j++) {
                float2 f = __half22float2(*(__half2*)&uu[j]);
                t[c8*8 + j*2    ] += f.x * s_dw[(c8*8 + j*2    )*9 + k9];
                t[c8*8 + j*2 + 1] += f.y * s_dw[(c8*8 + j*2 + 1)*9 + k9];
            }
        }
    }

    float mu = 0.f;
#pragma unroll
    for (int c = 0; c < 64; c++) mu += t[c];
    mu *= (1.0f / 64.0f);
    float var = 0.f;
#pragma unroll
    for (int c = 0; c < 64; c++) { float d = t[c] - mu; var += d * d; }
    var *= (1.0f / 64.0f);
    float rstd = rsqrtf(var + EPSV);
#pragma unroll
    for (int c = 0; c < 64; c++) {
        float z = (t[c] - mu) * rstd * s_lnw[c] + s_lnb[c];
        t[c] = 0.5f * z * (1.0f + erff(z * 0.70710678118654752f));
    }

    float o0 = 0.f, o1 = 0.f;
#pragma unroll
    for (int c = 0; c < 64; c++) { o0 += s_offw[c] * t[c]; o1 += s_offw[64 + c] * t[c]; }
    float off0 = tanhf(o0) * (1.0f / 63.0f) * OFRV;
    float off1 = tanhf(o1) * (1.0f / 63.0f) * OFRV;

    float refy = (0.5f + (float)py) * (2.0f / 63.0f) - 1.0f;
    float refx = (0.5f + (float)px) * (2.0f / 63.0f) - 1.0f;
    float gx = (off1 + refx + 1.0f) * 0.5f * 63.0f;
    float gy = (off0 + refy + 1.0f) * 0.5f * 63.0f;

    float x0f = floorf(gx), y0f = floorf(gy);
    float wx = gx - x0f, wy = gy - y0f;
    int x0 = (int)x0f, y0 = (int)y0f;
    int x1 = x0 + 1,   y1 = y0 + 1;

    float m00 = (x0 >= 0 && x0 <= 63 && y0 >= 0 && y0 <= 63) ? 1.f : 0.f;
    float m01 = (x1 >= 0 && x1 <= 63 && y0 >= 0 && y0 <= 63) ? 1.f : 0.f;
    float m10 = (x0 >= 0 && x0 <= 63 && y1 >= 0 && y1 <= 63) ? 1.f : 0.f;
    float m11 = (x1 >= 0 && x1 <= 63 && y1 >= 0 && y1 <= 63) ? 1.f : 0.f;

    int xc0 = min(max(x0, 0), 63), xc1 = min(max(x1, 0), 63);
    int yc0 = min(max(y0, 0), 63), yc1 = min(max(y1, 0), 63);

    float w00 = m00 * (1.0f - wx) * (1.0f - wy);
    float w01 = m01 * wx * (1.0f - wy);
    float w10 = m10 * (1.0f - wx) * wy;
    float w11 = m11 * wx * wy;

    int i00 = yc0 * 64 + xc0, i01 = yc0 * 64 + xc1;
    int i10 = yc1 * 64 + xc0, i11 = yc1 * 64 + xc1;

    const float* kvb = kv + bb * CHW;
#pragma unroll
    for (int c = 0; c < 64; c++) {
        const float* kc = kvb + c * HW;
        t[c] = w00 * kc[i00] + w01 * kc[i01] + w10 * kc[i10] + w11 * kc[i11];
    }

    __half* kout = g_kh + bb * CHW + p * 64;   // [n][c]
    __half* vout = g_vh + bb * CHW + p * 64;   // [n][c]
    for (int o4 = 0; o4 < 16; o4++) {
        float ka[4], va[4];
#pragma unroll
        for (int i = 0; i < 4; i++) { ka[i] = s_bk[o4*4+i]; va[i] = s_bv[o4*4+i]; }
#pragma unroll
        for (int c = 0; c < 64; c++) {
            float x = t[c];
#pragma unroll
            for (int i = 0; i < 4; i++) {
                ka[i] += s_wk[(o4*4+i)*64 + c] * x;
                va[i] += s_wv[(o4*4+i)*64 + c] * x;
            }
        }
        __half2 k0 = __floats2half2_rn(ka[0], ka[1]);
        __half2 k1 = __floats2half2_rn(ka[2], ka[3]);
        __half2 v0 = __floats2half2_rn(va[0], va[1]);
        __half2 v1 = __floats2half2_rn(va[2], va[3]);
        ((uint2*)kout)[o4] = make_uint2(*(uint32_t*)&k0, *(uint32_t*)&k1);
        ((uint2*)vout)[o4] = make_uint2(*(uint32_t*)&v0, *(uint32_t*)&v1);
    }
}

// ================= V column sums (fp32 accum, deterministic) =================
// g_vh [n][c]: seg = tid>>6 (8 segs of 512 keys), c = tid&63
__global__ void k_vsum() {
    __shared__ float red[512];
    int tid = threadIdx.x;
    int bb  = blockIdx.x;
    int seg = tid >> 6;
    int c   = tid & 63;
    const __half* vb = g_vh + bb * CHW + c;
    float acc = 0.f;
    int n0 = seg * 512;
    for (int i = 0; i < 512; i += 4) {
        acc += __half2float(vb[(n0 + i    ) * 64]);
        acc += __half2float(vb[(n0 + i + 1) * 64]);
        acc += __half2float(vb[(n0 + i + 2) * 64]);
        acc += __half2float(vb[(n0 + i + 3) * 64]);
    }
    red[seg * 64 + c] = acc;
    __syncthreads();
    if (tid < 64) {
        float s = 0.f;
#pragma unroll
        for (int g = 0; g < 8; g++) s += red[g * 64 + tid];
        g_vsum[bb * 64 + tid] = s;
    }
}

// ================= fp16 mma flash attention, ldmatrix fragments =============
// 256 thr = 8 warps. Warp w: query pair-block qw=w&3 (32 q), key half kh=w>>2.
// K and V smem both [key][c] fp16, 144-byte rows. V fragments via ldmatrix.trans.
// P [q][key] fp16, 272-byte rows.
#define KS0B 0
#define KS1B 18432
#define VS0B 36864
#define VS1B 55296
#define PSB  73728
#define ATTN_SMEM (PSB + 128*272)   // 108544 B

__global__ void __launch_bounds__(256) k_attn() {
    extern __shared__ char smc[];
    float* smf = (float*)smc;
    uint32_t sb = smem_u32(smc);
    int tid  = threadIdx.x;
    int wid  = tid >> 5;
    int lane = tid & 31;
    int qw   = wid & 3;
    int kh   = wid >> 2;
    int qr   = lane >> 2;
    int qc   = lane & 3;
    int lj   = lane & 7;
    int lt   = lane >> 3;
    int bb = blockIdx.y;
    int m0 = blockIdx.x * 128;

    const __half* qbh = g_qh + bb * CHW;
    const __half* kbh = g_kh + bb * CHW;
    const __half* vbh = g_vh + bb * CHW;

    // ---- Q fragments (fp16, persist in registers) ----
    uint32_t aq[2][4][4];
#pragma unroll
    for (int blk = 0; blk < 2; blk++) {
        const __half* qp = qbh + (m0 + qw * 32 + blk * 16) * 64;
#pragma unroll
        for (int kc = 0; kc < 4; kc++) {
            aq[blk][kc][0] = *(const uint32_t*)(qp +  qr      * 64 + kc*16 + qc*2);
            aq[blk][kc][1] = *(const uint32_t*)(qp + (qr + 8) * 64 + kc*16 + qc*2);
            aq[blk][kc][2] = *(const uint32_t*)(qp +  qr      * 64 + kc*16 + qc*2 + 8);
            aq[blk][kc][3] = *(const uint32_t*)(qp + (qr + 8) * 64 + kc*16 + qc*2 + 8);
        }
    }

    float oacc[2][8][4];
#pragma unroll
    for (int blk = 0; blk < 2; blk++)
#pragma unroll
        for (int nc = 0; nc < 8; nc++)
#pragma unroll
            for (int j = 0; j < 4; j++) oacc[blk][nc][j] = 0.f;
    float rs00 = 0.f, rs01 = 0.f, rs10 = 0.f, rs11 = 0.f;

    // ---- prefetch tile 0 (K and V identical geometry) ----
    {
#pragma unroll
        for (int it = 0; it < 4; it++) {
            int idx = tid + it * 256;                   // 0..1023
            int key = idx >> 3, c8 = idx & 7;
            cp16(sb + KS0B + key * 144 + c8 * 16, kbh + key * 64 + c8 * 8);
            cp16(sb + VS0B + key * 144 + c8 * 16, vbh + key * 64 + c8 * 8);
        }
        CP_COMMIT();
    }

    // ldmatrix per-lane address components
    uint32_t kq_off = (uint32_t)(lj * 144 + lt * 16);                       // K (non-trans)
    uint32_t vt_off = (uint32_t)(((lt & 1) * 8 + lj) * 144 + (lt >> 1) * 16); // V (trans)
    uint32_t pa0    = sb + PSB + (uint32_t)(kh * 128)
                    + (uint32_t)((qw * 32 + (lt & 1) * 8 + lj) * 272 + (lt >> 1) * 16);
    uint32_t pa1    = pa0 + 16 * 272;

    __half* Pb  = (__half*)(smc + PSB);
    __half* Pw0 = Pb + (qw * 32) * 136 + kh * 64;
    __half* Pw1 = Pw0 + 16 * 136;

    for (int i = 0; i < 32; i++) {
        __syncthreads();
        if (i + 1 < 32) {
            const __half* ks = kbh + (i + 1) * 128 * 64;
            const __half* vs = vbh + (i + 1) * 128 * 64;
            uint32_t ko = ((i + 1) & 1) ? KS1B : KS0B;
            uint32_t vo = ((i + 1) & 1) ? VS1B : VS0B;
#pragma unroll
            for (int it = 0; it < 4; it++) {
                int idx = tid + it * 256;
                int key = idx >> 3, c8 = idx & 7;
                cp16(sb + ko + key * 144 + c8 * 16, ks + key * 64 + c8 * 8);
                cp16(sb + vo + key * 144 + c8 * 16, vs + key * 64 + c8 * 8);
            }
            CP_COMMIT();
            CP_WAIT1();
        } else {
            CP_WAIT0();
        }
        __syncthreads();

        uint32_t Kb = sb + ((i & 1) ? KS1B : KS0B) + (uint32_t)(kh * 9216) + kq_off;
        uint32_t Vb = sb + ((i & 1) ? VS1B : VS0B) + (uint32_t)(kh * 9216) + vt_off;

        // ---- S = Q K^T ; P' = exp(S*scale)-1 -> smem (fp16) ----
#pragma unroll
        for (int nc = 0; nc < 8; nc++) {
            uint32_t b0, b1, b2, b3, c0, c1, c2, c3;
            LDSM4(b0, b1, b2, b3, Kb + nc * 1152);
            LDSM4(c0, c1, c2, c3, Kb + nc * 1152 + 64);
            float s0[4] = {0.f, 0.f, 0.f, 0.f};
            float s1[4] = {0.f, 0.f, 0.f, 0.f};
            mma_f16(s0, aq[0][0], b0, b1, s0);
            mma_f16(s0, aq[0][1], b2, b3, s0);
            mma_f16(s0, aq[0][2], c0, c1, s0);
            mma_f16(s0, aq[0][3], c2, c3, s0);
            mma_f16(s1, aq[1][0], b0, b1, s1);
            mma_f16(s1, aq[1][1], b2, b3, s1);
            mma_f16(s1, aq[1][2], c0, c1, s1);
            mma_f16(s1, aq[1][3], c2, c3, s1);

            float e00 = __expf(s0[0] * SCALEV) - 1.0f;
            float e01 = __expf(s0[1] * SCALEV) - 1.0f;
            float e02 = __expf(s0[2] * SCALEV) - 1.0f;
            float e03 = __expf(s0[3] * SCALEV) - 1.0f;
            rs00 += e00 + e01;
            rs01 += e02 + e03;
            *(__half2*)(Pw0 +  qr      * 136 + nc * 8 + qc * 2) = __floats2half2_rn(e00, e01);
            *(__half2*)(Pw0 + (qr + 8) * 136 + nc * 8 + qc * 2) = __floats2half2_rn(e02, e03);
            float e10 = __expf(s1[0] * SCALEV) - 1.0f;
            float e11 = __expf(s1[1] * SCALEV) - 1.0f;
            float e12 = __expf(s1[2] * SCALEV) - 1.0f;
            float e13 = __expf(s1[3] * SCALEV) - 1.0f;
            rs10 += e10 + e11;
            rs11 += e12 + e13;
            *(__half2*)(Pw1 +  qr      * 136 + nc * 8 + qc * 2) = __floats2half2_rn(e10, e11);
            *(__half2*)(Pw1 + (qr + 8) * 136 + nc * 8 + qc * 2) = __floats2half2_rn(e12, e13);
        }
        __syncwarp();

        // ---- O += P' @ V  (V fragments via ldmatrix.trans on [key][c]) ----
#pragma unroll
        for (int kc = 0; kc < 4; kc++) {
            uint32_t ap0[4], ap1[4];
            LDSM4(ap0[0], ap0[1], ap0[2], ap0[3], pa0 + kc * 32);
            LDSM4(ap1[0], ap1[1], ap1[2], ap1[3], pa1 + kc * 32);
            uint32_t Vk = Vb + (uint32_t)(kc * 16 * 144);
#pragma unroll
            for (int np = 0; np < 4; np++) {
                uint32_t b0, b1, b2, b3;
                LDSM4T(b0, b1, b2, b3, Vk + np * 32);
                mma_f16(oacc[0][np*2    ], ap0, b0, b1, oacc[0][np*2    ]);
                mma_f16(oacc[0][np*2 + 1], ap0, b2, b3, oacc[0][np*2 + 1]);
                mma_f16(oacc[1][np*2    ], ap1, b0, b1, oacc[1][np*2    ]);
                mma_f16(oacc[1][np*2 + 1], ap1, b2, b3, oacc[1][np*2 + 1]);
            }
        }
    }

    // ---- combine key halves (reuse K/V-buffer region as scratch) ----
    __syncthreads();
    float* scr = smf + qw * 2240;
    if (kh == 1) {
#pragma unroll
        for (int blk = 0; blk < 2; blk++) {
            float* s = scr + blk * 1120 + lane * 35;
#pragma unroll
            for (int nc = 0; nc < 8; nc++)
#pragma unroll
                for (int j = 0; j < 4; j++) s[nc * 4 + j] = oacc[blk][nc][j];
        }
        scr[lane * 35 + 32]        = rs00;
        scr[lane * 35 + 33]        = rs01;
        scr[1120 + lane * 35 + 32] = rs10;
        scr[1120 + lane * 35 + 33] = rs11;
    }
    __syncthreads();
    if (kh == 0) {
#pragma unroll
        for (int blk = 0; blk < 2; blk++) {
            float* s = scr + blk * 1120 + lane * 35;
#pragma unroll
            for (int nc = 0; nc < 8; nc++)
#pragma unroll
                for (int j = 0; j < 4; j++) oacc[blk][nc][j] += s[nc * 4 + j];
        }
        rs00 += scr[lane * 35 + 32];
        rs01 += scr[lane * 35 + 33];
        rs10 += scr[1120 + lane * 35 + 32];
        rs11 += scr[1120 + lane * 35 + 33];

        rs00 += __shfl_xor_sync(0xffffffffu, rs00, 1);
        rs00 += __shfl_xor_sync(0xffffffffu, rs00, 2);
        rs01 += __shfl_xor_sync(0xffffffffu, rs01, 1);
        rs01 += __shfl_xor_sync(0xffffffffu, rs01, 2);
        rs10 += __shfl_xor_sync(0xffffffffu, rs10, 1);
        rs10 += __shfl_xor_sync(0xffffffffu, rs10, 2);
        rs11 += __shfl_xor_sync(0xffffffffu, rs11, 1);
        rs11 += __shfl_xor_sync(0xffffffffu, rs11, 2);
        float inv00 = 1.0f / (4096.0f + rs00);
        float inv01 = 1.0f / (4096.0f + rs01);
        float inv10 = 1.0f / (4096.0f + rs10);
        float inv11 = 1.0f / (4096.0f + rs11);

        const float* vsum = g_vsum + bb * 64;
#pragma unroll
        for (int blk = 0; blk < 2; blk++) {
            float i0 = blk ? inv10 : inv00;
            float i1 = blk ? inv11 : inv01;
            float* ob = g_ao + bb * CHW + (m0 + qw * 32 + blk * 16) * 64;
#pragma unroll
            for (int nc = 0; nc < 8; nc++) {
                float2 vs2 = *(const float2*)(vsum + nc * 8 + 2 * qc);
                *(float2*)(ob +  qr      * 64 + nc * 8 + 2 * qc) =
                    make_float2((oacc[blk][nc][0] + vs2.x) * i0, (oacc[blk][nc][1] + vs2.y) * i0);
                *(float2*)(ob + (qr + 8) * 64 + nc * 8 + 2 * qc) =
                    make_float2((oacc[blk][nc][2] + vs2.x) * i1, (oacc[blk][nc][3] + vs2.y) * i1);
            }
        }
    }
}

// ================= launch =================
extern "C" void kernel_launch(void* const* d_in, const int* in_sizes, int n_in,
                              void* d_out, int out_size) {
    const float* prompt = (const float*)d_in[0];
    const float* kv     = (const float*)d_in[1];
    const float* wq     = (const float*)d_in[2];
    const float* bq     = (const float*)d_in[3];
    const float* wk     = (const float*)d_in[4];
    const float* bk     = (const float*)d_in[5];
    const float* wv     = (const float*)d_in[6];
    const float* bv     = (const float*)d_in[7];
    const float* wo     = (const float*)d_in[8];
    const float* bo     = (const float*)d_in[9];
    const float* dw_w   = (const float*)d_in[10];
    const float* dw_b   = (const float*)d_in[11];
    const float* ln_w   = (const float*)d_in[12];
    const float* ln_b   = (const float*)d_in[13];
    const float* off_w  = (const float*)d_in[14];
    float* out = (float*)d_out;

    cudaFuncSetAttribute(k_attn, cudaFuncAttributeMaxDynamicSharedMemorySize, ATTN_SMEM);

    k_convq<<<dim3(64, BB), 256>>>(prompt, wq, bq);
    k_fuse <<<dim3(32, BB), 128>>>(kv, dw_w, dw_b, ln_w, ln_b, off_w, wk, bk, wv, bv);
    k_vsum <<<BB, 512>>>();
    k_attn <<<dim3(32, BB), 256, ATTN_SMEM>>>();
    k_convo<<<dim3(64, BB), 256>>>(wo, bo, out);
}

// round 13
// speedup vs baseline: 1.5490x; 1.0623x over previous
#include <cuda_runtime.h>
#include <cuda_fp16.h>
#include <math.h>
#include <stdint.h>

#define BB 4
#define CC 64
#define HW 4096
#define CHW (CC*HW)
#define EPSV 1e-5f
#define OFRV 4.0f
#define SCALEV 0.125f

// -------- scratch (device globals) --------
__device__ __half g_qh[BB*CHW];   // [b][p][c]  fp16
__device__ __half g_xs[BB*CHW];   // [b][p][c]  gathered features fp16
__device__ __half g_kh[BB*CHW];   // [b][n][c]  fp16
__device__ __half g_vh[BB*CHW];   // [b][n][c]  fp16
__device__ float  g_ao[BB*CHW];   // [b][p][c]  fp32
__device__ float  g_vsum[BB*CC];  // colsum of V

// ================= helpers =================
__device__ __forceinline__ uint32_t smem_u32(const void* p){
    uint32_t a;
    asm("{ .reg .u64 t; cvta.to.shared.u64 t, %1; cvt.u32.u64 %0, t; }" : "=r"(a) : "l"(p));
    return a;
}
__device__ __forceinline__ void cp16(uint32_t dst, const void* src){
    asm volatile("cp.async.cg.shared.global [%0], [%1], 16;" :: "r"(dst), "l"(src));
}
#define CP_COMMIT() asm volatile("cp.async.commit_group;" ::: "memory")
#define CP_WAIT0()  asm volatile("cp.async.wait_group 0;" ::: "memory")
#define CP_WAIT1()  asm volatile("cp.async.wait_group 1;" ::: "memory")

#define LDSM4(R0,R1,R2,R3,ADDR) \
    asm volatile("ldmatrix.sync.aligned.m8n8.x4.shared.b16 {%0,%1,%2,%3}, [%4];" \
        : "=r"(R0),"=r"(R1),"=r"(R2),"=r"(R3) : "r"(ADDR))

#define LDSM4T(R0,R1,R2,R3,ADDR) \
    asm volatile("ldmatrix.sync.aligned.m8n8.x4.trans.shared.b16 {%0,%1,%2,%3}, [%4];" \
        : "=r"(R0),"=r"(R1),"=r"(R2),"=r"(R3) : "r"(ADDR))

__device__ __forceinline__ void mma_f16(float* d, const uint32_t* a,
                                        uint32_t b0, uint32_t b1, const float* c){
    asm volatile(
        "mma.sync.aligned.m16n8k16.row.col.f32.f16.f16.f32 "
        "{%0,%1,%2,%3}, {%4,%5,%6,%7}, {%8,%9}, {%10,%11,%12,%13};"
        : "=f"(d[0]), "=f"(d[1]), "=f"(d[2]), "=f"(d[3])
        : "r"(a[0]), "r"(a[1]), "r"(a[2]), "r"(a[3]),
          "r"(b0), "r"(b1),
          "f"(c[0]), "f"(c[1]), "f"(c[2]), "f"(c[3]));
}

// ================= conv1x1 q: prompt [c][p] -> g_qh [p][c] fp16
__global__ void k_convq(const float* __restrict__ prompt,
                        const float* __restrict__ wq,
                        const float* __restrict__ bq) {
    __shared__ float ws[4096];
    __shared__ float bs[64];
    int tid = threadIdx.x;
    for (int i = tid; i < 4096; i += 256) ws[i] = wq[i];
    if (tid < 64) bs[tid] = bq[tid];
    __syncthreads();
    int qtr = tid >> 6;
    int p   = blockIdx.x * 64 + (tid & 63);
    int bb  = blockIdx.y;
    const float* xb = prompt + bb * CHW + p;
    float xr[64];
#pragma unroll
    for (int c = 0; c < 64; c++) xr[c] = xb[c * HW];
    uint2* yb = (uint2*)(g_qh + bb * CHW + p * 64 + qtr * 16);
    const float* wbase = ws + qtr * 16 * 64;
#pragma unroll
    for (int o4 = 0; o4 < 4; o4++) {
        float a0 = bs[qtr*16 + o4*4 + 0], a1 = bs[qtr*16 + o4*4 + 1];
        float a2 = bs[qtr*16 + o4*4 + 2], a3 = bs[qtr*16 + o4*4 + 3];
#pragma unroll
        for (int c = 0; c < 64; c++) {
            float x = xr[c];
            a0 += wbase[(o4*4+0)*64 + c] * x;
            a1 += wbase[(o4*4+1)*64 + c] * x;
            a2 += wbase[(o4*4+2)*64 + c] * x;
            a3 += wbase[(o4*4+3)*64 + c] * x;
        }
        __half2 h0 = __floats2half2_rn(a0, a1);
        __half2 h1 = __floats2half2_rn(a2, a3);
        yb[o4] = make_uint2(*(uint32_t*)&h0, *(uint32_t*)&h1);
    }
}

// ================= conv1x1 out: g_ao [p][c] -> out [c][p]
__global__ void k_convo(const float* __restrict__ wo,
                        const float* __restrict__ bo,
                        float* __restrict__ out) {
    __shared__ float ws[4096];
    __shared__ float bs[64];
    int tid = threadIdx.x;
    for (int i = tid; i < 4096; i += 256) ws[i] = wo[i];
    if (tid < 64) bs[tid] = bo[tid];
    __syncthreads();
    int qtr = tid >> 6;
    int p   = blockIdx.x * 64 + (tid & 63);
    int bb  = blockIdx.y;
    const float4* xb4 = (const float4*)(g_ao + bb * CHW + p * 64);
    float xr[64];
#pragma unroll
    for (int c4 = 0; c4 < 16; c4++) {
        float4 v = xb4[c4];
        xr[c4*4+0] = v.x; xr[c4*4+1] = v.y; xr[c4*4+2] = v.z; xr[c4*4+3] = v.w;
    }
    float* yb = out + bb * CHW + (qtr * 16) * HW + p;
    const float* wbase = ws + qtr * 16 * 64;
#pragma unroll
    for (int o4 = 0; o4 < 4; o4++) {
        float a0 = bs[qtr*16 + o4*4 + 0], a1 = bs[qtr*16 + o4*4 + 1];
        float a2 = bs[qtr*16 + o4*4 + 2], a3 = bs[qtr*16 + o4*4 + 3];
#pragma unroll
        for (int c = 0; c < 64; c++) {
            float x = xr[c];
            a0 += wbase[(o4*4+0)*64 + c] * x;
            a1 += wbase[(o4*4+1)*64 + c] * x;
            a2 += wbase[(o4*4+2)*64 + c] * x;
            a3 += wbase[(o4*4+3)*64 + c] * x;
        }
        yb[(o4*4+0) * HW] = a0;
        yb[(o4*4+1) * HW] = a1;
        yb[(o4*4+2) * HW] = a2;
        yb[(o4*4+3) * HW] = a3;
    }
}

// ================= fused: dw3x3 + LN + GELU + offset + tanh + bilinear -> xs fp16
__global__ void k_fuse(const float* __restrict__ kv,
                       const float* __restrict__ dw_w,
                       const float* __restrict__ dw_b,
                       const float* __restrict__ ln_w,
                       const float* __restrict__ ln_b,
                       const float* __restrict__ off_w) {
    __shared__ float s_dw[576], s_dwb[64], s_lnw[64], s_lnb[64];
    __shared__ float s_offw[128];

    for (int i = threadIdx.x; i < 576; i += 128) s_dw[i] = dw_w[i];
    if (threadIdx.x < 64) {
        s_dwb[threadIdx.x] = dw_b[threadIdx.x];
        s_lnw[threadIdx.x] = ln_w[threadIdx.x];
        s_lnb[threadIdx.x] = ln_b[threadIdx.x];
    }
    if (threadIdx.x < 128) s_offw[threadIdx.x] = off_w[threadIdx.x];
    __syncthreads();

    int p  = blockIdx.x * 128 + threadIdx.x;
    int bb = blockIdx.y;
    int py = p >> 6;
    int px = p & 63;

    const __half* qb = g_qh + bb * CHW;   // [p][c]

    float t[64];
#pragma unroll
    for (int c = 0; c < 64; c++) t[c] = s_dwb[c];

    for (int k9 = 0; k9 < 9; k9++) {
        int dy = k9 / 3 - 1, dx = k9 % 3 - 1;
        int yy = py + dy, xx = px + dx;
        if (yy < 0 || yy > 63 || xx < 0 || xx > 63) continue;
        const uint4* qp = (const uint4*)(qb + (yy * 64 + xx) * 64);
#pragma unroll
        for (int c8 = 0; c8 < 8; c8++) {
            uint4 u = qp[c8];
            uint32_t uu[4] = {u.x, u.y, u.z, u.w};
#pragma unroll
            for (int j = 0; j < 4; j++) {
                float2 f = __half22float2(*(__half2*)&uu[j]);
                t[c8*8 + j*2    ] += f.x * s_dw[(c8*8 + j*2    )*9 + k9];
                t[c8*8 + j*2 + 1] += f.y * s_dw[(c8*8 + j*2 + 1)*9 + k9];
            }
        }
    }

    float mu = 0.f;
#pragma unroll
    for (int c = 0; c < 64; c++) mu += t[c];
    mu *= (1.0f / 64.0f);
    float var = 0.f;
#pragma unroll
    for (int c = 0; c < 64; c++) { float d = t[c] - mu; var += d * d; }
    var *= (1.0f / 64.0f);
    float rstd = rsqrtf(var + EPSV);
#pragma unroll
    for (int c = 0; c < 64; c++) {
        float z = (t[c] - mu) * rstd * s_lnw[c] + s_lnb[c];
        t[c] = 0.5f * z * (1.0f + erff(z * 0.70710678118654752f));
    }

    float o0 = 0.f, o1 = 0.f;
#pragma unroll
    for (int c = 0; c < 64; c++) { o0 += s_offw[c] * t[c]; o1 += s_offw[64 + c] * t[c]; }
    float off0 = tanhf(o0) * (1.0f / 63.0f) * OFRV;
    float off1 = tanhf(o1) * (1.0f / 63.0f) * OFRV;

    float refy = (0.5f + (float)py) * (2.0f / 63.0f) - 1.0f;
    float refx = (0.5f + (float)px) * (2.0f / 63.0f) - 1.0f;
    float gx = (off1 + refx + 1.0f) * 0.5f * 63.0f;
    float gy = (off0 + refy + 1.0f) * 0.5f * 63.0f;

    float x0f = floorf(gx), y0f = floorf(gy);
    float wx = gx - x0f, wy = gy - y0f;
    int x0 = (int)x0f, y0 = (int)y0f;
    int x1 = x0 + 1,   y1 = y0 + 1;

    float m00 = (x0 >= 0 && x0 <= 63 && y0 >= 0 && y0 <= 63) ? 1.f : 0.f;
    float m01 = (x1 >= 0 && x1 <= 63 && y0 >= 0 && y0 <= 63) ? 1.f : 0.f;
    float m10 = (x0 >= 0 && x0 <= 63 && y1 >= 0 && y1 <= 63) ? 1.f : 0.f;
    float m11 = (x1 >= 0 && x1 <= 63 && y1 >= 0 && y1 <= 63) ? 1.f : 0.f;

    int xc0 = min(max(x0, 0), 63), xc1 = min(max(x1, 0), 63);
    int yc0 = min(max(y0, 0), 63), yc1 = min(max(y1, 0), 63);

    float w00 = m00 * (1.0f - wx) * (1.0f - wy);
    float w01 = m01 * wx * (1.0f - wy);
    float w10 = m10 * (1.0f - wx) * wy;
    float w11 = m11 * wx * wy;

    int i00 = yc0 * 64 + xc0, i01 = yc0 * 64 + xc1;
    int i10 = yc1 * 64 + xc0, i11 = yc1 * 64 + xc1;

    const float* kvb = kv + bb * CHW;
    uint2* xout = (uint2*)(g_xs + bb * CHW + p * 64);
#pragma unroll
    for (int c4 = 0; c4 < 16; c4++) {
        float v[4];
#pragma unroll
        for (int j = 0; j < 4; j++) {
            const float* kc = kvb + (c4*4 + j) * HW;
            v[j] = w00 * kc[i00] + w01 * kc[i01] + w10 * kc[i10] + w11 * kc[i11];
        }
        __half2 h0 = __floats2half2_rn(v[0], v[1]);
        __half2 h1 = __floats2half2_rn(v[2], v[3]);
        xout[c4] = make_uint2(*(uint32_t*)&h0, *(uint32_t*)&h1);
    }
}

// ================= K/V projection GEMM (fp16 mma): K = xs*wk^T+bk, V = xs*wv^T+bv
// 256 thr = 8 warps; block handles 256 pixels (warp: 32 pixels = 2 m16 blocks)
#define KVP_XS 0
#define KVP_WK 36864
#define KVP_WV 46080
#define KVP_SMEM 55296

__global__ void __launch_bounds__(256) k_kvproj(const float* __restrict__ wk,
                                                const float* __restrict__ bk,
                                                const float* __restrict__ wv,
                                                const float* __restrict__ bv) {
    extern __shared__ char smc[];
    uint32_t sb = smem_u32(smc);
    int tid = threadIdx.x, wid = tid >> 5, lane = tid & 31;
    int lj = lane & 7, lt = lane >> 3;
    int qr = lane >> 2, qc = lane & 3;
    int bb = blockIdx.y;
    int p0 = blockIdx.x * 256;

    const __half* xsb = g_xs + bb * CHW + p0 * 64;
#pragma unroll
    for (int it = 0; it < 8; it++) {
        int idx = tid + it * 256;
        int row = idx >> 3, c8 = idx & 7;
        cp16(sb + KVP_XS + row * 144 + c8 * 16, xsb + row * 64 + c8 * 8);
    }
    CP_COMMIT();

    __half* swk = (__half*)(smc + KVP_WK);
    __half* swv = (__half*)(smc + KVP_WV);
    for (int i = tid; i < 4096; i += 256) {
        int o = i >> 6, c = i & 63;
        swk[o * 72 + c] = __float2half_rn(wk[i]);
        swv[o * 72 + c] = __float2half_rn(wv[i]);
    }
    CP_WAIT0();
    __syncthreads();

    // A fragments: xs rows wid*32 + blk*16
    uint32_t xa = sb + KVP_XS + (uint32_t)((wid * 32 + (lt & 1) * 8 + lj) * 144 + (lt >> 1) * 16);
    uint32_t ap[2][4][4];
#pragma unroll
    for (int blk = 0; blk < 2; blk++)
#pragma unroll
        for (int kc = 0; kc < 4; kc++)
            LDSM4(ap[blk][kc][0], ap[blk][kc][1], ap[blk][kc][2], ap[blk][kc][3],
                  xa + blk * 16 * 144 + kc * 32);

    uint32_t wfrag = (uint32_t)(lj * 144 + lt * 16);

#pragma unroll
    for (int mat = 0; mat < 2; mat++) {
        uint32_t wb = sb + (mat ? KVP_WV : KVP_WK) + wfrag;
        const float* bias = mat ? bv : bk;
        __half* gout = (mat ? g_vh : g_kh) + bb * CHW;

        float oa[2][8][4];
#pragma unroll
        for (int blk = 0; blk < 2; blk++)
#pragma unroll
            for (int nc = 0; nc < 8; nc++)
#pragma unroll
                for (int j = 0; j < 4; j++) oa[blk][nc][j] = 0.f;

#pragma unroll
        for (int nc = 0; nc < 8; nc++) {
            uint32_t b0, b1, b2, b3, c0, c1, c2, c3;
            LDSM4(b0, b1, b2, b3, wb + nc * 1152);
            LDSM4(c0, c1, c2, c3, wb + nc * 1152 + 64);
#pragma unroll
            for (int blk = 0; blk < 2; blk++) {
                mma_f16(oa[blk][nc], ap[blk][0], b0, b1, oa[blk][nc]);
                mma_f16(oa[blk][nc], ap[blk][1], b2, b3, oa[blk][nc]);
                mma_f16(oa[blk][nc], ap[blk][2], c0, c1, oa[blk][nc]);
                mma_f16(oa[blk][nc], ap[blk][3], c2, c3, oa[blk][nc]);
            }
        }

#pragma unroll
        for (int blk = 0; blk < 2; blk++) {
            int row0 = p0 + wid * 32 + blk * 16 + qr;
#pragma unroll
            for (int nc = 0; nc < 8; nc++) {
                float2 bv2 = *(const float2*)(bias + nc * 8 + qc * 2);
                __half2 h0 = __floats2half2_rn(oa[blk][nc][0] + bv2.x, oa[blk][nc][1] + bv2.y);
                __half2 h1 = __floats2half2_rn(oa[blk][nc][2] + bv2.x, oa[blk][nc][3] + bv2.y);
                *(__half2*)(gout +  row0      * 64 + nc * 8 + qc * 2) = h0;
                *(__half2*)(gout + (row0 + 8) * 64 + nc * 8 + qc * 2) = h1;
            }
        }
    }
}

// ================= V column sums (fp32 accum, deterministic) =================
__global__ void k_vsum() {
    __shared__ float red[512];
    int tid = threadIdx.x;
    int bb  = blockIdx.x;
    int seg = tid >> 6;
    int c   = tid & 63;
    const __half* vb = g_vh + bb * CHW + c;
    float acc = 0.f;
    int n0 = seg * 512;
    for (int i = 0; i < 512; i += 4) {
        acc += __half2float(vb[(n0 + i    ) * 64]);
        acc += __half2float(vb[(n0 + i + 1) * 64]);
        acc += __half2float(vb[(n0 + i + 2) * 64]);
        acc += __half2float(vb[(n0 + i + 3) * 64]);
    }
    red[seg * 64 + c] = acc;
    __syncthreads();
    if (tid < 64) {
        float s = 0.f;
#pragma unroll
        for (int g = 0; g < 8; g++) s += red[g * 64 + tid];
        g_vsum[bb * 64 + tid] = s;
    }
}

// ================= fp16 mma flash attention, 512 thr / 16 warps =============
// Warp w: query block qw=w&7 (16 q), key half kh=w>>3 (64 keys of 128-tile).
// K, V smem [key][c] fp16 144-byte rows; V frags via ldmatrix.trans; P 272-byte rows.
#define KS0B 0
#define KS1B 18432
#define VS0B 36864
#define VS1B 55296
#define PSB  73728
#define ATTN_SMEM (PSB + 128*272)   // 108544 B

__global__ void __launch_bounds__(512) k_attn() {
    extern __shared__ char smc[];
    float* smf = (float*)smc;
    uint32_t sb = smem_u32(smc);
    int tid  = threadIdx.x;
    int wid  = tid >> 5;
    int lane = tid & 31;
    int qw   = wid & 7;
    int kh   = wid >> 3;
    int qr   = lane >> 2;
    int qc   = lane & 3;
    int lj   = lane & 7;
    int lt   = lane >> 3;
    int bb = blockIdx.y;
    int m0 = blockIdx.x * 128;

    const __half* qbh = g_qh + bb * CHW;
    const __half* kbh = g_kh + bb * CHW;
    const __half* vbh = g_vh + bb * CHW;

    // ---- Q fragments (fp16, persist) ----
    uint32_t aq[4][4];
    {
        const __half* qp = qbh + (m0 + qw * 16) * 64;
#pragma unroll
        for (int kc = 0; kc < 4; kc++) {
            aq[kc][0] = *(const uint32_t*)(qp +  qr      * 64 + kc*16 + qc*2);
            aq[kc][1] = *(const uint32_t*)(qp + (qr + 8) * 64 + kc*16 + qc*2);
            aq[kc][2] = *(const uint32_t*)(qp +  qr      * 64 + kc*16 + qc*2 + 8);
            aq[kc][3] = *(const uint32_t*)(qp + (qr + 8) * 64 + kc*16 + qc*2 + 8);
        }
    }

    float oacc[8][4];
#pragma unroll
    for (int nc = 0; nc < 8; nc++)
#pragma unroll
        for (int j = 0; j < 4; j++) oacc[nc][j] = 0.f;
    float rs0 = 0.f, rs1 = 0.f;

    // ---- prefetch tile 0 ----
    {
#pragma unroll
        for (int it = 0; it < 2; it++) {
            int idx = tid + it * 512;                   // 0..1023
            int key = idx >> 3, c8 = idx & 7;
            cp16(sb + KS0B + key * 144 + c8 * 16, kbh + key * 64 + c8 * 8);
            cp16(sb + VS0B + key * 144 + c8 * 16, vbh + key * 64 + c8 * 8);
        }
        CP_COMMIT();
    }

    uint32_t kq_off = (uint32_t)(lj * 144 + lt * 16);
    uint32_t vt_off = (uint32_t)(((lt & 1) * 8 + lj) * 144 + (lt >> 1) * 16);
    uint32_t pa0    = sb + PSB + (uint32_t)(kh * 128)
                    + (uint32_t)((qw * 16 + (lt & 1) * 8 + lj) * 272 + (lt >> 1) * 16);

    __half* Pb  = (__half*)(smc + PSB);
    __half* Pw0 = Pb + (qw * 16) * 136 + kh * 64;

    for (int i = 0; i < 32; i++) {
        __syncthreads();
        if (i + 1 < 32) {
            const __half* ks = kbh + (i + 1) * 128 * 64;
            const __half* vs = vbh + (i + 1) * 128 * 64;
            uint32_t ko = ((i + 1) & 1) ? KS1B : KS0B;
            uint32_t vo = ((i + 1) & 1) ? VS1B : VS0B;
#pragma unroll
            for (int it = 0; it < 2; it++) {
                int idx = tid + it * 512;
                int key = idx >> 3, c8 = idx & 7;
                cp16(sb + ko + key * 144 + c8 * 16, ks + key * 64 + c8 * 8);
                cp16(sb + vo + key * 144 + c8 * 16, vs + key * 64 + c8 * 8);
            }
            CP_COMMIT();
            CP_WAIT1();
        } else {
            CP_WAIT0();
        }
        __syncthreads();

        uint32_t Kb = sb + ((i & 1) ? KS1B : KS0B) + (uint32_t)(kh * 9216) + kq_off;
        uint32_t Vb = sb + ((i & 1) ? VS1B : VS0B) + (uint32_t)(kh * 9216) + vt_off;

        // ---- S = Q K^T ; P' = exp(S*scale)-1 -> smem ----
#pragma unroll
        for (int nc = 0; nc < 8; nc++) {
            uint32_t b0, b1, b2, b3, c0, c1, c2, c3;
            LDSM4(b0, b1, b2, b3, Kb + nc * 1152);
            LDSM4(c0, c1, c2, c3, Kb + nc * 1152 + 64);
            float s0[4] = {0.f, 0.f, 0.f, 0.f};
            mma_f16(s0, aq[0], b0, b1, s0);
            mma_f16(s0, aq[1], b2, b3, s0);
            mma_f16(s0, aq[2], c0, c1, s0);
            mma_f16(s0, aq[3], c2, c3, s0);

            float e0 = __expf(s0[0] * SCALEV) - 1.0f;
            float e1 = __expf(s0[1] * SCALEV) - 1.0f;
            float e2 = __expf(s0[2] * SCALEV) - 1.0f;
            float e3 = __expf(s0[3] * SCALEV) - 1.0f;
            rs0 += e0 + e1;
            rs1 += e2 + e3;
            *(__half2*)(Pw0 +  qr      * 136 + nc * 8 + qc * 2) = __floats2half2_rn(e0, e1);
            *(__half2*)(Pw0 + (qr + 8) * 136 + nc * 8 + qc * 2) = __floats2half2_rn(e2, e3);
        }
        __syncwarp();

        // ---- O += P' @ V ----
#pragma unroll
        for (int kc = 0; kc < 4; kc++) {
            uint32_t ap[4];
            LDSM4(ap[0], ap[1], ap[2], ap[3], pa0 + kc * 32);
            uint32_t Vk = Vb + (uint32_t)(kc * 16 * 144);
#pragma unroll
            for (int np = 0; np < 4; np++) {
                uint32_t b0, b1, b2, b3;
                LDSM4T(b0, b1, b2, b3, Vk + np * 32);
                mma_f16(oacc[np*2    ], ap, b0, b1, oacc[np*2    ]);
                mma_f16(oacc[np*2 + 1], ap, b2, b3, oacc[np*2 + 1]);
            }
        }
    }

    // ---- combine key halves (reuse K/V region as scratch) ----
    __syncthreads();
    float* scr = smf + qw * 1120;
    if (kh == 1) {
        float* s = scr + lane * 35;
#pragma unroll
        for (int nc = 0; nc < 8; nc++)
#pragma unroll
            for (int j = 0; j < 4; j++) s[nc * 4 + j] = oacc[nc][j];
        s[32] = rs0;
        s[33] = rs1;
    }
    __syncthreads();
    if (kh == 0) {
        float* s = scr + lane * 35;
#pragma unroll
        for (int nc = 0; nc < 8; nc++)
#pragma unroll
            for (int j = 0; j < 4; j++) oacc[nc][j] += s[nc * 4 + j];
        rs0 += s[32];
        rs1 += s[33];

        rs0 += __shfl_xor_sync(0xffffffffu, rs0, 1);
        rs0 += __shfl_xor_sync(0xffffffffu, rs0, 2);
        rs1 += __shfl_xor_sync(0xffffffffu, rs1, 1);
        rs1 += __shfl_xor_sync(0xffffffffu, rs1, 2);
        float inv0 = 1.0f / (4096.0f + rs0);
        float inv1 = 1.0f / (4096.0f + rs1);

        const float* vsum = g_vsum + bb * 64;
        float* ob = g_ao + bb * CHW + (m0 + qw * 16) * 64;
#pragma unroll
        for (int nc = 0; nc < 8; nc++) {
            float2 vs2 = *(const float2*)(vsum + nc * 8 + 2 * qc);
            *(float2*)(ob +  qr      * 64 + nc * 8 + 2 * qc) =
                make_float2((oacc[nc][0] + vs2.x) * inv0, (oacc[nc][1] + vs2.y) * inv0);
            *(float2*)(ob + (qr + 8) * 64 + nc * 8 + 2 * qc) =
                make_float2((oacc[nc][2] + vs2.x) * inv1, (oacc[nc][3] + vs2.y) * inv1);
        }
    }
}

// ================= launch =================
extern "C" void kernel_launch(void* const* d_in, const int* in_sizes, int n_in,
                              void* d_out, int out_size) {
    const float* prompt = (const float*)d_in[0];
    const float* kv     = (const float*)d_in[1];
    const float* wq     = (const float*)d_in[2];
    const float* bq     = (const float*)d_in[3];
    const float* wk     = (const float*)d_in[4];
    const float* bk     = (const float*)d_in[5];
    const float* wv     = (const float*)d_in[6];
    const float* bv     = (const float*)d_in[7];
    const float* wo     = (const float*)d_in[8];
    const float* bo     = (const float*)d_in[9];
    const float* dw_w   = (const float*)d_in[10];
    const float* dw_b   = (const float*)d_in[11];
    const float* ln_w   = (const float*)d_in[12];
    const float* ln_b   = (const float*)d_in[13];
    const float* off_w  = (const float*)d_in[14];
    float* out = (float*)d_out;

    cudaFuncSetAttribute(k_attn,   cudaFuncAttributeMaxDynamicSharedMemorySize, ATTN_SMEM);
    cudaFuncSetAttribute(k_kvproj, cudaFuncAttributeMaxDynamicSharedMemorySize, KVP_SMEM);

    k_convq <<<dim3(64, BB), 256>>>(prompt, wq, bq);
    k_fuse  <<<dim3(32, BB), 128>>>(kv, dw_w, dw_b, ln_w, ln_b, off_w);
    k_kvproj<<<dim3(16, BB), 256, KVP_SMEM>>>(wk, bk, wv, bv);
    k_vsum  <<<BB, 512>>>();
    k_attn  <<<dim3(32, BB), 512, ATTN_SMEM>>>();
    k_convo <<<dim3(64, BB), 256>>>(wo, bo, out);
}

// round 14
// speedup vs baseline: 1.7171x; 1.1085x over previous
#include <cuda_runtime.h>
#include <cuda_fp16.h>
#include <math.h>
#include <stdint.h>

#define BB 4
#define CC 64
#define HW 4096
#define CHW (CC*HW)
#define EPSV 1e-5f
#define OFRV 4.0f
#define SCALEV 0.125f

// -------- scratch (device globals) --------
__device__ __half g_qh[BB*CHW];   // [b][p][c]  fp16
__device__ __half g_xs[BB*CHW];   // [b][p][c]  gathered features fp16
__device__ __half g_kh[BB*CHW];   // [b][n][c]  fp16
__device__ __half g_vh[BB*CHW];   // [b][n][c]  fp16
__device__ __half g_ao[BB*CHW];   // [b][p][c]  fp16 attention out
__device__ float  g_vspart[BB*8*64];
__device__ float  g_vsum[BB*CC];  // colsum of V

// ================= helpers =================
__device__ __forceinline__ uint32_t smem_u32(const void* p){
    uint32_t a;
    asm("{ .reg .u64 t; cvta.to.shared.u64 t, %1; cvt.u32.u64 %0, t; }" : "=r"(a) : "l"(p));
    return a;
}
__device__ __forceinline__ void cp16(uint32_t dst, const void* src){
    asm volatile("cp.async.cg.shared.global [%0], [%1], 16;" :: "r"(dst), "l"(src));
}
#define CP_COMMIT() asm volatile("cp.async.commit_group;" ::: "memory")
#define CP_WAIT0()  asm volatile("cp.async.wait_group 0;" ::: "memory")
#define CP_WAIT1()  asm volatile("cp.async.wait_group 1;" ::: "memory")

#define LDSM4(R0,R1,R2,R3,ADDR) \
    asm volatile("ldmatrix.sync.aligned.m8n8.x4.shared.b16 {%0,%1,%2,%3}, [%4];" \
        : "=r"(R0),"=r"(R1),"=r"(R2),"=r"(R3) : "r"(ADDR))

#define LDSM4T(R0,R1,R2,R3,ADDR) \
    asm volatile("ldmatrix.sync.aligned.m8n8.x4.trans.shared.b16 {%0,%1,%2,%3}, [%4];" \
        : "=r"(R0),"=r"(R1),"=r"(R2),"=r"(R3) : "r"(ADDR))

__device__ __forceinline__ void mma_f16(float* d, const uint32_t* a,
                                        uint32_t b0, uint32_t b1, const float* c){
    asm volatile(
        "mma.sync.aligned.m16n8k16.row.col.f32.f16.f16.f32 "
        "{%0,%1,%2,%3}, {%4,%5,%6,%7}, {%8,%9}, {%10,%11,%12,%13};"
        : "=f"(d[0]), "=f"(d[1]), "=f"(d[2]), "=f"(d[3])
        : "r"(a[0]), "r"(a[1]), "r"(a[2]), "r"(a[3]),
          "r"(b0), "r"(b1),
          "f"(c[0]), "f"(c[1]), "f"(c[2]), "f"(c[3]));
}

// ================= conv1x1 q: prompt [c][p] -> g_qh [p][c] fp16
__global__ void k_convq(const float* __restrict__ prompt,
                        const float* __restrict__ wq,
                        const float* __restrict__ bq) {
    __shared__ float ws[4096];
    __shared__ float bs[64];
    int tid = threadIdx.x;
    for (int i = tid; i < 4096; i += 256) ws[i] = wq[i];
    if (tid < 64) bs[tid] = bq[tid];
    __syncthreads();
    int qtr = tid >> 6;
    int p   = blockIdx.x * 64 + (tid & 63);
    int bb  = blockIdx.y;
    const float* xb = prompt + bb * CHW + p;
    float xr[64];
#pragma unroll
    for (int c = 0; c < 64; c++) xr[c] = xb[c * HW];
    uint2* yb = (uint2*)(g_qh + bb * CHW + p * 64 + qtr * 16);
    const float* wbase = ws + qtr * 16 * 64;
#pragma unroll
    for (int o4 = 0; o4 < 4; o4++) {
        float a0 = bs[qtr*16 + o4*4 + 0], a1 = bs[qtr*16 + o4*4 + 1];
        float a2 = bs[qtr*16 + o4*4 + 2], a3 = bs[qtr*16 + o4*4 + 3];
#pragma unroll
        for (int c = 0; c < 64; c++) {
            float x = xr[c];
            a0 += wbase[(o4*4+0)*64 + c] * x;
            a1 += wbase[(o4*4+1)*64 + c] * x;
            a2 += wbase[(o4*4+2)*64 + c] * x;
            a3 += wbase[(o4*4+3)*64 + c] * x;
        }
        __half2 h0 = __floats2half2_rn(a0, a1);
        __half2 h1 = __floats2half2_rn(a2, a3);
        yb[o4] = make_uint2(*(uint32_t*)&h0, *(uint32_t*)&h1);
    }
}

// ================= fused: dw3x3 + LN + GELU + offset + tanh + bilinear -> xs fp16
__global__ void k_fuse(const float* __restrict__ kv,
                       const float* __restrict__ dw_w,
                       const float* __restrict__ dw_b,
                       const float* __restrict__ ln_w,
                       const float* __restrict__ ln_b,
                       const float* __restrict__ off_w) {
    __shared__ float s_dw[576], s_dwb[64], s_lnw[64], s_lnb[64];
    __shared__ float s_offw[128];

    for (int i = threadIdx.x; i < 576; i += 128) s_dw[i] = dw_w[i];
    if (threadIdx.x < 64) {
        s_dwb[threadIdx.x] = dw_b[threadIdx.x];
        s_lnw[threadIdx.x] = ln_w[threadIdx.x];
        s_lnb[threadIdx.x] = ln_b[threadIdx.x];
    }
    if (threadIdx.x < 128) s_offw[threadIdx.x] = off_w[threadIdx.x];
    __syncthreads();

    int p  = blockIdx.x * 128 + threadIdx.x;
    int bb = blockIdx.y;
    int py = p >> 6;
    int px = p & 63;

    const __half* qb = g_qh + bb * CHW;   // [p][c]

    float t[64];
#pragma unroll
    for (int c = 0; c < 64; c++) t[c] = s_dwb[c];

    for (int k9 = 0; k9 < 9; k9++) {
        int dy = k9 / 3 - 1, dx = k9 % 3 - 1;
        int yy = py + dy, xx = px + dx;
        if (yy < 0 || yy > 63 || xx < 0 || xx > 63) continue;
        const uint4* qp = (const uint4*)(qb + (yy * 64 + xx) * 64);
#pragma unroll
        for (int c8 = 0; c8 < 8; c8++) {
            uint4 u = qp[c8];
            uint32_t uu[4] = {u.x, u.y, u.z, u.w};
#pragma unroll
            for (int j = 0; j < 4; j++) {
                float2 f = __half22float2(*(__half2*)&uu[j]);
                t[c8*8 + j*2    ] += f.x * s_dw[(c8*8 + j*2    )*9 + k9];
                t[c8*8 + j*2 + 1] += f.y * s_dw[(c8*8 + j*2 + 1)*9 + k9];
            }
        }
    }

    float mu = 0.f;
#pragma unroll
    for (int c = 0; c < 64; c++) mu += t[c];
    mu *= (1.0f / 64.0f);
    float var = 0.f;
#pragma unroll
    for (int c = 0; c < 64; c++) { float d = t[c] - mu; var += d * d; }
    var *= (1.0f / 64.0f);
    float rstd = rsqrtf(var + EPSV);
#pragma unroll
    for (int c = 0; c < 64; c++) {
        float z = (t[c] - mu) * rstd * s_lnw[c] + s_lnb[c];
        t[c] = 0.5f * z * (1.0f + erff(z * 0.70710678118654752f));
    }

    float o0 = 0.f, o1 = 0.f;
#pragma unroll
    for (int c = 0; c < 64; c++) { o0 += s_offw[c] * t[c]; o1 += s_offw[64 + c] * t[c]; }
    float off0 = tanhf(o0) * (1.0f / 63.0f) * OFRV;
    float off1 = tanhf(o1) * (1.0f / 63.0f) * OFRV;

    float refy = (0.5f + (float)py) * (2.0f / 63.0f) - 1.0f;
    float refx = (0.5f + (float)px) * (2.0f / 63.0f) - 1.0f;
    float gx = (off1 + refx + 1.0f) * 0.5f * 63.0f;
    float gy = (off0 + refy + 1.0f) * 0.5f * 63.0f;

    float x0f = floorf(gx), y0f = floorf(gy);
    float wx = gx - x0f, wy = gy - y0f;
    int x0 = (int)x0f, y0 = (int)y0f;
    int x1 = x0 + 1,   y1 = y0 + 1;

    float m00 = (x0 >= 0 && x0 <= 63 && y0 >= 0 && y0 <= 63) ? 1.f : 0.f;
    float m01 = (x1 >= 0 && x1 <= 63 && y0 >= 0 && y0 <= 63) ? 1.f : 0.f;
    float m10 = (x0 >= 0 && x0 <= 63 && y1 >= 0 && y1 <= 63) ? 1.f : 0.f;
    float m11 = (x1 >= 0 && x1 <= 63 && y1 >= 0 && y1 <= 63) ? 1.f : 0.f;

    int xc0 = min(max(x0, 0), 63), xc1 = min(max(x1, 0), 63);
    int yc0 = min(max(y0, 0), 63), yc1 = min(max(y1, 0), 63);

    float w00 = m00 * (1.0f - wx) * (1.0f - wy);
    float w01 = m01 * wx * (1.0f - wy);
    float w10 = m10 * (1.0f - wx) * wy;
    float w11 = m11 * wx * wy;

    int i00 = yc0 * 64 + xc0, i01 = yc0 * 64 + xc1;
    int i10 = yc1 * 64 + xc0, i11 = yc1 * 64 + xc1;

    const float* kvb = kv + bb * CHW;
    uint2* xout = (uint2*)(g_xs + bb * CHW + p * 64);
#pragma unroll
    for (int c4 = 0; c4 < 16; c4++) {
        float v[4];
#pragma unroll
        for (int j = 0; j < 4; j++) {
            const float* kc = kvb + (c4*4 + j) * HW;
            v[j] = w00 * kc[i00] + w01 * kc[i01] + w10 * kc[i10] + w11 * kc[i11];
        }
        __half2 h0 = __floats2half2_rn(v[0], v[1]);
        __half2 h1 = __floats2half2_rn(v[2], v[3]);
        xout[c4] = make_uint2(*(uint32_t*)&h0, *(uint32_t*)&h1);
    }
}

// ================= K/V projection GEMM (fp16 mma)
#define KVP_XS 0
#define KVP_WK 36864
#define KVP_WV 46080
#define KVP_SMEM 55296

__global__ void __launch_bounds__(256) k_kvproj(const float* __restrict__ wk,
                                                const float* __restrict__ bk,
                                                const float* __restrict__ wv,
                                                const float* __restrict__ bv) {
    extern __shared__ char smc[];
    uint32_t sb = smem_u32(smc);
    int tid = threadIdx.x, wid = tid >> 5, lane = tid & 31;
    int lj = lane & 7, lt = lane >> 3;
    int qr = lane >> 2, qc = lane & 3;
    int bb = blockIdx.y;
    int p0 = blockIdx.x * 256;

    const __half* xsb = g_xs + bb * CHW + p0 * 64;
#pragma unroll
    for (int it = 0; it < 8; it++) {
        int idx = tid + it * 256;
        int row = idx >> 3, c8 = idx & 7;
        cp16(sb + KVP_XS + row * 144 + c8 * 16, xsb + row * 64 + c8 * 8);
    }
    CP_COMMIT();

    __half* swk = (__half*)(smc + KVP_WK);
    __half* swv = (__half*)(smc + KVP_WV);
    for (int i = tid; i < 4096; i += 256) {
        int o = i >> 6, c = i & 63;
        swk[o * 72 + c] = __float2half_rn(wk[i]);
        swv[o * 72 + c] = __float2half_rn(wv[i]);
    }
    CP_WAIT0();
    __syncthreads();

    uint32_t xa = sb + KVP_XS + (uint32_t)((wid * 32 + (lt & 1) * 8 + lj) * 144 + (lt >> 1) * 16);
    uint32_t ap[2][4][4];
#pragma unroll
    for (int blk = 0; blk < 2; blk++)
#pragma unroll
        for (int kc = 0; kc < 4; kc++)
            LDSM4(ap[blk][kc][0], ap[blk][kc][1], ap[blk][kc][2], ap[blk][kc][3],
                  xa + blk * 16 * 144 + kc * 32);

    uint32_t wfrag = (uint32_t)(lj * 144 + lt * 16);

#pragma unroll
    for (int mat = 0; mat < 2; mat++) {
        uint32_t wb = sb + (mat ? KVP_WV : KVP_WK) + wfrag;
        const float* bias = mat ? bv : bk;
        __half* gout = (mat ? g_vh : g_kh) + bb * CHW;

        float oa[2][8][4];
#pragma unroll
        for (int blk = 0; blk < 2; blk++)
#pragma unroll
            for (int nc = 0; nc < 8; nc++)
#pragma unroll
                for (int j = 0; j < 4; j++) oa[blk][nc][j] = 0.f;

#pragma unroll
        for (int nc = 0; nc < 8; nc++) {
            uint32_t b0, b1, b2, b3, c0, c1, c2, c3;
            LDSM4(b0, b1, b2, b3, wb + nc * 1152);
            LDSM4(c0, c1, c2, c3, wb + nc * 1152 + 64);
#pragma unroll
            for (int blk = 0; blk < 2; blk++) {
                mma_f16(oa[blk][nc], ap[blk][0], b0, b1, oa[blk][nc]);
                mma_f16(oa[blk][nc], ap[blk][1], b2, b3, oa[blk][nc]);
                mma_f16(oa[blk][nc], ap[blk][2], c0, c1, oa[blk][nc]);
                mma_f16(oa[blk][nc], ap[blk][3], c2, c3, oa[blk][nc]);
            }
        }

#pragma unroll
        for (int blk = 0; blk < 2; blk++) {
            int row0 = p0 + wid * 32 + blk * 16 + qr;
#pragma unroll
            for (int nc = 0; nc < 8; nc++) {
                float2 bv2 = *(const float2*)(bias + nc * 8 + qc * 2);
                __half2 h0 = __floats2half2_rn(oa[blk][nc][0] + bv2.x, oa[blk][nc][1] + bv2.y);
                __half2 h1 = __floats2half2_rn(oa[blk][nc][2] + bv2.x, oa[blk][nc][3] + bv2.y);
                *(__half2*)(gout +  row0      * 64 + nc * 8 + qc * 2) = h0;
                *(__half2*)(gout + (row0 + 8) * 64 + nc * 8 + qc * 2) = h1;
            }
        }
    }
}

// ================= V column sums: stage 1 (32 blocks) + stage 2 =============
__global__ void k_vsum1() {
    __shared__ float red[512];
    int tid = threadIdx.x;
    int bb  = blockIdx.y;
    int part = tid >> 6;               // 0..7
    int c    = tid & 63;
    int n0   = blockIdx.x * 512 + part * 64;
    const __half* vb = g_vh + bb * CHW + c;
    float acc = 0.f;
#pragma unroll 8
    for (int i = 0; i < 64; i++) acc += __half2float(vb[(n0 + i) * 64]);
    red[part * 64 + c] = acc;
    __syncthreads();
    if (tid < 64) {
        float s = 0.f;
#pragma unroll
        for (int g = 0; g < 8; g++) s += red[g * 64 + tid];
        g_vspart[bb * 512 + blockIdx.x * 64 + tid] = s;
    }
}
__global__ void k_vsum2() {
    int bb = blockIdx.x, c = threadIdx.x;
    float s = 0.f;
#pragma unroll
    for (int g = 0; g < 8; g++) s += g_vspart[bb * 512 + g * 64 + c];
    g_vsum[bb * 64 + c] = s;
}

// ================= fp16 mma flash attention, 512 thr / 16 warps =============
#define KS0B 0
#define KS1B 18432
#define VS0B 36864
#define VS1B 55296
#define PSB  73728
#define ATTN_SMEM (PSB + 128*272)   // 108544 B

__global__ void __launch_bounds__(512) k_attn() {
    extern __shared__ char smc[];
    float* smf = (float*)smc;
    uint32_t sb = smem_u32(smc);
    int tid  = threadIdx.x;
    int wid  = tid >> 5;
    int lane = tid & 31;
    int qw   = wid & 7;
    int kh   = wid >> 3;
    int qr   = lane >> 2;
    int qc   = lane & 3;
    int lj   = lane & 7;
    int lt   = lane >> 3;
    int bb = blockIdx.y;
    int m0 = blockIdx.x * 128;

    const __half* qbh = g_qh + bb * CHW;
    const __half* kbh = g_kh + bb * CHW;
    const __half* vbh = g_vh + bb * CHW;

    uint32_t aq[4][4];
    {
        const __half* qp = qbh + (m0 + qw * 16) * 64;
#pragma unroll
        for (int kc = 0; kc < 4; kc++) {
            aq[kc][0] = *(const uint32_t*)(qp +  qr      * 64 + kc*16 + qc*2);
            aq[kc][1] = *(const uint32_t*)(qp + (qr + 8) * 64 + kc*16 + qc*2);
            aq[kc][2] = *(const uint32_t*)(qp +  qr      * 64 + kc*16 + qc*2 + 8);
            aq[kc][3] = *(const uint32_t*)(qp + (qr + 8) * 64 + kc*16 + qc*2 + 8);
        }
    }

    float oacc[8][4];
#pragma unroll
    for (int nc = 0; nc < 8; nc++)
#pragma unroll
        for (int j = 0; j < 4; j++) oacc[nc][j] = 0.f;
    float rs0 = 0.f, rs1 = 0.f;

    {
#pragma unroll
        for (int it = 0; it < 2; it++) {
            int idx = tid + it * 512;
            int key = idx >> 3, c8 = idx & 7;
            cp16(sb + KS0B + key * 144 + c8 * 16, kbh + key * 64 + c8 * 8);
            cp16(sb + VS0B + key * 144 + c8 * 16, vbh + key * 64 + c8 * 8);
        }
        CP_COMMIT();
    }

    uint32_t kq_off = (uint32_t)(lj * 144 + lt * 16);
    uint32_t vt_off = (uint32_t)(((lt & 1) * 8 + lj) * 144 + (lt >> 1) * 16);
    uint32_t pa0    = sb + PSB + (uint32_t)(kh * 128)
                    + (uint32_t)((qw * 16 + (lt & 1) * 8 + lj) * 272 + (lt >> 1) * 16);

    __half* Pb  = (__half*)(smc + PSB);
    __half* Pw0 = Pb + (qw * 16) * 136 + kh * 64;

    for (int i = 0; i < 32; i++) {
        __syncthreads();
        if (i + 1 < 32) {
            const __half* ks = kbh + (i + 1) * 128 * 64;
            const __half* vs = vbh + (i + 1) * 128 * 64;
            uint32_t ko = ((i + 1) & 1) ? KS1B : KS0B;
            uint32_t vo = ((i + 1) & 1) ? VS1B : VS0B;
#pragma unroll
            for (int it = 0; it < 2; it++) {
                int idx = tid + it * 512;
                int key = idx >> 3, c8 = idx & 7;
                cp16(sb + ko + key * 144 + c8 * 16, ks + key * 64 + c8 * 8);
                cp16(sb + vo + key * 144 + c8 * 16, vs + key * 64 + c8 * 8);
            }
            CP_COMMIT();
            CP_WAIT1();
        } else {
            CP_WAIT0();
        }
        __syncthreads();

        uint32_t Kb = sb + ((i & 1) ? KS1B : KS0B) + (uint32_t)(kh * 9216) + kq_off;
        uint32_t Vb = sb + ((i & 1) ? VS1B : VS0B) + (uint32_t)(kh * 9216) + vt_off;

#pragma unroll
        for (int nc = 0; nc < 8; nc++) {
            uint32_t b0, b1, b2, b3, c0, c1, c2, c3;
            LDSM4(b0, b1, b2, b3, Kb + nc * 1152);
            LDSM4(c0, c1, c2, c3, Kb + nc * 1152 + 64);
            float s0[4] = {0.f, 0.f, 0.f, 0.f};
            mma_f16(s0, aq[0], b0, b1, s0);
            mma_f16(s0, aq[1], b2, b3, s0);
            mma_f16(s0, aq[2], c0, c1, s0);
            mma_f16(s0, aq[3], c2, c3, s0);

            float e0 = __expf(s0[0] * SCALEV) - 1.0f;
            float e1 = __expf(s0[1] * SCALEV) - 1.0f;
            float e2 = __expf(s0[2] * SCALEV) - 1.0f;
            float e3 = __expf(s0[3] * SCALEV) - 1.0f;
            rs0 += e0 + e1;
            rs1 += e2 + e3;
            *(__half2*)(Pw0 +  qr      * 136 + nc * 8 + qc * 2) = __floats2half2_rn(e0, e1);
            *(__half2*)(Pw0 + (qr + 8) * 136 + nc * 8 + qc * 2) = __floats2half2_rn(e2, e3);
        }
        __syncwarp();

#pragma unroll
        for (int kc = 0; kc < 4; kc++) {
            uint32_t ap[4];
            LDSM4(ap[0], ap[1], ap[2], ap[3], pa0 + kc * 32);
            uint32_t Vk = Vb + (uint32_t)(kc * 16 * 144);
#pragma unroll
            for (int np = 0; np < 4; np++) {
                uint32_t b0, b1, b2, b3;
                LDSM4T(b0, b1, b2, b3, Vk + np * 32);
                mma_f16(oacc[np*2    ], ap, b0, b1, oacc[np*2    ]);
                mma_f16(oacc[np*2 + 1], ap, b2, b3, oacc[np*2 + 1]);
            }
        }
    }

    __syncthreads();
    float* scr = smf + qw * 1120;
    if (kh == 1) {
        float* s = scr + lane * 35;
#pragma unroll
        for (int nc = 0; nc < 8; nc++)
#pragma unroll
            for (int j = 0; j < 4; j++) s[nc * 4 + j] = oacc[nc][j];
        s[32] = rs0;
        s[33] = rs1;
    }
    __syncthreads();
    if (kh == 0) {
        float* s = scr + lane * 35;
#pragma unroll
        for (int nc = 0; nc < 8; nc++)
#pragma unroll
            for (int j = 0; j < 4; j++) oacc[nc][j] += s[nc * 4 + j];
        rs0 += s[32];
        rs1 += s[33];

        rs0 += __shfl_xor_sync(0xffffffffu, rs0, 1);
        rs0 += __shfl_xor_sync(0xffffffffu, rs0, 2);
        rs1 += __shfl_xor_sync(0xffffffffu, rs1, 1);
        rs1 += __shfl_xor_sync(0xffffffffu, rs1, 2);
        float inv0 = 1.0f / (4096.0f + rs0);
        float inv1 = 1.0f / (4096.0f + rs1);

        const float* vsum = g_vsum + bb * 64;
        __half* ob = g_ao + bb * CHW + (m0 + qw * 16) * 64;
#pragma unroll
        for (int nc = 0; nc < 8; nc++) {
            float2 vs2 = *(const float2*)(vsum + nc * 8 + 2 * qc);
            *(__half2*)(ob +  qr      * 64 + nc * 8 + 2 * qc) =
                __floats2half2_rn((oacc[nc][0] + vs2.x) * inv0, (oacc[nc][1] + vs2.y) * inv0);
            *(__half2*)(ob + (qr + 8) * 64 + nc * 8 + 2 * qc) =
                __floats2half2_rn((oacc[nc][2] + vs2.x) * inv1, (oacc[nc][3] + vs2.y) * inv1);
        }
    }
}

// ================= output projection GEMM: out[c][p] = ao[p][c]*wo^T + bo =====
#define OP_AO 0
#define OP_WO 36864
#define OP_SMEM 46080

__global__ void __launch_bounds__(256) k_oproj(const float* __restrict__ wo,
                                               const float* __restrict__ bo,
                                               float* __restrict__ out) {
    extern __shared__ char smc[];
    uint32_t sb = smem_u32(smc);
    int tid = threadIdx.x, wid = tid >> 5, lane = tid & 31;
    int lj = lane & 7, lt = lane >> 3;
    int qr = lane >> 2, qc = lane & 3;
    int bb = blockIdx.y;
    int p0 = blockIdx.x * 256;

    const __half* aob = g_ao + bb * CHW + p0 * 64;
#pragma unroll
    for (int it = 0; it < 8; it++) {
        int idx = tid + it * 256;
        int row = idx >> 3, c8 = idx & 7;
        cp16(sb + OP_AO + row * 144 + c8 * 16, aob + row * 64 + c8 * 8);
    }
    CP_COMMIT();

    __half* swo = (__half*)(smc + OP_WO);
    for (int i = tid; i < 4096; i += 256) {
        int o = i >> 6, c = i & 63;
        swo[o * 72 + c] = __float2half_rn(wo[i]);
    }
    CP_WAIT0();
    __syncthreads();

    uint32_t xa = sb + OP_AO + (uint32_t)((wid * 32 + (lt & 1) * 8 + lj) * 144 + (lt >> 1) * 16);
    uint32_t ap[2][4][4];
#pragma unroll
    for (int blk = 0; blk < 2; blk++)
#pragma unroll
        for (int kc = 0; kc < 4; kc++)
            LDSM4(ap[blk][kc][0], ap[blk][kc][1], ap[blk][kc][2], ap[blk][kc][3],
                  xa + blk * 16 * 144 + kc * 32);

    uint32_t wb = sb + OP_WO + (uint32_t)(lj * 144 + lt * 16);

    float oa[2][8][4];
#pragma unroll
    for (int blk = 0; blk < 2; blk++)
#pragma unroll
        for (int nc = 0; nc < 8; nc++)
#pragma unroll
            for (int j = 0; j < 4; j++) oa[blk][nc][j] = 0.f;

#pragma unroll
    for (int nc = 0; nc < 8; nc++) {
        uint32_t b0, b1, b2, b3, c0, c1, c2, c3;
        LDSM4(b0, b1, b2, b3, wb + nc * 1152);
        LDSM4(c0, c1, c2, c3, wb + nc * 1152 + 64);
#pragma unroll
        for (int blk = 0; blk < 2; blk++) {
            mma_f16(oa[blk][nc], ap[blk][0], b0, b1, oa[blk][nc]);
            mma_f16(oa[blk][nc], ap[blk][1], b2, b3, oa[blk][nc]);
            mma_f16(oa[blk][nc], ap[blk][2], c0, c1, oa[blk][nc]);
            mma_f16(oa[blk][nc], ap[blk][3], c2, c3, oa[blk][nc]);
        }
    }

    float* outb = out + bb * CHW;
#pragma unroll
    for (int blk = 0; blk < 2; blk++) {
        int prow = p0 + wid * 32 + blk * 16 + qr;
#pragma unroll
        for (int nc = 0; nc < 8; nc++) {
            int ch = nc * 8 + qc * 2;
            float2 bo2 = *(const float2*)(bo + ch);
            outb[ ch      * HW + prow    ] = oa[blk][nc][0] + bo2.x;
            outb[(ch + 1) * HW + prow    ] = oa[blk][nc][1] + bo2.y;
            outb[ ch      * HW + prow + 8] = oa[blk][nc][2] + bo2.x;
            outb[(ch + 1) * HW + prow + 8] = oa[blk][nc][3] + bo2.y;
        }
    }
}

// ================= launch =================
extern "C" void kernel_launch(void* const* d_in, const int* in_sizes, int n_in,
                              void* d_out, int out_size) {
    const float* prompt = (const float*)d_in[0];
    const float* kv     = (const float*)d_in[1];
    const float* wq     = (const float*)d_in[2];
    const float* bq     = (const float*)d_in[3];
    const float* wk     = (const float*)d_in[4];
    const float* bk     = (const float*)d_in[5];
    const float* wv     = (const float*)d_in[6];
    const float* bv     = (const float*)d_in[7];
    const float* wo     = (const float*)d_in[8];
    const float* bo     = (const float*)d_in[9];
    const float* dw_w   = (const float*)d_in[10];
    const float* dw_b   = (const float*)d_in[11];
    const float* ln_w   = (const float*)d_in[12];
    const float* ln_b   = (const float*)d_in[13];
    const float* off_w  = (const float*)d_in[14];
    float* out = (float*)d_out;

    cudaFuncSetAttribute(k_attn,   cudaFuncAttributeMaxDynamicSharedMemorySize, ATTN_SMEM);
    cudaFuncSetAttribute(k_kvproj, cudaFuncAttributeMaxDynamicSharedMemorySize, KVP_SMEM);
    cudaFuncSetAttribute(k_oproj,  cudaFuncAttributeMaxDynamicSharedMemorySize, OP_SMEM);

    k_convq <<<dim3(64, BB), 256>>>(prompt, wq, bq);
    k_fuse  <<<dim3(32, BB), 128>>>(kv, dw_w, dw_b, ln_w, ln_b, off_w);
    k_kvproj<<<dim3(16, BB), 256, KVP_SMEM>>>(wk, bk, wv, bv);
    k_vsum1 <<<dim3(8, BB), 512>>>();
    k_vsum2 <<<BB, 64>>>();
    k_attn  <<<dim3(32, BB), 512, ATTN_SMEM>>>();
    k_oproj <<<dim3(16, BB), 256, OP_SMEM>>>(wo, bo, out);
}

// round 15
// speedup vs baseline: 1.7749x; 1.0337x over previous
#include <cuda_runtime.h>
#include <cuda_fp16.h>
#include <math.h>
#include <stdint.h>

#define BB 4
#define CC 64
#define HW 4096
#define CHW (CC*HW)
#define EPSV 1e-5f
#define OFRV 4.0f
#define SCALEV 0.125f

// -------- scratch (device globals) --------
__device__ __half g_qh[BB*CHW];   // [b][p][c]  fp16
__device__ __half g_xs[BB*CHW];   // [b][p][c]  gathered features fp16
__device__ __half g_kh[BB*CHW];   // [b][n][c]  fp16
__device__ __half g_vh[BB*CHW];   // [b][n][c]  fp16
__device__ __half g_ao[BB*CHW];   // [b][p][c]  fp16 attention out
__device__ float  g_vspart[BB*16*64];
__device__ float  g_vsum[BB*CC];  // colsum of V

// ================= helpers =================
__device__ __forceinline__ uint32_t smem_u32(const void* p){
    uint32_t a;
    asm("{ .reg .u64 t; cvta.to.shared.u64 t, %1; cvt.u32.u64 %0, t; }" : "=r"(a) : "l"(p));
    return a;
}
__device__ __forceinline__ void cp16(uint32_t dst, const void* src){
    asm volatile("cp.async.cg.shared.global [%0], [%1], 16;" :: "r"(dst), "l"(src));
}
#define CP_COMMIT() asm volatile("cp.async.commit_group;" ::: "memory")
#define CP_WAIT0()  asm volatile("cp.async.wait_group 0;" ::: "memory")
#define CP_WAIT1()  asm volatile("cp.async.wait_group 1;" ::: "memory")

#define LDSM4(R0,R1,R2,R3,ADDR) \
    asm volatile("ldmatrix.sync.aligned.m8n8.x4.shared.b16 {%0,%1,%2,%3}, [%4];" \
        : "=r"(R0),"=r"(R1),"=r"(R2),"=r"(R3) : "r"(ADDR))

#define LDSM4T(R0,R1,R2,R3,ADDR) \
    asm volatile("ldmatrix.sync.aligned.m8n8.x4.trans.shared.b16 {%0,%1,%2,%3}, [%4];" \
        : "=r"(R0),"=r"(R1),"=r"(R2),"=r"(R3) : "r"(ADDR))

__device__ __forceinline__ void mma_f16(float* d, const uint32_t* a,
                                        uint32_t b0, uint32_t b1, const float* c){
    asm volatile(
        "mma.sync.aligned.m16n8k16.row.col.f32.f16.f16.f32 "
        "{%0,%1,%2,%3}, {%4,%5,%6,%7}, {%8,%9}, {%10,%11,%12,%13};"
        : "=f"(d[0]), "=f"(d[1]), "=f"(d[2]), "=f"(d[3])
        : "r"(a[0]), "r"(a[1]), "r"(a[2]), "r"(a[3]),
          "r"(b0), "r"(b1),
          "f"(c[0]), "f"(c[1]), "f"(c[2]), "f"(c[3]));
}

// ================= q projection GEMM: q[p][c] = prompt^T[p][c'] * wq^T + bq
// prompt is [c'][p] fp32; transpose-convert into smem [c'][p] fp16 rows, A via ldmatrix.trans
#define QP_PX 0
#define QP_W  33792              // 64 rows * 528 B
#define QP_SMEM (33792 + 9216)   // + wq fp16 72-stride

__global__ void __launch_bounds__(256) k_qproj(const float* __restrict__ prompt,
                                               const float* __restrict__ wq,
                                               const float* __restrict__ bq) {
    extern __shared__ char smc[];
    uint32_t sb = smem_u32(smc);
    int tid = threadIdx.x, wid = tid >> 5, lane = tid & 31;
    int lj = lane & 7, lt = lane >> 3;
    int qr = lane >> 2, qc = lane & 3;
    int bb = blockIdx.y;
    int p0 = blockIdx.x * 256;

    // transpose-convert prompt[c'][p0..p0+255] -> smem fp16 rows (528 B stride)
    {
        int c   = tid >> 2;        // 0..63
        int seg = tid & 3;         // 64 pixels each
        const float4* pr = (const float4*)(prompt + bb * CHW + c * HW + p0 + seg * 64);
        __half* dst = (__half*)(smc + QP_PX + c * 528) + seg * 64;
#pragma unroll
        for (int i = 0; i < 16; i++) {
            float4 v = pr[i];
            __half2 h0 = __floats2half2_rn(v.x, v.y);
            __half2 h1 = __floats2half2_rn(v.z, v.w);
            ((uint2*)dst)[i] = make_uint2(*(uint32_t*)&h0, *(uint32_t*)&h1);
        }
    }
    __half* sw = (__half*)(smc + QP_W);
    for (int i = tid; i < 4096; i += 256) {
        int o = i >> 6, c = i & 63;
        sw[o * 72 + c] = __float2half_rn(wq[i]);
    }
    __syncthreads();

    // A fragments via ldmatrix.trans: rows = channel (k), cols = pixel (m)
    uint32_t xa = sb + QP_PX + (uint32_t)(((lt >> 1) * 8 + lj) * 528
                + (wid * 32 + (lt & 1) * 8) * 2);
    uint32_t ap[2][4][4];
#pragma unroll
    for (int blk = 0; blk < 2; blk++)
#pragma unroll
        for (int kc = 0; kc < 4; kc++)
            LDSM4T(ap[blk][kc][0], ap[blk][kc][1], ap[blk][kc][2], ap[blk][kc][3],
                   xa + (uint32_t)(kc * 16 * 528 + blk * 32));

    uint32_t wb = sb + QP_W + (uint32_t)(lj * 144 + lt * 16);

    float oa[2][8][4];
#pragma unroll
    for (int blk = 0; blk < 2; blk++)
#pragma unroll
        for (int nc = 0; nc < 8; nc++)
#pragma unroll
            for (int j = 0; j < 4; j++) oa[blk][nc][j] = 0.f;

#pragma unroll
    for (int nc = 0; nc < 8; nc++) {
        uint32_t b0, b1, b2, b3, c0, c1, c2, c3;
        LDSM4(b0, b1, b2, b3, wb + nc * 1152);
        LDSM4(c0, c1, c2, c3, wb + nc * 1152 + 64);
#pragma unroll
        for (int blk = 0; blk < 2; blk++) {
            mma_f16(oa[blk][nc], ap[blk][0], b0, b1, oa[blk][nc]);
            mma_f16(oa[blk][nc], ap[blk][1], b2, b3, oa[blk][nc]);
            mma_f16(oa[blk][nc], ap[blk][2], c0, c1, oa[blk][nc]);
            mma_f16(oa[blk][nc], ap[blk][3], c2, c3, oa[blk][nc]);
        }
    }

    __half* gout = g_qh + bb * CHW;
#pragma unroll
    for (int blk = 0; blk < 2; blk++) {
        int row0 = p0 + wid * 32 + blk * 16 + qr;
#pragma unroll
        for (int nc = 0; nc < 8; nc++) {
            float2 b2v = *(const float2*)(bq + nc * 8 + qc * 2);
            *(__half2*)(gout +  row0      * 64 + nc * 8 + qc * 2) =
                __floats2half2_rn(oa[blk][nc][0] + b2v.x, oa[blk][nc][1] + b2v.y);
            *(__half2*)(gout + (row0 + 8) * 64 + nc * 8 + qc * 2) =
                __floats2half2_rn(oa[blk][nc][2] + b2v.x, oa[blk][nc][3] + b2v.y);
        }
    }
}

// ================= fused: dw3x3 + LN + GELU + offset + tanh + bilinear -> xs fp16
__global__ void k_fuse(const float* __restrict__ kv,
                       const float* __restrict__ dw_w,
                       const float* __restrict__ dw_b,
                       const float* __restrict__ ln_w,
                       const float* __restrict__ ln_b,
                       const float* __restrict__ off_w) {
    __shared__ float s_dw[576], s_dwb[64], s_lnw[64], s_lnb[64];
    __shared__ float s_offw[128];

    for (int i = threadIdx.x; i < 576; i += 128) s_dw[i] = dw_w[i];
    if (threadIdx.x < 64) {
        s_dwb[threadIdx.x] = dw_b[threadIdx.x];
        s_lnw[threadIdx.x] = ln_w[threadIdx.x];
        s_lnb[threadIdx.x] = ln_b[threadIdx.x];
    }
    if (threadIdx.x < 128) s_offw[threadIdx.x] = off_w[threadIdx.x];
    __syncthreads();

    int p  = blockIdx.x * 128 + threadIdx.x;
    int bb = blockIdx.y;
    int py = p >> 6;
    int px = p & 63;

    const __half* qb = g_qh + bb * CHW;

    float t[64];
#pragma unroll
    for (int c = 0; c < 64; c++) t[c] = s_dwb[c];

    for (int k9 = 0; k9 < 9; k9++) {
        int dy = k9 / 3 - 1, dx = k9 % 3 - 1;
        int yy = py + dy, xx = px + dx;
        if (yy < 0 || yy > 63 || xx < 0 || xx > 63) continue;
        const uint4* qp = (const uint4*)(qb + (yy * 64 + xx) * 64);
#pragma unroll
        for (int c8 = 0; c8 < 8; c8++) {
            uint4 u = qp[c8];
            uint32_t uu[4] = {u.x, u.y, u.z, u.w};
#pragma unroll
            for (int j = 0; j < 4; j++) {
                float2 f = __half22float2(*(__half2*)&uu[j]);
                t[c8*8 + j*2    ] += f.x * s_dw[(c8*8 + j*2    )*9 + k9];
                t[c8*8 + j*2 + 1] += f.y * s_dw[(c8*8 + j*2 + 1)*9 + k9];
            }
        }
    }

    float mu = 0.f;
#pragma unroll
    for (int c = 0; c < 64; c++) mu += t[c];
    mu *= (1.0f / 64.0f);
    float var = 0.f;
#pragma unroll
    for (int c = 0; c < 64; c++) { float d = t[c] - mu; var += d * d; }
    var *= (1.0f / 64.0f);
    float rstd = rsqrtf(var + EPSV);
#pragma unroll
    for (int c = 0; c < 64; c++) {
        float z = (t[c] - mu) * rstd * s_lnw[c] + s_lnb[c];
        t[c] = 0.5f * z * (1.0f + erff(z * 0.70710678118654752f));
    }

    float o0 = 0.f, o1 = 0.f;
#pragma unroll
    for (int c = 0; c < 64; c++) { o0 += s_offw[c] * t[c]; o1 += s_offw[64 + c] * t[c]; }
    float off0 = tanhf(o0) * (1.0f / 63.0f) * OFRV;
    float off1 = tanhf(o1) * (1.0f / 63.0f) * OFRV;

    float refy = (0.5f + (float)py) * (2.0f / 63.0f) - 1.0f;
    float refx = (0.5f + (float)px) * (2.0f / 63.0f) - 1.0f;
    float gx = (off1 + refx + 1.0f) * 0.5f * 63.0f;
    float gy = (off0 + refy + 1.0f) * 0.5f * 63.0f;

    float x0f = floorf(gx), y0f = floorf(gy);
    float wx = gx - x0f, wy = gy - y0f;
    int x0 = (int)x0f, y0 = (int)y0f;
    int x1 = x0 + 1,   y1 = y0 + 1;

    float m00 = (x0 >= 0 && x0 <= 63 && y0 >= 0 && y0 <= 63) ? 1.f : 0.f;
    float m01 = (x1 >= 0 && x1 <= 63 && y0 >= 0 && y0 <= 63) ? 1.f : 0.f;
    float m10 = (x0 >= 0 && x0 <= 63 && y1 >= 0 && y1 <= 63) ? 1.f : 0.f;
    float m11 = (x1 >= 0 && x1 <= 63 && y1 >= 0 && y1 <= 63) ? 1.f : 0.f;

    int xc0 = min(max(x0, 0), 63), xc1 = min(max(x1, 0), 63);
    int yc0 = min(max(y0, 0), 63), yc1 = min(max(y1, 0), 63);

    float w00 = m00 * (1.0f - wx) * (1.0f - wy);
    float w01 = m01 * wx * (1.0f - wy);
    float w10 = m10 * (1.0f - wx) * wy;
    float w11 = m11 * wx * wy;

    int i00 = yc0 * 64 + xc0, i01 = yc0 * 64 + xc1;
    int i10 = yc1 * 64 + xc0, i11 = yc1 * 64 + xc1;

    const float* kvb = kv + bb * CHW;
    uint2* xout = (uint2*)(g_xs + bb * CHW + p * 64);
#pragma unroll
    for (int c4 = 0; c4 < 16; c4++) {
        float v[4];
#pragma unroll
        for (int j = 0; j < 4; j++) {
            const float* kc = kvb + (c4*4 + j) * HW;
            v[j] = w00 * kc[i00] + w01 * kc[i01] + w10 * kc[i10] + w11 * kc[i11];
        }
        __half2 h0 = __floats2half2_rn(v[0], v[1]);
        __half2 h1 = __floats2half2_rn(v[2], v[3]);
        xout[c4] = make_uint2(*(uint32_t*)&h0, *(uint32_t*)&h1);
    }
}

// ================= K/V projection GEMM (fp16 mma) + V column partial sums
#define KVP_XS 0
#define KVP_WK 36864
#define KVP_WV 46080
#define KVP_SMEM 55296

__global__ void __launch_bounds__(256) k_kvproj(const float* __restrict__ wk,
                                                const float* __restrict__ bk,
                                                const float* __restrict__ wv,
                                                const float* __restrict__ bv) {
    extern __shared__ char smc[];
    __shared__ float s_sums[8][64];
    uint32_t sb = smem_u32(smc);
    int tid = threadIdx.x, wid = tid >> 5, lane = tid & 31;
    int lj = lane & 7, lt = lane >> 3;
    int qr = lane >> 2, qc = lane & 3;
    int bb = blockIdx.y;
    int p0 = blockIdx.x * 256;

    const __half* xsb = g_xs + bb * CHW + p0 * 64;
#pragma unroll
    for (int it = 0; it < 8; it++) {
        int idx = tid + it * 256;
        int row = idx >> 3, c8 = idx & 7;
        cp16(sb + KVP_XS + row * 144 + c8 * 16, xsb + row * 64 + c8 * 8);
    }
    CP_COMMIT();

    __half* swk = (__half*)(smc + KVP_WK);
    __half* swv = (__half*)(smc + KVP_WV);
    for (int i = tid; i < 4096; i += 256) {
        int o = i >> 6, c = i & 63;
        swk[o * 72 + c] = __float2half_rn(wk[i]);
        swv[o * 72 + c] = __float2half_rn(wv[i]);
    }
    CP_WAIT0();
    __syncthreads();

    uint32_t xa = sb + KVP_XS + (uint32_t)((wid * 32 + (lt & 1) * 8 + lj) * 144 + (lt >> 1) * 16);
    uint32_t ap[2][4][4];
#pragma unroll
    for (int blk = 0; blk < 2; blk++)
#pragma unroll
        for (int kc = 0; kc < 4; kc++)
            LDSM4(ap[blk][kc][0], ap[blk][kc][1], ap[blk][kc][2], ap[blk][kc][3],
                  xa + blk * 16 * 144 + kc * 32);

    uint32_t wfrag = (uint32_t)(lj * 144 + lt * 16);

#pragma unroll
    for (int mat = 0; mat < 2; mat++) {
        uint32_t wb = sb + (mat ? KVP_WV : KVP_WK) + wfrag;
        const float* bias = mat ? bv : bk;
        __half* gout = (mat ? g_vh : g_kh) + bb * CHW;

        float oa[2][8][4];
#pragma unroll
        for (int blk = 0; blk < 2; blk++)
#pragma unroll
            for (int nc = 0; nc < 8; nc++)
#pragma unroll
                for (int j = 0; j < 4; j++) oa[blk][nc][j] = 0.f;

#pragma unroll
        for (int nc = 0; nc < 8; nc++) {
            uint32_t b0, b1, b2, b3, c0, c1, c2, c3;
            LDSM4(b0, b1, b2, b3, wb + nc * 1152);
            LDSM4(c0, c1, c2, c3, wb + nc * 1152 + 64);
#pragma unroll
            for (int blk = 0; blk < 2; blk++) {
                mma_f16(oa[blk][nc], ap[blk][0], b0, b1, oa[blk][nc]);
                mma_f16(oa[blk][nc], ap[blk][1], b2, b3, oa[blk][nc]);
                mma_f16(oa[blk][nc], ap[blk][2], c0, c1, oa[blk][nc]);
                mma_f16(oa[blk][nc], ap[blk][3], c2, c3, oa[blk][nc]);
            }
        }

#pragma unroll
        for (int blk = 0; blk < 2; blk++) {
            int row0 = p0 + wid * 32 + blk * 16 + qr;
#pragma unroll
            for (int nc = 0; nc < 8; nc++) {
                float2 bv2 = *(const float2*)(bias + nc * 8 + qc * 2);
                __half2 h0 = __floats2half2_rn(oa[blk][nc][0] + bv2.x, oa[blk][nc][1] + bv2.y);
                __half2 h1 = __floats2half2_rn(oa[blk][nc][2] + bv2.x, oa[blk][nc][3] + bv2.y);
                *(__half2*)(gout +  row0      * 64 + nc * 8 + qc * 2) = h0;
                *(__half2*)(gout + (row0 + 8) * 64 + nc * 8 + qc * 2) = h1;
            }
        }

        // ---- V column partial sums (fp32, pre-rounding, deterministic) ----
        if (mat == 1) {
#pragma unroll
            for (int nc = 0; nc < 8; nc++) {
                float2 bv2 = *(const float2*)(bias + nc * 8 + qc * 2);
                float s0 = oa[0][nc][0] + oa[0][nc][2] + oa[1][nc][0] + oa[1][nc][2] + 4.0f * bv2.x;
                float s1 = oa[0][nc][1] + oa[0][nc][3] + oa[1][nc][1] + oa[1][nc][3] + 4.0f * bv2.y;
                // reduce over qr (lanes differing in bits 2..4)
                s0 += __shfl_xor_sync(0xffffffffu, s0, 4);
                s0 += __shfl_xor_sync(0xffffffffu, s0, 8);
                s0 += __shfl_xor_sync(0xffffffffu, s0, 16);
                s1 += __shfl_xor_sync(0xffffffffu, s1, 4);
                s1 += __shfl_xor_sync(0xffffffffu, s1, 8);
                s1 += __shfl_xor_sync(0xffffffffu, s1, 16);
                if (qr == 0) {
                    s_sums[wid][nc * 8 + qc * 2    ] = s0;
                    s_sums[wid][nc * 8 + qc * 2 + 1] = s1;
                }
            }
            __syncthreads();
            if (tid < 64) {
                float s = 0.f;
#pragma unroll
                for (int g = 0; g < 8; g++) s += s_sums[g][tid];
                g_vspart[bb * 1024 + blockIdx.x * 64 + tid] = s;
            }
        }
    }
}

// ================= V column sums stage 2 =================
__global__ void k_vsum2() {
    int bb = blockIdx.x, c = threadIdx.x;
    float s = 0.f;
#pragma unroll
    for (int g = 0; g < 16; g++) s += g_vspart[bb * 1024 + g * 64 + c];
    g_vsum[bb * 64 + c] = s;
}

// ================= fp16 mma flash attention, 512 thr / 16 warps =============
#define KS0B 0
#define KS1B 18432
#define VS0B 36864
#define VS1B 55296
#define PSB  73728
#define ATTN_SMEM (PSB + 128*272)   // 108544 B

__global__ void __launch_bounds__(512) k_attn() {
    extern __shared__ char smc[];
    float* smf = (float*)smc;
    uint32_t sb = smem_u32(smc);
    int tid  = threadIdx.x;
    int wid  = tid >> 5;
    int lane = tid & 31;
    int qw   = wid & 7;
    int kh   = wid >> 3;
    int qr   = lane >> 2;
    int qc   = lane & 3;
    int lj   = lane & 7;
    int lt   = lane >> 3;
    int bb = blockIdx.y;
    int m0 = blockIdx.x * 128;

    const __half* qbh = g_qh + bb * CHW;
    const __half* kbh = g_kh + bb * CHW;
    const __half* vbh = g_vh + bb * CHW;

    uint32_t aq[4][4];
    {
        const __half* qp = qbh + (m0 + qw * 16) * 64;
#pragma unroll
        for (int kc = 0; kc < 4; kc++) {
            aq[kc][0] = *(const uint32_t*)(qp +  qr      * 64 + kc*16 + qc*2);
            aq[kc][1] = *(const uint32_t*)(qp + (qr + 8) * 64 + kc*16 + qc*2);
            aq[kc][2] = *(const uint32_t*)(qp +  qr      * 64 + kc*16 + qc*2 + 8);
            aq[kc][3] = *(const uint32_t*)(qp + (qr + 8) * 64 + kc*16 + qc*2 + 8);
        }
    }

    float oacc[8][4];
#pragma unroll
    for (int nc = 0; nc < 8; nc++)
#pragma unroll
        for (int j = 0; j < 4; j++) oacc[nc][j] = 0.f;
    float rs0 = 0.f, rs1 = 0.f;

    {
#pragma unroll
        for (int it = 0; it < 2; it++) {
            int idx = tid + it * 512;
            int key = idx >> 3, c8 = idx & 7;
            cp16(sb + KS0B + key * 144 + c8 * 16, kbh + key * 64 + c8 * 8);
            cp16(sb + VS0B + key * 144 + c8 * 16, vbh + key * 64 + c8 * 8);
        }
        CP_COMMIT();
    }

    uint32_t kq_off = (uint32_t)(lj * 144 + lt * 16);
    uint32_t vt_off = (uint32_t)(((lt & 1) * 8 + lj) * 144 + (lt >> 1) * 16);
    uint32_t pa0    = sb + PSB + (uint32_t)(kh * 128)
                    + (uint32_t)((qw * 16 + (lt & 1) * 8 + lj) * 272 + (lt >> 1) * 16);

    __half* Pb  = (__half*)(smc + PSB);
    __half* Pw0 = Pb + (qw * 16) * 136 + kh * 64;

    for (int i = 0; i < 32; i++) {
        __syncthreads();
        if (i + 1 < 32) {
            const __half* ks = kbh + (i + 1) * 128 * 64;
            const __half* vs = vbh + (i + 1) * 128 * 64;
            uint32_t ko = ((i + 1) & 1) ? KS1B : KS0B;
            uint32_t vo = ((i + 1) & 1) ? VS1B : VS0B;
#pragma unroll
            for (int it = 0; it < 2; it++) {
                int idx = tid + it * 512;
                int key = idx >> 3, c8 = idx & 7;
                cp16(sb + ko + key * 144 + c8 * 16, ks + key * 64 + c8 * 8);
                cp16(sb + vo + key * 144 + c8 * 16, vs + key * 64 + c8 * 8);
            }
            CP_COMMIT();
            CP_WAIT1();
        } else {
            CP_WAIT0();
        }
        __syncthreads();

        uint32_t Kb = sb + ((i & 1) ? KS1B : KS0B) + (uint32_t)(kh * 9216) + kq_off;
        uint32_t Vb = sb + ((i & 1) ? VS1B : VS0B) + (uint32_t)(kh * 9216) + vt_off;

#pragma unroll
        for (int nc = 0; nc < 8; nc++) {
            uint32_t b0, b1, b2, b3, c0, c1, c2, c3;
            LDSM4(b0, b1, b2, b3, Kb + nc * 1152);
            LDSM4(c0, c1, c2, c3, Kb + nc * 1152 + 64);
            float s0[4] = {0.f, 0.f, 0.f, 0.f};
            mma_f16(s0, aq[0], b0, b1, s0);
            mma_f16(s0, aq[1], b2, b3, s0);
            mma_f16(s0, aq[2], c0, c1, s0);
            mma_f16(s0, aq[3], c2, c3, s0);

            float e0 = __expf(s0[0] * SCALEV) - 1.0f;
            float e1 = __expf(s0[1] * SCALEV) - 1.0f;
            float e2 = __expf(s0[2] * SCALEV) - 1.0f;
            float e3 = __expf(s0[3] * SCALEV) - 1.0f;
            rs0 += e0 + e1;
            rs1 += e2 + e3;
            *(__half2*)(Pw0 +  qr      * 136 + nc * 8 + qc * 2) = __floats2half2_rn(e0, e1);
            *(__half2*)(Pw0 + (qr + 8) * 136 + nc * 8 + qc * 2) = __floats2half2_rn(e2, e3);
        }
        __syncwarp();

#pragma unroll
        for (int kc = 0; kc < 4; kc++) {
            uint32_t ap[4];
            LDSM4(ap[0], ap[1], ap[2], ap[3], pa0 + kc * 32);
            uint32_t Vk = Vb + (uint32_t)(kc * 16 * 144);
#pragma unroll
            for (int np = 0; np < 4; np++) {
                uint32_t b0, b1, b2, b3;
                LDSM4T(b0, b1, b2, b3, Vk + np * 32);
                mma_f16(oacc[np*2    ], ap, b0, b1, oacc[np*2    ]);
                mma_f16(oacc[np*2 + 1], ap, b2, b3, oacc[np*2 + 1]);
            }
        }
    }

    __syncthreads();
    float* scr = smf + qw * 1120;
    if (kh == 1) {
        float* s = scr + lane * 35;
#pragma unroll
        for (int nc = 0; nc < 8; nc++)
#pragma unroll
            for (int j = 0; j < 4; j++) s[nc * 4 + j] = oacc[nc][j];
        s[32] = rs0;
        s[33] = rs1;
    }
    __syncthreads();
    if (kh == 0) {
        float* s = scr + lane * 35;
#pragma unroll
        for (int nc = 0; nc < 8; nc++)
#pragma unroll
            for (int j = 0; j < 4; j++) oacc[nc][j] += s[nc * 4 + j];
        rs0 += s[32];
        rs1 += s[33];

        rs0 += __shfl_xor_sync(0xffffffffu, rs0, 1);
        rs0 += __shfl_xor_sync(0xffffffffu, rs0, 2);
        rs1 += __shfl_xor_sync(0xffffffffu, rs1, 1);
        rs1 += __shfl_xor_sync(0xffffffffu, rs1, 2);
        float inv0 = 1.0f / (4096.0f + rs0);
        float inv1 = 1.0f / (4096.0f + rs1);

        const float* vsum = g_vsum + bb * 64;
        __half* ob = g_ao + bb * CHW + (m0 + qw * 16) * 64;
#pragma unroll
        for (int nc = 0; nc < 8; nc++) {
            float2 vs2 = *(const float2*)(vsum + nc * 8 + 2 * qc);
            *(__half2*)(ob +  qr      * 64 + nc * 8 + 2 * qc) =
                __floats2half2_rn((oacc[nc][0] + vs2.x) * inv0, (oacc[nc][1] + vs2.y) * inv0);
            *(__half2*)(ob + (qr + 8) * 64 + nc * 8 + 2 * qc) =
                __floats2half2_rn((oacc[nc][2] + vs2.x) * inv1, (oacc[nc][3] + vs2.y) * inv1);
        }
    }
}

// ================= output projection GEMM: out[c][p] = ao[p][c]*wo^T + bo =====
#define OP_AO 0
#define OP_WO 36864
#define OP_SMEM 46080

__global__ void __launch_bounds__(256) k_oproj(const float* __restrict__ wo,
                                               const float* __restrict__ bo,
                                               float* __restrict__ out) {
    extern __shared__ char smc[];
    uint32_t sb = smem_u32(smc);
    int tid = threadIdx.x, wid = tid >> 5, lane = tid & 31;
    int lj = lane & 7, lt = lane >> 3;
    int qr = lane >> 2, qc = lane & 3;
    int bb = blockIdx.y;
    int p0 = blockIdx.x * 256;

    const __half* aob = g_ao + bb * CHW + p0 * 64;
#pragma unroll
    for (int it = 0; it < 8; it++) {
        int idx = tid + it * 256;
        int row = idx >> 3, c8 = idx & 7;
        cp16(sb + OP_AO + row * 144 + c8 * 16, aob + row * 64 + c8 * 8);
    }
    CP_COMMIT();

    __half* swo = (__half*)(smc + OP_WO);
    for (int i = tid; i < 4096; i += 256) {
        int o = i >> 6, c = i & 63;
        swo[o * 72 + c] = __float2half_rn(wo[i]);
    }
    CP_WAIT0();
    __syncthreads();

    uint32_t xa = sb + OP_AO + (uint32_t)((wid * 32 + (lt & 1) * 8 + lj) * 144 + (lt >> 1) * 16);
    uint32_t ap[2][4][4];
#pragma unroll
    for (int blk = 0; blk < 2; blk++)
#pragma unroll
        for (int kc = 0; kc < 4; kc++)
            LDSM4(ap[blk][kc][0], ap[blk][kc][1], ap[blk][kc][2], ap[blk][kc][3],
                  xa + blk * 16 * 144 + kc * 32);

    uint32_t wb = sb + OP_WO + (uint32_t)(lj * 144 + lt * 16);

    float oa[2][8][4];
#pragma unroll
    for (int blk = 0; blk < 2; blk++)
#pragma unroll
        for (int nc = 0; nc < 8; nc++)
#pragma unroll
            for (int j = 0; j < 4; j++) oa[blk][nc][j] = 0.f;

#pragma unroll
    for (int nc = 0; nc < 8; nc++) {
        uint32_t b0, b1, b2, b3, c0, c1, c2, c3;
        LDSM4(b0, b1, b2, b3, wb + nc * 1152);
        LDSM4(c0, c1, c2, c3, wb + nc * 1152 + 64);
#pragma unroll
        for (int blk = 0; blk < 2; blk++) {
            mma_f16(oa[blk][nc], ap[blk][0], b0, b1, oa[blk][nc]);
            mma_f16(oa[blk][nc], ap[blk][1], b2, b3, oa[blk][nc]);
            mma_f16(oa[blk][nc], ap[blk][2], c0, c1, oa[blk][nc]);
            mma_f16(oa[blk][nc], ap[blk][3], c2, c3, oa[blk][nc]);
        }
    }

    float* outb = out + bb * CHW;
#pragma unroll
    for (int blk = 0; blk < 2; blk++) {
        int prow = p0 + wid * 32 + blk * 16 + qr;
#pragma unroll
        for (int nc = 0; nc < 8; nc++) {
            int ch = nc * 8 + qc * 2;
            float2 bo2 = *(const float2*)(bo + ch);
            outb[ ch      * HW + prow    ] = oa[blk][nc][0] + bo2.x;
            outb[(ch + 1) * HW + prow    ] = oa[blk][nc][1] + bo2.y;
            outb[ ch      * HW + prow + 8] = oa[blk][nc][2] + bo2.x;
            outb[(ch + 1) * HW + prow + 8] = oa[blk][nc][3] + bo2.y;
        }
    }
}

// ================= launch =================
extern "C" void kernel_launch(void* const* d_in, const int* in_sizes, int n_in,
                              void* d_out, int out_size) {
    const float* prompt = (const float*)d_in[0];
    const float* kv     = (const float*)d_in[1];
    const float* wq     = (const float*)d_in[2];
    const float* bq     = (const float*)d_in[3];
    const float* wk     = (const float*)d_in[4];
    const float* bk     = (const float*)d_in[5];
    const float* wv     = (const float*)d_in[6];
    const float* bv     = (const float*)d_in[7];
    const float* wo     = (const float*)d_in[8];
    const float* bo     = (const float*)d_in[9];
    const float* dw_w   = (const float*)d_in[10];
    const float* dw_b   = (const float*)d_in[11];
    const float* ln_w   = (const float*)d_in[12];
    const float* ln_b   = (const float*)d_in[13];
    const float* off_w  = (const float*)d_in[14];
    float* out = (float*)d_out;

    cudaFuncSetAttribute(k_attn,   cudaFuncAttributeMaxDynamicSharedMemorySize, ATTN_SMEM);
    cudaFuncSetAttribute(k_kvproj, cudaFuncAttributeMaxDynamicSharedMemorySize, KVP_SMEM);
    cudaFuncSetAttribute(k_oproj,  cudaFuncAttributeMaxDynamicSharedMemorySize, OP_SMEM);
    cudaFuncSetAttribute(k_qproj,  cudaFuncAttributeMaxDynamicSharedMemorySize, QP_SMEM);

    k_qproj <<<dim3(16, BB), 256, QP_SMEM>>>(prompt, wq, bq);
    k_fuse  <<<dim3(32, BB), 128>>>(kv, dw_w, dw_b, ln_w, ln_b, off_w);
    k_kvproj<<<dim3(16, BB), 256, KVP_SMEM>>>(wk, bk, wv, bv);
    k_vsum2 <<<BB, 64>>>();
    k_attn  <<<dim3(32, BB), 512, ATTN_SMEM>>>();
    k_oproj <<<dim3(16, BB), 256, OP_SMEM>>>(wo, bo, out);
}

// round 16
// speedup vs baseline: 1.8772x; 1.0576x over previous
#include <cuda_runtime.h>
#include <cuda_fp16.h>
#include <math.h>
#include <stdint.h>

#define BB 4
#define CC 64
#define HW 4096
#define CHW (CC*HW)
#define EPSV 1e-5f
#define OFRV 4.0f
#define SCALEV 0.125f

// -------- scratch (device globals) --------
__device__ __half g_qh[BB*CHW];   // [b][p][c]  fp16
__device__ __half g_xs[BB*CHW];   // [b][p][c]  gathered features fp16
__device__ __half g_kh[BB*CHW];   // [b][n][c]  fp16
__device__ __half g_vh[BB*CHW];   // [b][n][c]  fp16
__device__ __half g_ao[BB*CHW];   // [b][p][c]  fp16 attention out
__device__ float  g_vspart[BB*32*64];

// ================= helpers =================
__device__ __forceinline__ uint32_t smem_u32(const void* p){
    uint32_t a;
    asm("{ .reg .u64 t; cvta.to.shared.u64 t, %1; cvt.u32.u64 %0, t; }" : "=r"(a) : "l"(p));
    return a;
}
__device__ __forceinline__ void cp16(uint32_t dst, const void* src){
    asm volatile("cp.async.cg.shared.global [%0], [%1], 16;" :: "r"(dst), "l"(src));
}
#define CP_COMMIT() asm volatile("cp.async.commit_group;" ::: "memory")
#define CP_WAIT0()  asm volatile("cp.async.wait_group 0;" ::: "memory")
#define CP_WAIT1()  asm volatile("cp.async.wait_group 1;" ::: "memory")

#define LDSM4(R0,R1,R2,R3,ADDR) \
    asm volatile("ldmatrix.sync.aligned.m8n8.x4.shared.b16 {%0,%1,%2,%3}, [%4];" \
        : "=r"(R0),"=r"(R1),"=r"(R2),"=r"(R3) : "r"(ADDR))

#define LDSM4T(R0,R1,R2,R3,ADDR) \
    asm volatile("ldmatrix.sync.aligned.m8n8.x4.trans.shared.b16 {%0,%1,%2,%3}, [%4];" \
        : "=r"(R0),"=r"(R1),"=r"(R2),"=r"(R3) : "r"(ADDR))

__device__ __forceinline__ void mma_f16(float* d, const uint32_t* a,
                                        uint32_t b0, uint32_t b1, const float* c){
    asm volatile(
        "mma.sync.aligned.m16n8k16.row.col.f32.f16.f16.f32 "
        "{%0,%1,%2,%3}, {%4,%5,%6,%7}, {%8,%9}, {%10,%11,%12,%13};"
        : "=f"(d[0]), "=f"(d[1]), "=f"(d[2]), "=f"(d[3])
        : "r"(a[0]), "r"(a[1]), "r"(a[2]), "r"(a[3]),
          "r"(b0), "r"(b1),
          "f"(c[0]), "f"(c[1]), "f"(c[2]), "f"(c[3]));
}

// ================= q projection GEMM: 128 pixels/block ======================
// prompt [c][p] fp32 -> smem [c][p] fp16 (272-B rows), A via ldmatrix.trans
#define QP_PX 0
#define QP_W  17408              // 64 rows * 272 B
#define QP_SMEM (17408 + 9216)

__global__ void __launch_bounds__(256) k_qproj(const float* __restrict__ prompt,
                                               const float* __restrict__ wq,
                                               const float* __restrict__ bq) {
    extern __shared__ char smc[];
    uint32_t sb = smem_u32(smc);
    int tid = threadIdx.x, wid = tid >> 5, lane = tid & 31;
    int lj = lane & 7, lt = lane >> 3;
    int qr = lane >> 2, qc = lane & 3;
    int bb = blockIdx.y;
    int p0 = blockIdx.x * 128;

    // transpose-convert prompt[c][p0..p0+127] -> smem fp16 rows
    {
        int c   = tid >> 2;        // 0..63
        int seg = tid & 3;         // 32 pixels each
        const float4* pr = (const float4*)(prompt + bb * CHW + c * HW + p0 + seg * 32);
        __half* dst = (__half*)(smc + QP_PX + c * 272) + seg * 32;
#pragma unroll
        for (int i = 0; i < 8; i++) {
            float4 v = pr[i];
            __half2 h0 = __floats2half2_rn(v.x, v.y);
            __half2 h1 = __floats2half2_rn(v.z, v.w);
            ((uint2*)dst)[i] = make_uint2(*(uint32_t*)&h0, *(uint32_t*)&h1);
        }
    }
    __half* sw = (__half*)(smc + QP_W);
    for (int i = tid; i < 4096; i += 256) {
        int o = i >> 6, c = i & 63;
        sw[o * 72 + c] = __float2half_rn(wq[i]);
    }
    __syncthreads();

    uint32_t xa = sb + QP_PX + (uint32_t)(((lt >> 1) * 8 + lj) * 272
                + (wid * 16 + (lt & 1) * 8) * 2);
    uint32_t ap[4][4];
#pragma unroll
    for (int kc = 0; kc < 4; kc++)
        LDSM4T(ap[kc][0], ap[kc][1], ap[kc][2], ap[kc][3],
               xa + (uint32_t)(kc * 16 * 272));

    uint32_t wb = sb + QP_W + (uint32_t)(lj * 144 + lt * 16);

    float oa[8][4];
#pragma unroll
    for (int nc = 0; nc < 8; nc++)
#pragma unroll
        for (int j = 0; j < 4; j++) oa[nc][j] = 0.f;

#pragma unroll
    for (int nc = 0; nc < 8; nc++) {
        uint32_t b0, b1, b2, b3, c0, c1, c2, c3;
        LDSM4(b0, b1, b2, b3, wb + nc * 1152);
        LDSM4(c0, c1, c2, c3, wb + nc * 1152 + 64);
        mma_f16(oa[nc], ap[0], b0, b1, oa[nc]);
        mma_f16(oa[nc], ap[1], b2, b3, oa[nc]);
        mma_f16(oa[nc], ap[2], c0, c1, oa[nc]);
        mma_f16(oa[nc], ap[3], c2, c3, oa[nc]);
    }

    __half* gout = g_qh + bb * CHW;
    int row0 = p0 + wid * 16 + qr;
#pragma unroll
    for (int nc = 0; nc < 8; nc++) {
        float2 b2v = *(const float2*)(bq + nc * 8 + qc * 2);
        *(__half2*)(gout +  row0      * 64 + nc * 8 + qc * 2) =
            __floats2half2_rn(oa[nc][0] + b2v.x, oa[nc][1] + b2v.y);
        *(__half2*)(gout + (row0 + 8) * 64 + nc * 8 + qc * 2) =
            __floats2half2_rn(oa[nc][2] + b2v.x, oa[nc][3] + b2v.y);
    }
}

// ================= fused: dw3x3 + LN + GELU + offset + tanh + bilinear -> xs
__global__ void k_fuse(const float* __restrict__ kv,
                       const float* __restrict__ dw_w,
                       const float* __restrict__ dw_b,
                       const float* __restrict__ ln_w,
                       const float* __restrict__ ln_b,
                       const float* __restrict__ off_w) {
    __shared__ float s_dw[576], s_dwb[64], s_lnw[64], s_lnb[64];
    __shared__ float s_offw[128];

    for (int i = threadIdx.x; i < 576; i += 128) s_dw[i] = dw_w[i];
    if (threadIdx.x < 64) {
        s_dwb[threadIdx.x] = dw_b[threadIdx.x];
        s_lnw[threadIdx.x] = ln_w[threadIdx.x];
        s_lnb[threadIdx.x] = ln_b[threadIdx.x];
    }
    if (threadIdx.x < 128) s_offw[threadIdx.x] = off_w[threadIdx.x];
    __syncthreads();

    int p  = blockIdx.x * 128 + threadIdx.x;
    int bb = blockIdx.y;
    int py = p >> 6;
    int px = p & 63;

    const __half* qb = g_qh + bb * CHW;

    float t[64];
#pragma unroll
    for (int c = 0; c < 64; c++) t[c] = s_dwb[c];

    for (int k9 = 0; k9 < 9; k9++) {
        int dy = k9 / 3 - 1, dx = k9 % 3 - 1;
        int yy = py + dy, xx = px + dx;
        if (yy < 0 || yy > 63 || xx < 0 || xx > 63) continue;
        const uint4* qp = (const uint4*)(qb + (yy * 64 + xx) * 64);
#pragma unroll
        for (int c8 = 0; c8 < 8; c8++) {
            uint4 u = qp[c8];
            uint32_t uu[4] = {u.x, u.y, u.z, u.w};
#pragma unroll
            for (int j = 0; j < 4; j++) {
                float2 f = __half22float2(*(__half2*)&uu[j]);
                t[c8*8 + j*2    ] += f.x * s_dw[(c8*8 + j*2    )*9 + k9];
                t[c8*8 + j*2 + 1] += f.y * s_dw[(c8*8 + j*2 + 1)*9 + k9];
            }
        }
    }

    float mu = 0.f;
#pragma unroll
    for (int c = 0; c < 64; c++) mu += t[c];
    mu *= (1.0f / 64.0f);
    float var = 0.f;
#pragma unroll
    for (int c = 0; c < 64; c++) { float d = t[c] - mu; var += d * d; }
    var *= (1.0f / 64.0f);
    float rstd = rsqrtf(var + EPSV);
#pragma unroll
    for (int c = 0; c < 64; c++) {
        float z = (t[c] - mu) * rstd * s_lnw[c] + s_lnb[c];
        t[c] = 0.5f * z * (1.0f + erff(z * 0.70710678118654752f));
    }

    float o0 = 0.f, o1 = 0.f;
#pragma unroll
    for (int c = 0; c < 64; c++) { o0 += s_offw[c] * t[c]; o1 += s_offw[64 + c] * t[c]; }
    float off0 = tanhf(o0) * (1.0f / 63.0f) * OFRV;
    float off1 = tanhf(o1) * (1.0f / 63.0f) * OFRV;

    float refy = (0.5f + (float)py) * (2.0f / 63.0f) - 1.0f;
    float refx = (0.5f + (float)px) * (2.0f / 63.0f) - 1.0f;
    float gx = (off1 + refx + 1.0f) * 0.5f * 63.0f;
    float gy = (off0 + refy + 1.0f) * 0.5f * 63.0f;

    float x0f = floorf(gx), y0f = floorf(gy);
    float wx = gx - x0f, wy = gy - y0f;
    int x0 = (int)x0f, y0 = (int)y0f;
    int x1 = x0 + 1,   y1 = y0 + 1;

    float m00 = (x0 >= 0 && x0 <= 63 && y0 >= 0 && y0 <= 63) ? 1.f : 0.f;
    float m01 = (x1 >= 0 && x1 <= 63 && y0 >= 0 && y0 <= 63) ? 1.f : 0.f;
    float m10 = (x0 >= 0 && x0 <= 63 && y1 >= 0 && y1 <= 63) ? 1.f : 0.f;
    float m11 = (x1 >= 0 && x1 <= 63 && y1 >= 0 && y1 <= 63) ? 1.f : 0.f;

    int xc0 = min(max(x0, 0), 63), xc1 = min(max(x1, 0), 63);
    int yc0 = min(max(y0, 0), 63), yc1 = min(max(y1, 0), 63);

    float w00 = m00 * (1.0f - wx) * (1.0f - wy);
    float w01 = m01 * wx * (1.0f - wy);
    float w10 = m10 * (1.0f - wx) * wy;
    float w11 = m11 * wx * wy;

    int i00 = yc0 * 64 + xc0, i01 = yc0 * 64 + xc1;
    int i10 = yc1 * 64 + xc0, i11 = yc1 * 64 + xc1;

    const float* kvb = kv + bb * CHW;
    uint2* xout = (uint2*)(g_xs + bb * CHW + p * 64);
#pragma unroll
    for (int c4 = 0; c4 < 16; c4++) {
        float v[4];
#pragma unroll
        for (int j = 0; j < 4; j++) {
            const float* kc = kvb + (c4*4 + j) * HW;
            v[j] = w00 * kc[i00] + w01 * kc[i01] + w10 * kc[i10] + w11 * kc[i11];
        }
        __half2 h0 = __floats2half2_rn(v[0], v[1]);
        __half2 h1 = __floats2half2_rn(v[2], v[3]);
        xout[c4] = make_uint2(*(uint32_t*)&h0, *(uint32_t*)&h1);
    }
}

// ================= K/V projection GEMM (128 pixels/block) + V partial sums ==
#define KVP_XS 0
#define KVP_WK 18432
#define KVP_WV 27648
#define KVP_SMEM 36864

__global__ void __launch_bounds__(256) k_kvproj(const float* __restrict__ wk,
                                                const float* __restrict__ bk,
                                                const float* __restrict__ wv,
                                                const float* __restrict__ bv) {
    extern __shared__ char smc[];
    __shared__ float s_sums[8][64];
    uint32_t sb = smem_u32(smc);
    int tid = threadIdx.x, wid = tid >> 5, lane = tid & 31;
    int lj = lane & 7, lt = lane >> 3;
    int qr = lane >> 2, qc = lane & 3;
    int bb = blockIdx.y;
    int p0 = blockIdx.x * 128;

    const __half* xsb = g_xs + bb * CHW + p0 * 64;
#pragma unroll
    for (int it = 0; it < 4; it++) {
        int idx = tid + it * 256;
        int row = idx >> 3, c8 = idx & 7;
        cp16(sb + KVP_XS + row * 144 + c8 * 16, xsb + row * 64 + c8 * 8);
    }
    CP_COMMIT();

    __half* swk = (__half*)(smc + KVP_WK);
    __half* swv = (__half*)(smc + KVP_WV);
    for (int i = tid; i < 4096; i += 256) {
        int o = i >> 6, c = i & 63;
        swk[o * 72 + c] = __float2half_rn(wk[i]);
        swv[o * 72 + c] = __float2half_rn(wv[i]);
    }
    CP_WAIT0();
    __syncthreads();

    uint32_t xa = sb + KVP_XS + (uint32_t)((wid * 16 + (lt & 1) * 8 + lj) * 144 + (lt >> 1) * 16);
    uint32_t ap[4][4];
#pragma unroll
    for (int kc = 0; kc < 4; kc++)
        LDSM4(ap[kc][0], ap[kc][1], ap[kc][2], ap[kc][3], xa + kc * 32);

    uint32_t wfrag = (uint32_t)(lj * 144 + lt * 16);

#pragma unroll
    for (int mat = 0; mat < 2; mat++) {
        uint32_t wb = sb + (mat ? KVP_WV : KVP_WK) + wfrag;
        const float* bias = mat ? bv : bk;
        __half* gout = (mat ? g_vh : g_kh) + bb * CHW;

        float oa[8][4];
#pragma unroll
        for (int nc = 0; nc < 8; nc++)
#pragma unroll
            for (int j = 0; j < 4; j++) oa[nc][j] = 0.f;

#pragma unroll
        for (int nc = 0; nc < 8; nc++) {
            uint32_t b0, b1, b2, b3, c0, c1, c2, c3;
            LDSM4(b0, b1, b2, b3, wb + nc * 1152);
            LDSM4(c0, c1, c2, c3, wb + nc * 1152 + 64);
            mma_f16(oa[nc], ap[0], b0, b1, oa[nc]);
            mma_f16(oa[nc], ap[1], b2, b3, oa[nc]);
            mma_f16(oa[nc], ap[2], c0, c1, oa[nc]);
            mma_f16(oa[nc], ap[3], c2, c3, oa[nc]);
        }

        int row0 = p0 + wid * 16 + qr;
#pragma unroll
        for (int nc = 0; nc < 8; nc++) {
            float2 bv2 = *(const float2*)(bias + nc * 8 + qc * 2);
            *(__half2*)(gout +  row0      * 64 + nc * 8 + qc * 2) =
                __floats2half2_rn(oa[nc][0] + bv2.x, oa[nc][1] + bv2.y);
            *(__half2*)(gout + (row0 + 8) * 64 + nc * 8 + qc * 2) =
                __floats2half2_rn(oa[nc][2] + bv2.x, oa[nc][3] + bv2.y);
        }

        // ---- V column partial sums (fp32, pre-rounding, deterministic) ----
        if (mat == 1) {
#pragma unroll
            for (int nc = 0; nc < 8; nc++) {
                float2 bv2 = *(const float2*)(bias + nc * 8 + qc * 2);
                float s0 = oa[nc][0] + oa[nc][2] + 2.0f * bv2.x;
                float s1 = oa[nc][1] + oa[nc][3] + 2.0f * bv2.y;
                s0 += __shfl_xor_sync(0xffffffffu, s0, 4);
                s0 += __shfl_xor_sync(0xffffffffu, s0, 8);
                s0 += __shfl_xor_sync(0xffffffffu, s0, 16);
                s1 += __shfl_xor_sync(0xffffffffu, s1, 4);
                s1 += __shfl_xor_sync(0xffffffffu, s1, 8);
                s1 += __shfl_xor_sync(0xffffffffu, s1, 16);
                if (qr == 0) {
                    s_sums[wid][nc * 8 + qc * 2    ] = s0;
                    s_sums[wid][nc * 8 + qc * 2 + 1] = s1;
                }
            }
            __syncthreads();
            if (tid < 64) {
                float s = 0.f;
#pragma unroll
                for (int g = 0; g < 8; g++) s += s_sums[g][tid];
                g_vspart[bb * 2048 + blockIdx.x * 64 + tid] = s;
            }
        }
    }
}

// ================= fp16 mma flash attention, 512 thr / 16 warps =============
#define KS0B 0
#define KS1B 18432
#define VS0B 36864
#define VS1B 55296
#define PSB  73728
#define VSUMB (PSB + 128*272)        // 108544
#define ATTN_SMEM (VSUMB + 256)      // 108800

__global__ void __launch_bounds__(512) k_attn() {
    extern __shared__ char smc[];
    float* smf = (float*)smc;
    uint32_t sb = smem_u32(smc);
    int tid  = threadIdx.x;
    int wid  = tid >> 5;
    int lane = tid & 31;
    int qw   = wid & 7;
    int kh   = wid >> 3;
    int qr   = lane >> 2;
    int qc   = lane & 3;
    int lj   = lane & 7;
    int lt   = lane >> 3;
    int bb = blockIdx.y;
    int m0 = blockIdx.x * 128;

    const __half* qbh = g_qh + bb * CHW;
    const __half* kbh = g_kh + bb * CHW;
    const __half* vbh = g_vh + bb * CHW;

    uint32_t aq[4][4];
    {
        const __half* qp = qbh + (m0 + qw * 16) * 64;
#pragma unroll
        for (int kc = 0; kc < 4; kc++) {
            aq[kc][0] = *(const uint32_t*)(qp +  qr      * 64 + kc*16 + qc*2);
            aq[kc][1] = *(const uint32_t*)(qp + (qr + 8) * 64 + kc*16 + qc*2);
            aq[kc][2] = *(const uint32_t*)(qp +  qr      * 64 + kc*16 + qc*2 + 8);
            aq[kc][3] = *(const uint32_t*)(qp + (qr + 8) * 64 + kc*16 + qc*2 + 8);
        }
    }

    float oacc[8][4];
#pragma unroll
    for (int nc = 0; nc < 8; nc++)
#pragma unroll
        for (int j = 0; j < 4; j++) oacc[nc][j] = 0.f;
    float rs0 = 0.f, rs1 = 0.f;

    {
#pragma unroll
        for (int it = 0; it < 2; it++) {
            int idx = tid + it * 512;
            int key = idx >> 3, c8 = idx & 7;
            cp16(sb + KS0B + key * 144 + c8 * 16, kbh + key * 64 + c8 * 8);
            cp16(sb + VS0B + key * 144 + c8 * 16, vbh + key * 64 + c8 * 8);
        }
        CP_COMMIT();
    }

    // ---- reduce V column partial sums into smem (replaces k_vsum2) ----
    float* s_vsum = (float*)(smc + VSUMB);
    if (tid < 64) {
        float s = 0.f;
#pragma unroll
        for (int g = 0; g < 32; g++) s += g_vspart[bb * 2048 + g * 64 + tid];
        s_vsum[tid] = s;
    }

    uint32_t kq_off = (uint32_t)(lj * 144 + lt * 16);
    uint32_t vt_off = (uint32_t)(((lt & 1) * 8 + lj) * 144 + (lt >> 1) * 16);
    uint32_t pa0    = sb + PSB + (uint32_t)(kh * 128)
                    + (uint32_t)((qw * 16 + (lt & 1) * 8 + lj) * 272 + (lt >> 1) * 16);

    __half* Pb  = (__half*)(smc + PSB);
    __half* Pw0 = Pb + (qw * 16) * 136 + kh * 64;

    for (int i = 0; i < 32; i++) {
        __syncthreads();
        if (i + 1 < 32) {
            const __half* ks = kbh + (i + 1) * 128 * 64;
            const __half* vs = vbh + (i + 1) * 128 * 64;
            uint32_t ko = ((i + 1) & 1) ? KS1B : KS0B;
            uint32_t vo = ((i + 1) & 1) ? VS1B : VS0B;
#pragma unroll
            for (int it = 0; it < 2; it++) {
                int idx = tid + it * 512;
                int key = idx >> 3, c8 = idx & 7;
                cp16(sb + ko + key * 144 + c8 * 16, ks + key * 64 + c8 * 8);
                cp16(sb + vo + key * 144 + c8 * 16, vs + key * 64 + c8 * 8);
            }
            CP_COMMIT();
            CP_WAIT1();
        } else {
            CP_WAIT0();
        }
        __syncthreads();

        uint32_t Kb = sb + ((i & 1) ? KS1B : KS0B) + (uint32_t)(kh * 9216) + kq_off;
        uint32_t Vb = sb + ((i & 1) ? VS1B : VS0B) + (uint32_t)(kh * 9216) + vt_off;

#pragma unroll
        for (int nc = 0; nc < 8; nc++) {
            uint32_t b0, b1, b2, b3, c0, c1, c2, c3;
            LDSM4(b0, b1, b2, b3, Kb + nc * 1152);
            LDSM4(c0, c1, c2, c3, Kb + nc * 1152 + 64);
            float s0[4] = {0.f, 0.f, 0.f, 0.f};
            mma_f16(s0, aq[0], b0, b1, s0);
            mma_f16(s0, aq[1], b2, b3, s0);
            mma_f16(s0, aq[2], c0, c1, s0);
            mma_f16(s0, aq[3], c2, c3, s0);

            float e0 = __expf(s0[0] * SCALEV) - 1.0f;
            float e1 = __expf(s0[1] * SCALEV) - 1.0f;
            float e2 = __expf(s0[2] * SCALEV) - 1.0f;
            float e3 = __expf(s0[3] * SCALEV) - 1.0f;
            rs0 += e0 + e1;
            rs1 += e2 + e3;
            *(__half2*)(Pw0 +  qr      * 136 + nc * 8 + qc * 2) = __floats2half2_rn(e0, e1);
            *(__half2*)(Pw0 + (qr + 8) * 136 + nc * 8 + qc * 2) = __floats2half2_rn(e2, e3);
        }
        __syncwarp();

#pragma unroll
        for (int kc = 0; kc < 4; kc++) {
            uint32_t ap[4];
            LDSM4(ap[0], ap[1], ap[2], ap[3], pa0 + kc * 32);
            uint32_t Vk = Vb + (uint32_t)(kc * 16 * 144);
#pragma unroll
            for (int np = 0; np < 4; np++) {
                uint32_t b0, b1, b2, b3;
                LDSM4T(b0, b1, b2, b3, Vk + np * 32);
                mma_f16(oacc[np*2    ], ap, b0, b1, oacc[np*2    ]);
                mma_f16(oacc[np*2 + 1], ap, b2, b3, oacc[np*2 + 1]);
            }
        }
    }

    __syncthreads();
    float* scr = smf + qw * 1120;
    if (kh == 1) {
        float* s = scr + lane * 35;
#pragma unroll
        for (int nc = 0; nc < 8; nc++)
#pragma unroll
            for (int j = 0; j < 4; j++) s[nc * 4 + j] = oacc[nc][j];
        s[32] = rs0;
        s[33] = rs1;
    }
    __syncthreads();
    if (kh == 0) {
        float* s = scr + lane * 35;
#pragma unroll
        for (int nc = 0; nc < 8; nc++)
#pragma unroll
            for (int j = 0; j < 4; j++) oacc[nc][j] += s[nc * 4 + j];
        rs0 += s[32];
        rs1 += s[33];

        rs0 += __shfl_xor_sync(0xffffffffu, rs0, 1);
        rs0 += __shfl_xor_sync(0xffffffffu, rs0, 2);
        rs1 += __shfl_xor_sync(0xffffffffu, rs1, 1);
        rs1 += __shfl_xor_sync(0xffffffffu, rs1, 2);
        float inv0 = 1.0f / (4096.0f + rs0);
        float inv1 = 1.0f / (4096.0f + rs1);

        __half* ob = g_ao + bb * CHW + (m0 + qw * 16) * 64;
#pragma unroll
        for (int nc = 0; nc < 8; nc++) {
            float2 vs2 = *(const float2*)(s_vsum + nc * 8 + 2 * qc);
            *(__half2*)(ob +  qr      * 64 + nc * 8 + 2 * qc) =
                __floats2half2_rn((oacc[nc][0] + vs2.x) * inv0, (oacc[nc][1] + vs2.y) * inv0);
            *(__half2*)(ob + (qr + 8) * 64 + nc * 8 + 2 * qc) =
                __floats2half2_rn((oacc[nc][2] + vs2.x) * inv1, (oacc[nc][3] + vs2.y) * inv1);
        }
    }
}

// ================= output projection GEMM (128 pixels/block) ================
#define OP_AO 0
#define OP_WO 18432
#define OP_SMEM 27648

__global__ void __launch_bounds__(256) k_oproj(const float* __restrict__ wo,
                                               const float* __restrict__ bo,
                                               float* __restrict__ out) {
    extern __shared__ char smc[];
    uint32_t sb = smem_u32(smc);
    int tid = threadIdx.x, wid = tid >> 5, lane = tid & 31;
    int lj = lane & 7, lt = lane >> 3;
    int qr = lane >> 2, qc = lane & 3;
    int bb = blockIdx.y;
    int p0 = blockIdx.x * 128;

    const __half* aob = g_ao + bb * CHW + p0 * 64;
#pragma unroll
    for (int it = 0; it < 4; it++) {
        int idx = tid + it * 256;
        int row = idx >> 3, c8 = idx & 7;
        cp16(sb + OP_AO + row * 144 + c8 * 16, aob + row * 64 + c8 * 8);
    }
    CP_COMMIT();

    __half* swo = (__half*)(smc + OP_WO);
    for (int i = tid; i < 4096; i += 256) {
        int o = i >> 6, c = i & 63;
        swo[o * 72 + c] = __float2half_rn(wo[i]);
    }
    CP_WAIT0();
    __syncthreads();

    uint32_t xa = sb + OP_AO + (uint32_t)((wid * 16 + (lt & 1) * 8 + lj) * 144 + (lt >> 1) * 16);
    uint32_t ap[4][4];
#pragma unroll
    for (int kc = 0; kc < 4; kc++)
        LDSM4(ap[kc][0], ap[kc][1], ap[kc][2], ap[kc][3], xa + kc * 32);

    uint32_t wb = sb + OP_WO + (uint32_t)(lj * 144 + lt * 16);

    float oa[8][4];
#pragma unroll
    for (int nc = 0; nc < 8; nc++)
#pragma unroll
        for (int j = 0; j < 4; j++) oa[nc][j] = 0.f;

#pragma unroll
    for (int nc = 0; nc < 8; nc++) {
        uint32_t b0, b1, b2, b3, c0, c1, c2, c3;
        LDSM4(b0, b1, b2, b3, wb + nc * 1152);
        LDSM4(c0, c1, c2, c3, wb + nc * 1152 + 64);
        mma_f16(oa[nc], ap[0], b0, b1, oa[nc]);
        mma_f16(oa[nc], ap[1], b2, b3, oa[nc]);
        mma_f16(oa[nc], ap[2], c0, c1, oa[nc]);
        mma_f16(oa[nc], ap[3], c2, c3, oa[nc]);
    }

    float* outb = out + bb * CHW;
    int prow = p0 + wid * 16 + qr;
#pragma unroll
    for (int nc = 0; nc < 8; nc++) {
        int ch = nc * 8 + qc * 2;
        float2 bo2 = *(const float2*)(bo + ch);
        outb[ ch      * HW + prow    ] = oa[nc][0] + bo2.x;
        outb[(ch + 1) * HW + prow    ] = oa[nc][1] + bo2.y;
        outb[ ch      * HW + prow + 8] = oa[nc][2] + bo2.x;
        outb[(ch + 1) * HW + prow + 8] = oa[nc][3] + bo2.y;
    }
}

// ================= launch =================
extern "C" void kernel_launch(void* const* d_in, const int* in_sizes, int n_in,
                              void* d_out, int out_size) {
    const float* prompt = (const float*)d_in[0];
    const float* kv     = (const float*)d_in[1];
    const float* wq     = (const float*)d_in[2];
    const float* bq     = (const float*)d_in[3];
    const float* wk     = (const float*)d_in[4];
    const float* bk     = (const float*)d_in[5];
    const float* wv     = (const float*)d_in[6];
    const float* bv     = (const float*)d_in[7];
    const float* wo     = (const float*)d_in[8];
    const float* bo     = (const float*)d_in[9];
    const float* dw_w   = (const float*)d_in[10];
    const float* dw_b   = (const float*)d_in[11];
    const float* ln_w   = (const float*)d_in[12];
    const float* ln_b   = (const float*)d_in[13];
    const float* off_w  = (const float*)d_in[14];
    float* out = (float*)d_out;

    cudaFuncSetAttribute(k_attn,   cudaFuncAttributeMaxDynamicSharedMemorySize, ATTN_SMEM);
    cudaFuncSetAttribute(k_kvproj, cudaFuncAttributeMaxDynamicSharedMemorySize, KVP_SMEM);
    cudaFuncSetAttribute(k_oproj,  cudaFuncAttributeMaxDynamicSharedMemorySize, OP_SMEM);
    cudaFuncSetAttribute(k_qproj,  cudaFuncAttributeMaxDynamicSharedMemorySize, QP_SMEM);

    k_qproj <<<dim3(32, BB), 256, QP_SMEM>>>(prompt, wq, bq);
    k_fuse  <<<dim3(32, BB), 128>>>(kv, dw_w, dw_b, ln_w, ln_b, off_w);
    k_kvproj<<<dim3(32, BB), 256, KVP_SMEM>>>(wk, bk, wv, bv);
    k_attn  <<<dim3(32, BB), 512, ATTN_SMEM>>>();
    k_oproj <<<dim3(32, BB), 256, OP_SMEM>>>(wo, bo, out);
}

// round 17
// speedup vs baseline: 2.0754x; 1.1056x over previous
#include <cuda_runtime.h>
#include <cuda_fp16.h>
#include <math.h>
#include <stdint.h>

#define BB 4
#define CC 64
#define HW 4096
#define CHW (CC*HW)
#define EPSV 1e-5f
#define OFRV 4.0f
#define SCALEV 0.125f

// -------- scratch (device globals) --------
__device__ __half g_qh[BB*CHW];   // [b][p][c]  fp16
__device__ __half g_xs[BB*CHW];   // [b][p][c]  gathered features fp16
__device__ __half g_kh[BB*CHW];   // [b][n][c]  fp16
__device__ __half g_vh[BB*CHW];   // [b][n][c]  fp16
__device__ __half g_ao[BB*CHW];   // [b][p][c]  fp16 attention out
__device__ float  g_vspart[BB*32*64];

// ================= helpers =================
__device__ __forceinline__ uint32_t smem_u32(const void* p){
    uint32_t a;
    asm("{ .reg .u64 t; cvta.to.shared.u64 t, %1; cvt.u32.u64 %0, t; }" : "=r"(a) : "l"(p));
    return a;
}
__device__ __forceinline__ void cp16(uint32_t dst, const void* src){
    asm volatile("cp.async.cg.shared.global [%0], [%1], 16;" :: "r"(dst), "l"(src));
}
#define CP_COMMIT() asm volatile("cp.async.commit_group;" ::: "memory")
#define CP_WAIT0()  asm volatile("cp.async.wait_group 0;" ::: "memory")
#define CP_WAIT1()  asm volatile("cp.async.wait_group 1;" ::: "memory")

#define LDSM4(R0,R1,R2,R3,ADDR) \
    asm volatile("ldmatrix.sync.aligned.m8n8.x4.shared.b16 {%0,%1,%2,%3}, [%4];" \
        : "=r"(R0),"=r"(R1),"=r"(R2),"=r"(R3) : "r"(ADDR))

#define LDSM4T(R0,R1,R2,R3,ADDR) \
    asm volatile("ldmatrix.sync.aligned.m8n8.x4.trans.shared.b16 {%0,%1,%2,%3}, [%4];" \
        : "=r"(R0),"=r"(R1),"=r"(R2),"=r"(R3) : "r"(ADDR))

__device__ __forceinline__ void mma_f16(float* d, const uint32_t* a,
                                        uint32_t b0, uint32_t b1, const float* c){
    asm volatile(
        "mma.sync.aligned.m16n8k16.row.col.f32.f16.f16.f32 "
        "{%0,%1,%2,%3}, {%4,%5,%6,%7}, {%8,%9}, {%10,%11,%12,%13};"
        : "=f"(d[0]), "=f"(d[1]), "=f"(d[2]), "=f"(d[3])
        : "r"(a[0]), "r"(a[1]), "r"(a[2]), "r"(a[3]),
          "r"(b0), "r"(b1),
          "f"(c[0]), "f"(c[1]), "f"(c[2]), "f"(c[3]));
}
__device__ __forceinline__ uint32_t packh2(float a, float b){
    __half2 h = __floats2half2_rn(a, b);
    return *(uint32_t*)&h;
}

// ================= q projection GEMM: 128 pixels/block ======================
#define QP_PX 0
#define QP_W  17408
#define QP_SMEM (17408 + 9216)

__global__ void __launch_bounds__(256) k_qproj(const float* __restrict__ prompt,
                                               const float* __restrict__ wq,
                                               const float* __restrict__ bq) {
    extern __shared__ char smc[];
    uint32_t sb = smem_u32(smc);
    int tid = threadIdx.x, wid = tid >> 5, lane = tid & 31;
    int lj = lane & 7, lt = lane >> 3;
    int qr = lane >> 2, qc = lane & 3;
    int bb = blockIdx.y;
    int p0 = blockIdx.x * 128;

    {
        int c   = tid >> 2;
        int seg = tid & 3;
        const float4* pr = (const float4*)(prompt + bb * CHW + c * HW + p0 + seg * 32);
        __half* dst = (__half*)(smc + QP_PX + c * 272) + seg * 32;
#pragma unroll
        for (int i = 0; i < 8; i++) {
            float4 v = pr[i];
            __half2 h0 = __floats2half2_rn(v.x, v.y);
            __half2 h1 = __floats2half2_rn(v.z, v.w);
            ((uint2*)dst)[i] = make_uint2(*(uint32_t*)&h0, *(uint32_t*)&h1);
        }
    }
    __half* sw = (__half*)(smc + QP_W);
    for (int i = tid; i < 4096; i += 256) {
        int o = i >> 6, c = i & 63;
        sw[o * 72 + c] = __float2half_rn(wq[i]);
    }
    __syncthreads();

    uint32_t xa = sb + QP_PX + (uint32_t)(((lt >> 1) * 8 + lj) * 272
                + (wid * 16 + (lt & 1) * 8) * 2);
    uint32_t ap[4][4];
#pragma unroll
    for (int kc = 0; kc < 4; kc++)
        LDSM4T(ap[kc][0], ap[kc][1], ap[kc][2], ap[kc][3],
               xa + (uint32_t)(kc * 16 * 272));

    uint32_t wb = sb + QP_W + (uint32_t)(lj * 144 + lt * 16);

    float oa[8][4];
#pragma unroll
    for (int nc = 0; nc < 8; nc++)
#pragma unroll
        for (int j = 0; j < 4; j++) oa[nc][j] = 0.f;

#pragma unroll
    for (int nc = 0; nc < 8; nc++) {
        uint32_t b0, b1, b2, b3, c0, c1, c2, c3;
        LDSM4(b0, b1, b2, b3, wb + nc * 1152);
        LDSM4(c0, c1, c2, c3, wb + nc * 1152 + 64);
        mma_f16(oa[nc], ap[0], b0, b1, oa[nc]);
        mma_f16(oa[nc], ap[1], b2, b3, oa[nc]);
        mma_f16(oa[nc], ap[2], c0, c1, oa[nc]);
        mma_f16(oa[nc], ap[3], c2, c3, oa[nc]);
    }

    __half* gout = g_qh + bb * CHW;
    int row0 = p0 + wid * 16 + qr;
#pragma unroll
    for (int nc = 0; nc < 8; nc++) {
        float2 b2v = *(const float2*)(bq + nc * 8 + qc * 2);
        *(__half2*)(gout +  row0      * 64 + nc * 8 + qc * 2) =
            __floats2half2_rn(oa[nc][0] + b2v.x, oa[nc][1] + b2v.y);
        *(__half2*)(gout + (row0 + 8) * 64 + nc * 8 + qc * 2) =
            __floats2half2_rn(oa[nc][2] + b2v.x, oa[nc][3] + b2v.y);
    }
}

// ================= fused: dw3x3 + LN + GELU + offset + tanh + bilinear -> xs
__global__ void k_fuse(const float* __restrict__ kv,
                       const float* __restrict__ dw_w,
                       const float* __restrict__ dw_b,
                       const float* __restrict__ ln_w,
                       const float* __restrict__ ln_b,
                       const float* __restrict__ off_w) {
    __shared__ float s_dw[576], s_dwb[64], s_lnw[64], s_lnb[64];
    __shared__ float s_offw[128];

    for (int i = threadIdx.x; i < 576; i += 128) s_dw[i] = dw_w[i];
    if (threadIdx.x < 64) {
        s_dwb[threadIdx.x] = dw_b[threadIdx.x];
        s_lnw[threadIdx.x] = ln_w[threadIdx.x];
        s_lnb[threadIdx.x] = ln_b[threadIdx.x];
    }
    if (threadIdx.x < 128) s_offw[threadIdx.x] = off_w[threadIdx.x];
    __syncthreads();

    int p  = blockIdx.x * 128 + threadIdx.x;
    int bb = blockIdx.y;
    int py = p >> 6;
    int px = p & 63;

    const __half* qb = g_qh + bb * CHW;

    float t[64];
#pragma unroll
    for (int c = 0; c < 64; c++) t[c] = s_dwb[c];

    for (int k9 = 0; k9 < 9; k9++) {
        int dy = k9 / 3 - 1, dx = k9 % 3 - 1;
        int yy = py + dy, xx = px + dx;
        if (yy < 0 || yy > 63 || xx < 0 || xx > 63) continue;
        const uint4* qp = (const uint4*)(qb + (yy * 64 + xx) * 64);
#pragma unroll
        for (int c8 = 0; c8 < 8; c8++) {
            uint4 u = qp[c8];
            uint32_t uu[4] = {u.x, u.y, u.z, u.w};
#pragma unroll
            for (int j = 0; j < 4; j++) {
                float2 f = __half22float2(*(__half2*)&uu[j]);
                t[c8*8 + j*2    ] += f.x * s_dw[(c8*8 + j*2    )*9 + k9];
                t[c8*8 + j*2 + 1] += f.y * s_dw[(c8*8 + j*2 + 1)*9 + k9];
            }
        }
    }

    float mu = 0.f;
#pragma unroll
    for (int c = 0; c < 64; c++) mu += t[c];
    mu *= (1.0f / 64.0f);
    float var = 0.f;
#pragma unroll
    for (int c = 0; c < 64; c++) { float d = t[c] - mu; var += d * d; }
    var *= (1.0f / 64.0f);
    float rstd = rsqrtf(var + EPSV);
#pragma unroll
    for (int c = 0; c < 64; c++) {
        float z = (t[c] - mu) * rstd * s_lnw[c] + s_lnb[c];
        t[c] = 0.5f * z * (1.0f + erff(z * 0.70710678118654752f));
    }

    float o0 = 0.f, o1 = 0.f;
#pragma unroll
    for (int c = 0; c < 64; c++) { o0 += s_offw[c] * t[c]; o1 += s_offw[64 + c] * t[c]; }
    float off0 = tanhf(o0) * (1.0f / 63.0f) * OFRV;
    float off1 = tanhf(o1) * (1.0f / 63.0f) * OFRV;

    float refy = (0.5f + (float)py) * (2.0f / 63.0f) - 1.0f;
    float refx = (0.5f + (float)px) * (2.0f / 63.0f) - 1.0f;
    float gx = (off1 + refx + 1.0f) * 0.5f * 63.0f;
    float gy = (off0 + refy + 1.0f) * 0.5f * 63.0f;

    float x0f = floorf(gx), y0f = floorf(gy);
    float wx = gx - x0f, wy = gy - y0f;
    int x0 = (int)x0f, y0 = (int)y0f;
    int x1 = x0 + 1,   y1 = y0 + 1;

    float m00 = (x0 >= 0 && x0 <= 63 && y0 >= 0 && y0 <= 63) ? 1.f : 0.f;
    float m01 = (x1 >= 0 && x1 <= 63 && y0 >= 0 && y0 <= 63) ? 1.f : 0.f;
    float m10 = (x0 >= 0 && x0 <= 63 && y1 >= 0 && y1 <= 63) ? 1.f : 0.f;
    float m11 = (x1 >= 0 && x1 <= 63 && y1 >= 0 && y1 <= 63) ? 1.f : 0.f;

    int xc0 = min(max(x0, 0), 63), xc1 = min(max(x1, 0), 63);
    int yc0 = min(max(y0, 0), 63), yc1 = min(max(y1, 0), 63);

    float w00 = m00 * (1.0f - wx) * (1.0f - wy);
    float w01 = m01 * wx * (1.0f - wy);
    float w10 = m10 * (1.0f - wx) * wy;
    float w11 = m11 * wx * wy;

    int i00 = yc0 * 64 + xc0, i01 = yc0 * 64 + xc1;
    int i10 = yc1 * 64 + xc0, i11 = yc1 * 64 + xc1;

    const float* kvb = kv + bb * CHW;
    uint2* xout = (uint2*)(g_xs + bb * CHW + p * 64);
#pragma unroll
    for (int c4 = 0; c4 < 16; c4++) {
        float v[4];
#pragma unroll
        for (int j = 0; j < 4; j++) {
            const float* kc = kvb + (c4*4 + j) * HW;
            v[j] = w00 * kc[i00] + w01 * kc[i01] + w10 * kc[i10] + w11 * kc[i11];
        }
        __half2 h0 = __floats2half2_rn(v[0], v[1]);
        __half2 h1 = __floats2half2_rn(v[2], v[3]);
        xout[c4] = make_uint2(*(uint32_t*)&h0, *(uint32_t*)&h1);
    }
}

// ================= K/V projection GEMM (128 pixels/block) + V partial sums ==
#define KVP_XS 0
#define KVP_WK 18432
#define KVP_WV 27648
#define KVP_SMEM 36864

__global__ void __launch_bounds__(256) k_kvproj(const float* __restrict__ wk,
                                                const float* __restrict__ bk,
                                                const float* __restrict__ wv,
                                                const float* __restrict__ bv) {
    extern __shared__ char smc[];
    __shared__ float s_sums[8][64];
    uint32_t sb = smem_u32(smc);
    int tid = threadIdx.x, wid = tid >> 5, lane = tid & 31;
    int lj = lane & 7, lt = lane >> 3;
    int qr = lane >> 2, qc = lane & 3;
    int bb = blockIdx.y;
    int p0 = blockIdx.x * 128;

    const __half* xsb = g_xs + bb * CHW + p0 * 64;
#pragma unroll
    for (int it = 0; it < 4; it++) {
        int idx = tid + it * 256;
        int row = idx >> 3, c8 = idx & 7;
        cp16(sb + KVP_XS + row * 144 + c8 * 16, xsb + row * 64 + c8 * 8);
    }
    CP_COMMIT();

    __half* swk = (__half*)(smc + KVP_WK);
    __half* swv = (__half*)(smc + KVP_WV);
    for (int i = tid; i < 4096; i += 256) {
        int o = i >> 6, c = i & 63;
        swk[o * 72 + c] = __float2half_rn(wk[i]);
        swv[o * 72 + c] = __float2half_rn(wv[i]);
    }
    CP_WAIT0();
    __syncthreads();

    uint32_t xa = sb + KVP_XS + (uint32_t)((wid * 16 + (lt & 1) * 8 + lj) * 144 + (lt >> 1) * 16);
    uint32_t ap[4][4];
#pragma unroll
    for (int kc = 0; kc < 4; kc++)
        LDSM4(ap[kc][0], ap[kc][1], ap[kc][2], ap[kc][3], xa + kc * 32);

    uint32_t wfrag = (uint32_t)(lj * 144 + lt * 16);

#pragma unroll
    for (int mat = 0; mat < 2; mat++) {
        uint32_t wb = sb + (mat ? KVP_WV : KVP_WK) + wfrag;
        const float* bias = mat ? bv : bk;
        __half* gout = (mat ? g_vh : g_kh) + bb * CHW;

        float oa[8][4];
#pragma unroll
        for (int nc = 0; nc < 8; nc++)
#pragma unroll
            for (int j = 0; j < 4; j++) oa[nc][j] = 0.f;

#pragma unroll
        for (int nc = 0; nc < 8; nc++) {
            uint32_t b0, b1, b2, b3, c0, c1, c2, c3;
            LDSM4(b0, b1, b2, b3, wb + nc * 1152);
            LDSM4(c0, c1, c2, c3, wb + nc * 1152 + 64);
            mma_f16(oa[nc], ap[0], b0, b1, oa[nc]);
            mma_f16(oa[nc], ap[1], b2, b3, oa[nc]);
            mma_f16(oa[nc], ap[2], c0, c1, oa[nc]);
            mma_f16(oa[nc], ap[3], c2, c3, oa[nc]);
        }

        int row0 = p0 + wid * 16 + qr;
#pragma unroll
        for (int nc = 0; nc < 8; nc++) {
            float2 bv2 = *(const float2*)(bias + nc * 8 + qc * 2);
            *(__half2*)(gout +  row0      * 64 + nc * 8 + qc * 2) =
                __floats2half2_rn(oa[nc][0] + bv2.x, oa[nc][1] + bv2.y);
            *(__half2*)(gout + (row0 + 8) * 64 + nc * 8 + qc * 2) =
                __floats2half2_rn(oa[nc][2] + bv2.x, oa[nc][3] + bv2.y);
        }

        if (mat == 1) {
#pragma unroll
            for (int nc = 0; nc < 8; nc++) {
                float2 bv2 = *(const float2*)(bias + nc * 8 + qc * 2);
                float s0 = oa[nc][0] + oa[nc][2] + 2.0f * bv2.x;
                float s1 = oa[nc][1] + oa[nc][3] + 2.0f * bv2.y;
                s0 += __shfl_xor_sync(0xffffffffu, s0, 4);
                s0 += __shfl_xor_sync(0xffffffffu, s0, 8);
                s0 += __shfl_xor_sync(0xffffffffu, s0, 16);
                s1 += __shfl_xor_sync(0xffffffffu, s1, 4);
                s1 += __shfl_xor_sync(0xffffffffu, s1, 8);
                s1 += __shfl_xor_sync(0xffffffffu, s1, 16);
                if (qr == 0) {
                    s_sums[wid][nc * 8 + qc * 2    ] = s0;
                    s_sums[wid][nc * 8 + qc * 2 + 1] = s1;
                }
            }
            __syncthreads();
            if (tid < 64) {
                float s = 0.f;
#pragma unroll
                for (int g = 0; g < 8; g++) s += s_sums[g][tid];
                g_vspart[bb * 2048 + blockIdx.x * 64 + tid] = s;
            }
        }
    }
}

// ================= fp16 mma flash attention, 512 thr / 16 warps =============
// P kept ENTIRELY in registers (S-accum fragment == PV A-operand fragment).
#define KS0B 0
#define KS1B 18432
#define VS0B 36864
#define VS1B 55296
#define ATTN_SMEM 73728

__global__ void __launch_bounds__(512) k_attn() {
    extern __shared__ char smc[];
    float* smf = (float*)smc;
    __shared__ float s_vsum[64];
    uint32_t sb = smem_u32(smc);
    int tid  = threadIdx.x;
    int wid  = tid >> 5;
    int lane = tid & 31;
    int qw   = wid & 7;
    int kh   = wid >> 3;
    int qr   = lane >> 2;
    int qc   = lane & 3;
    int lj   = lane & 7;
    int lt   = lane >> 3;
    int bb = blockIdx.y;
    int m0 = blockIdx.x * 128;

    const __half* qbh = g_qh + bb * CHW;
    const __half* kbh = g_kh + bb * CHW;
    const __half* vbh = g_vh + bb * CHW;

    uint32_t aq[4][4];
    {
        const __half* qp = qbh + (m0 + qw * 16) * 64;
#pragma unroll
        for (int kc = 0; kc < 4; kc++) {
            aq[kc][0] = *(const uint32_t*)(qp +  qr      * 64 + kc*16 + qc*2);
            aq[kc][1] = *(const uint32_t*)(qp + (qr + 8) * 64 + kc*16 + qc*2);
            aq[kc][2] = *(const uint32_t*)(qp +  qr      * 64 + kc*16 + qc*2 + 8);
            aq[kc][3] = *(const uint32_t*)(qp + (qr + 8) * 64 + kc*16 + qc*2 + 8);
        }
    }

    float oacc[8][4];
#pragma unroll
    for (int nc = 0; nc < 8; nc++)
#pragma unroll
        for (int j = 0; j < 4; j++) oacc[nc][j] = 0.f;
    float rs0 = 0.f, rs1 = 0.f;

    {
#pragma unroll
        for (int it = 0; it < 2; it++) {
            int idx = tid + it * 512;
            int key = idx >> 3, c8 = idx & 7;
            cp16(sb + KS0B + key * 144 + c8 * 16, kbh + key * 64 + c8 * 8);
            cp16(sb + VS0B + key * 144 + c8 * 16, vbh + key * 64 + c8 * 8);
        }
        CP_COMMIT();
    }

    // reduce V column partial sums into smem (overlaps tile-0 cp.async)
    if (tid < 64) {
        float s = 0.f;
#pragma unroll
        for (int g = 0; g < 32; g++) s += g_vspart[bb * 2048 + g * 64 + tid];
        s_vsum[tid] = s;
    }

    uint32_t kq_off = (uint32_t)(lj * 144 + lt * 16);
    uint32_t vt_off = (uint32_t)(((lt & 1) * 8 + lj) * 144 + (lt >> 1) * 16);

    for (int i = 0; i < 32; i++) {
        __syncthreads();
        if (i + 1 < 32) {
            const __half* ks = kbh + (i + 1) * 128 * 64;
            const __half* vs = vbh + (i + 1) * 128 * 64;
            uint32_t ko = ((i + 1) & 1) ? KS1B : KS0B;
            uint32_t vo = ((i + 1) & 1) ? VS1B : VS0B;
#pragma unroll
            for (int it = 0; it < 2; it++) {
                int idx = tid + it * 512;
                int key = idx >> 3, c8 = idx & 7;
                cp16(sb + ko + key * 144 + c8 * 16, ks + key * 64 + c8 * 8);
                cp16(sb + vo + key * 144 + c8 * 16, vs + key * 64 + c8 * 8);
            }
            CP_COMMIT();
            CP_WAIT1();
        } else {
            CP_WAIT0();
        }
        __syncthreads();

        uint32_t Kb = sb + ((i & 1) ? KS1B : KS0B) + (uint32_t)(kh * 9216) + kq_off;
        uint32_t Vb = sb + ((i & 1) ? VS1B : VS0B) + (uint32_t)(kh * 9216) + vt_off;

        // ---- S = Q K^T ; P' = exp(S*scale)-1 packed directly into A-fragments
        uint32_t pp[8][2];
#pragma unroll
        for (int nc = 0; nc < 8; nc++) {
            uint32_t b0, b1, b2, b3, c0, c1, c2, c3;
            LDSM4(b0, b1, b2, b3, Kb + nc * 1152);
            LDSM4(c0, c1, c2, c3, Kb + nc * 1152 + 64);
            float s0[4] = {0.f, 0.f, 0.f, 0.f};
            mma_f16(s0, aq[0], b0, b1, s0);
            mma_f16(s0, aq[1], b2, b3, s0);
            mma_f16(s0, aq[2], c0, c1, s0);
            mma_f16(s0, aq[3], c2, c3, s0);

            float e0 = __expf(s0[0] * SCALEV) - 1.0f;
            float e1 = __expf(s0[1] * SCALEV) - 1.0f;
            float e2 = __expf(s0[2] * SCALEV) - 1.0f;
            float e3 = __expf(s0[3] * SCALEV) - 1.0f;
            rs0 += e0 + e1;
            rs1 += e2 + e3;
            pp[nc][0] = packh2(e0, e1);   // (qr,   nc*8+2qc, +1)
            pp[nc][1] = packh2(e2, e3);   // (qr+8, nc*8+2qc, +1)
        }

        // ---- O += P' @ V (P fragments straight from registers) ----
#pragma unroll
        for (int kc = 0; kc < 4; kc++) {
            uint32_t ap[4] = { pp[2*kc][0], pp[2*kc][1], pp[2*kc+1][0], pp[2*kc+1][1] };
            uint32_t Vk = Vb + (uint32_t)(kc * 16 * 144);
#pragma unroll
            for (int np = 0; np < 4; np++) {
                uint32_t b0, b1, b2, b3;
                LDSM4T(b0, b1, b2, b3, Vk + np * 32);
                mma_f16(oacc[np*2    ], ap, b0, b1, oacc[np*2    ]);
                mma_f16(oacc[np*2 + 1], ap, b2, b3, oacc[np*2 + 1]);
            }
        }
    }

    // ---- combine key halves (scratch overlaps K buffers, after barrier) ----
    __syncthreads();
    float* scr = smf + qw * 1120;
    if (kh == 1) {
        float* s = scr + lane * 35;
#pragma unroll
        for (int nc = 0; nc < 8; nc++)
#pragma unroll
            for (int j = 0; j < 4; j++) s[nc * 4 + j] = oacc[nc][j];
        s[32] = rs0;
        s[33] = rs1;
    }
    __syncthreads();
    if (kh == 0) {
        float* s = scr + lane * 35;
#pragma unroll
        for (int nc = 0; nc < 8; nc++)
#pragma unroll
            for (int j = 0; j < 4; j++) oacc[nc][j] += s[nc * 4 + j];
        rs0 += s[32];
        rs1 += s[33];

        rs0 += __shfl_xor_sync(0xffffffffu, rs0, 1);
        rs0 += __shfl_xor_sync(0xffffffffu, rs0, 2);
        rs1 += __shfl_xor_sync(0xffffffffu, rs1, 1);
        rs1 += __shfl_xor_sync(0xffffffffu, rs1, 2);
        float inv0 = 1.0f / (4096.0f + rs0);
        float inv1 = 1.0f / (4096.0f + rs1);

        __half* ob = g_ao + bb * CHW + (m0 + qw * 16) * 64;
#pragma unroll
        for (int nc = 0; nc < 8; nc++) {
            float2 vs2 = *(const float2*)(s_vsum + nc * 8 + 2 * qc);
            *(__half2*)(ob +  qr      * 64 + nc * 8 + 2 * qc) =
                __floats2half2_rn((oacc[nc][0] + vs2.x) * inv0, (oacc[nc][1] + vs2.y) * inv0);
            *(__half2*)(ob + (qr + 8) * 64 + nc * 8 + 2 * qc) =
                __floats2half2_rn((oacc[nc][2] + vs2.x) * inv1, (oacc[nc][3] + vs2.y) * inv1);
        }
    }
}

// ================= output projection GEMM (128 pixels/block) ================
#define OP_AO 0
#define OP_WO 18432
#define OP_SMEM 27648

__global__ void __launch_bounds__(256) k_oproj(const float* __restrict__ wo,
                                               const float* __restrict__ bo,
                                               float* __restrict__ out) {
    extern __shared__ char smc[];
    uint32_t sb = smem_u32(smc);
    int tid = threadIdx.x, wid = tid >> 5, lane = tid & 31;
    int lj = lane & 7, lt = lane >> 3;
    int qr = lane >> 2, qc = lane & 3;
    int bb = blockIdx.y;
    int p0 = blockIdx.x * 128;

    const __half* aob = g_ao + bb * CHW + p0 * 64;
#pragma unroll
    for (int it = 0; it < 4; it++) {
        int idx = tid + it * 256;
        int row = idx >> 3, c8 = idx & 7;
        cp16(sb + OP_AO + row * 144 + c8 * 16, aob + row * 64 + c8 * 8);
    }
    CP_COMMIT();

    __half* swo = (__half*)(smc + OP_WO);
    for (int i = tid; i < 4096; i += 256) {
        int o = i >> 6, c = i & 63;
        swo[o * 72 + c] = __float2half_rn(wo[i]);
    }
    CP_WAIT0();
    __syncthreads();

    uint32_t xa = sb + OP_AO + (uint32_t)((wid * 16 + (lt & 1) * 8 + lj) * 144 + (lt >> 1) * 16);
    uint32_t ap[4][4];
#pragma unroll
    for (int kc = 0; kc < 4; kc++)
        LDSM4(ap[kc][0], ap[kc][1], ap[kc][2], ap[kc][3], xa + kc * 32);

    uint32_t wb = sb + OP_WO + (uint32_t)(lj * 144 + lt * 16);

    float oa[8][4];
#pragma unroll
    for (int nc = 0; nc < 8; nc++)
#pragma unroll
        for (int j = 0; j < 4; j++) oa[nc][j] = 0.f;

#pragma unroll
    for (int nc = 0; nc < 8; nc++) {
        uint32_t b0, b1, b2, b3, c0, c1, c2, c3;
        LDSM4(b0, b1, b2, b3, wb + nc * 1152);
        LDSM4(c0, c1, c2, c3, wb + nc * 1152 + 64);
        mma_f16(oa[nc], ap[0], b0, b1, oa[nc]);
        mma_f16(oa[nc], ap[1], b2, b3, oa[nc]);
        mma_f16(oa[nc], ap[2], c0, c1, oa[nc]);
        mma_f16(oa[nc], ap[3], c2, c3, oa[nc]);
    }

    float* outb = out + bb * CHW;
    int prow = p0 + wid * 16 + qr;
#pragma unroll
    for (int nc = 0; nc < 8; nc++) {
        int ch = nc * 8 + qc * 2;
        float2 bo2 = *(const float2*)(bo + ch);
        outb[ ch      * HW + prow    ] = oa[nc][0] + bo2.x;
        outb[(ch + 1) * HW + prow    ] = oa[nc][1] + bo2.y;
        outb[ ch      * HW + prow + 8] = oa[nc][2] + bo2.x;
        outb[(ch + 1) * HW + prow + 8] = oa[nc][3] + bo2.y;
    }
}

// ================= launch =================
extern "C" void kernel_launch(void* const* d_in, const int* in_sizes, int n_in,
                              void* d_out, int out_size) {
    const float* prompt = (const float*)d_in[0];
    const float* kv     = (const float*)d_in[1];
    const float* wq     = (const float*)d_in[2];
    const float* bq     = (const float*)d_in[3];
    const float* wk     = (const float*)d_in[4];
    const float* bk     = (const float*)d_in[5];
    const float* wv     = (const float*)d_in[6];
    const float* bv     = (const float*)d_in[7];
    const float* wo     = (const float*)d_in[8];
    const float* bo     = (const float*)d_in[9];
    const float* dw_w   = (const float*)d_in[10];
    const float* dw_b   = (const float*)d_in[11];
    const float* ln_w   = (const float*)d_in[12];
    const float* ln_b   = (const float*)d_in[13];
    const float* off_w  = (const float*)d_in[14];
    float* out = (float*)d_out;

    cudaFuncSetAttribute(k_attn,   cudaFuncAttributeMaxDynamicSharedMemorySize, ATTN_SMEM);
    cudaFuncSetAttribute(k_kvproj, cudaFuncAttributeMaxDynamicSharedMemorySize, KVP_SMEM);
    cudaFuncSetAttribute(k_oproj,  cudaFuncAttributeMaxDynamicSharedMemorySize, OP_SMEM);
    cudaFuncSetAttribute(k_qproj,  cudaFuncAttributeMaxDynamicSharedMemorySize, QP_SMEM);

    k_qproj <<<dim3(32, BB), 256, QP_SMEM>>>(prompt, wq, bq);
    k_fuse  <<<dim3(32, BB), 128>>>(kv, dw_w, dw_b, ln_w, ln_b, off_w);
    k_kvproj<<<dim3(32, BB), 256, KVP_SMEM>>>(wk, bk, wv, bv);
    k_attn  <<<dim3(32, BB), 512, ATTN_SMEM>>>();
    k_oproj <<<dim3(32, BB), 256, OP_SMEM>>>(wo, bo, out);
}